// round 9
// baseline (speedup 1.0000x reference)
#include <cuda_runtime.h>
#include <cuda_bf16.h>
#include <math.h>
#include <stdint.h>

// ---------------- problem constants -----------------------------------------
#define BATCH   8
#define SEQ_L   32
#define DIM     2048
#define KVR     512
#define QR      768
#define NH      16
#define DNR     128
#define DR      64
#define DV      128
#define MAXT    4096
#define START_P 4064
#define QKD     192
#define CATD    576
#define MBL     256
#define ROWSPB  512
#define SCALE_F 0.07216878364870323f
#define KVD_PAD 640

// ---------------- fp32 scratch ----------------------------------------------
__device__ __align__(16) float g_qd  [MBL * QR];
__device__ __align__(16) float g_kv  [MBL * CATD];
__device__ __align__(16) float g_S   [(size_t)BATCH * ROWSPB * MAXT];
// ---------------- bf16 hi/lo operands ----------------------------------------
__device__ __align__(16) __nv_bfloat16 g_qc_h[BATCH * ROWSPB * CATD];
__device__ __align__(16) __nv_bfloat16 g_qc_l[BATCH * ROWSPB * CATD];
__device__ __align__(16) __nv_bfloat16 g_kc_h[(size_t)BATCH * MAXT * CATD];
__device__ __align__(16) __nv_bfloat16 g_kc_l[(size_t)BATCH * MAXT * CATD];
__device__ __align__(16) __nv_bfloat16 g_kt_h[(size_t)BATCH * KVR * MAXT];
__device__ __align__(16) __nv_bfloat16 g_kt_l[(size_t)BATCH * KVR * MAXT];
__device__ __align__(16) __nv_bfloat16 g_p_h [(size_t)BATCH * ROWSPB * MAXT];
__device__ __align__(16) __nv_bfloat16 g_p_l [(size_t)BATCH * ROWSPB * MAXT];
__device__ __align__(16) __nv_bfloat16 g_xh  [MBL * DIM];
__device__ __align__(16) __nv_bfloat16 g_xl  [MBL * DIM];
__device__ __align__(16) __nv_bfloat16 g_qnh [MBL * QR];
__device__ __align__(16) __nv_bfloat16 g_qnl [MBL * QR];
__device__ __align__(16) __nv_bfloat16 g_qh  [MBL * NH * QKD];
__device__ __align__(16) __nv_bfloat16 g_ql  [MBL * NH * QKD];
__device__ __align__(16) __nv_bfloat16 g_Oh  [BATCH * ROWSPB * KVR];
__device__ __align__(16) __nv_bfloat16 g_Ol  [BATCH * ROWSPB * KVR];
__device__ __align__(16) __nv_bfloat16 g_o2h [MBL * NH * DV];
__device__ __align__(16) __nv_bfloat16 g_o2l [MBL * NH * DV];
__device__ __align__(16) __nv_bfloat16 g_wqdh[QR * DIM];
__device__ __align__(16) __nv_bfloat16 g_wqdl[QR * DIM];
__device__ __align__(16) __nv_bfloat16 g_wquh[NH * QKD * QR];
__device__ __align__(16) __nv_bfloat16 g_wqul[NH * QKD * QR];
__device__ __align__(16) __nv_bfloat16 g_wkvdh[KVD_PAD * DIM];
__device__ __align__(16) __nv_bfloat16 g_wkvdl[KVD_PAD * DIM];
__device__ __align__(16) __nv_bfloat16 g_wouth[DIM * NH * DV];
__device__ __align__(16) __nv_bfloat16 g_woutl[DIM * NH * DV];
__device__ __align__(16) __nv_bfloat16 g_wvh [NH * 256 * KVR];
__device__ __align__(16) __nv_bfloat16 g_wvl [NH * 256 * KVR];
__device__ __align__(16) __nv_bfloat16 g_wnrth[NH * KVR * DNR];
__device__ __align__(16) __nv_bfloat16 g_wnrtl[NH * KVR * DNR];

// ================= helpers ===================================================
__device__ __forceinline__ uint32_t smem_u32(const void* p) {
    uint32_t a;
    asm("{ .reg .u64 t; cvta.to.shared.u64 t, %1; cvt.u32.u64 %0, t; }" : "=r"(a) : "l"(p));
    return a;
}
__device__ __forceinline__ uint32_t sw128(uint32_t o) { return o ^ ((o >> 3) & 0x70); }
__device__ __forceinline__ void cpa16(uint32_t saddr, const void* g) {
    asm volatile("cp.async.cg.shared.global [%0], [%1], 16;" :: "r"(saddr), "l"(g));
}
__device__ __forceinline__ void cpa_commit() { asm volatile("cp.async.commit_group;" ::: "memory"); }
__device__ __forceinline__ void cpa_wait1()  { asm volatile("cp.async.wait_group 1;" ::: "memory"); }
__device__ __forceinline__ void cpa_wait0()  { asm volatile("cp.async.wait_group 0;" ::: "memory"); }
__device__ __forceinline__ void ldm_x4(uint32_t* r, uint32_t addr) {
    asm volatile("ldmatrix.sync.aligned.m8n8.x4.shared.b16 {%0,%1,%2,%3}, [%4];"
                 : "=r"(r[0]), "=r"(r[1]), "=r"(r[2]), "=r"(r[3]) : "r"(addr));
}
__device__ __forceinline__ void mma_bf16(float* c, const uint32_t* a, const uint32_t* b) {
    asm volatile("mma.sync.aligned.m16n8k16.row.col.f32.bf16.bf16.f32 "
                 "{%0,%1,%2,%3}, {%4,%5,%6,%7}, {%8,%9}, {%0,%1,%2,%3};"
                 : "+f"(c[0]), "+f"(c[1]), "+f"(c[2]), "+f"(c[3])
                 : "r"(a[0]), "r"(a[1]), "r"(a[2]), "r"(a[3]), "r"(b[0]), "r"(b[1]));
}
__device__ __forceinline__ void split_write(float x, __nv_bfloat16* h, __nv_bfloat16* l, size_t i) {
    __nv_bfloat16 hv = __float2bfloat16(x);
    h[i] = hv;
    l[i] = __float2bfloat16(x - __bfloat162float(hv));
}
__device__ __forceinline__ void split4(float4 v, __nv_bfloat16* h, __nv_bfloat16* l, size_t i4) {
    __nv_bfloat16 h0 = __float2bfloat16(v.x), h1 = __float2bfloat16(v.y);
    __nv_bfloat16 h2 = __float2bfloat16(v.z), h3 = __float2bfloat16(v.w);
    __nv_bfloat16 l0 = __float2bfloat16(v.x - __bfloat162float(h0));
    __nv_bfloat16 l1 = __float2bfloat16(v.y - __bfloat162float(h1));
    __nv_bfloat16 l2 = __float2bfloat16(v.z - __bfloat162float(h2));
    __nv_bfloat16 l3 = __float2bfloat16(v.w - __bfloat162float(h3));
    __nv_bfloat162 hh0 = {h0, h1}, hh1 = {h2, h3};
    __nv_bfloat162 ll0 = {l0, l1}, ll1 = {l2, l3};
    uint2 hw = make_uint2(*(uint32_t*)&hh0, *(uint32_t*)&hh1);
    uint2 lw = make_uint2(*(uint32_t*)&ll0, *(uint32_t*)&ll1);
    *(uint2*)&h[i4 * 4] = hw;
    *(uint2*)&l[i4 * 4] = lw;
}

#define STAGE_B 65536

// ======== 3-stage pipelined mainloop, ONE barrier per chunk ==================
// order: wait(chunk c) -> sync -> prefetch(c+2) -> compute(c).
// prefetch lands in stage (c+2)%3, which held chunk c-1; barrier guarantees all
// warps finished computing c-1 before the overwrite.
#define PREFETCH_CHUNK(SB, KE)                                                       \
    _Pragma("unroll") for (int t = 0; t < 4; t++)                                    \
        _Pragma("unroll") for (int i = 0; i < 4; i++)                                \
            cpa16((SB) + soff[t][i], srcs[t] + (KE) + i * 8);                        \
    cpa_commit();

#define MAINLOOP_128(NCH)                                                            \
    {                                                                                \
        const int pre = ((NCH) < 2) ? (NCH) : 2;                                     \
        for (int s = 0; s < pre; s++) {                                              \
            const int ke = s * 64 + lhalf * 32;                                      \
            const uint32_t sb = smem32 + (uint32_t)s * STAGE_B;                      \
            PREFETCH_CHUNK(sb, ke)                                                   \
        }                                                                            \
    }                                                                                \
    for (int c = 0; c < (NCH); c++) {                                                \
        if (c + 1 < (NCH)) { cpa_wait1(); } else { cpa_wait0(); }                    \
        __syncthreads();                                                             \
        if (c + 2 < (NCH)) {                                                         \
            const int ke = (c + 2) * 64 + lhalf * 32;                                \
            const uint32_t sb = smem32 + (uint32_t)((c + 2) % 3) * STAGE_B;          \
            PREFETCH_CHUNK(sb, ke)                                                   \
        }                                                                            \
        const uint32_t st = smem32 + (uint32_t)(c % 3) * STAGE_B;                    \
        const uint32_t Ah32 = st, Al32 = st + 16384, Bh32 = st + 32768, Bl32 = st + 49152; \
        _Pragma("unroll") for (int ks = 0; ks < 4; ks++) {                           \
            const uint32_t kofs = ks * 32u + qsel * 16u;                             \
            uint32_t ah[4][4], al[4][4];                                             \
            _Pragma("unroll") for (int mf = 0; mf < 4; mf++) {                       \
                int row = wm + mf * 16 + qrow;                                       \
                ldm_x4(ah[mf], Ah32 + sw128((uint32_t)row * 128u + kofs));           \
            }                                                                        \
            uint32_t bh[4][2], bl[4][2];                                             \
            _Pragma("unroll") for (int nh = 0; nh < 2; nh++) {                       \
                int row = wn + nh * 16 + qrow;                                       \
                uint32_t t[4];                                                       \
                ldm_x4(t, Bh32 + sw128((uint32_t)row * 128u + kofs));                \
                bh[nh * 2 + 0][0] = t[0]; bh[nh * 2 + 0][1] = t[2];                  \
                bh[nh * 2 + 1][0] = t[1]; bh[nh * 2 + 1][1] = t[3];                  \
                ldm_x4(t, Bl32 + sw128((uint32_t)row * 128u + kofs));                \
                bl[nh * 2 + 0][0] = t[0]; bl[nh * 2 + 0][1] = t[2];                  \
                bl[nh * 2 + 1][0] = t[1]; bl[nh * 2 + 1][1] = t[3];                  \
            }                                                                        \
            _Pragma("unroll") for (int mf = 0; mf < 4; mf++) {                       \
                int row = wm + mf * 16 + qrow;                                       \
                ldm_x4(al[mf], Al32 + sw128((uint32_t)row * 128u + kofs));           \
            }                                                                        \
            _Pragma("unroll") for (int mf = 0; mf < 4; mf++)                         \
                _Pragma("unroll") for (int nf = 0; nf < 4; nf++)                     \
                    mma_bf16(acc[mf][nf], ah[mf], bh[nf]);                           \
            _Pragma("unroll") for (int mf = 0; mf < 4; mf++)                         \
                _Pragma("unroll") for (int nf = 0; nf < 4; nf++)                     \
                    mma_bf16(acc[mf][nf], ah[mf], bl[nf]);                           \
            _Pragma("unroll") for (int mf = 0; mf < 4; mf++)                         \
                _Pragma("unroll") for (int nf = 0; nf < 4; nf++)                     \
                    mma_bf16(acc[mf][nf], al[mf], bh[nf]);                           \
        }                                                                            \
    }

#define DECL_COMMON                                                                  \
    const int tid = threadIdx.x;                                                     \
    const int warp = tid >> 5, lane = tid & 31;                                      \
    const int wm = (warp >> 2) * 64, wn = (warp & 3) * 32;                           \
    const int lrow = tid >> 1, lhalf = tid & 1;                                      \
    const uint32_t smem32 = smem_u32(smem);                                          \
    const int qrow = lane & 15, qsel = lane >> 4;                                    \
    float acc[4][4][4];                                                              \
    _Pragma("unroll") for (int i = 0; i < 4; i++)                                    \
        _Pragma("unroll") for (int j = 0; j < 4; j++)                                \
            _Pragma("unroll") for (int r = 0; r < 4; r++) acc[i][j][r] = 0.f;        \
    uint32_t soff[4][4];                                                             \
    _Pragma("unroll") for (int t = 0; t < 4; t++)                                    \
        _Pragma("unroll") for (int i = 0; i < 4; i++)                                \
            soff[t][i] = (uint32_t)t * 16384u + sw128((uint32_t)lrow * 128u + lhalf * 64u + i * 16u);

// ====== generic 128x128 NT gemm with split-bf16 output (ogemm, qu) ===========
__global__ void __launch_bounds__(256)
gemm_mma_osplit(const __nv_bfloat16* __restrict__ Ah, const __nv_bfloat16* __restrict__ Al, size_t sAz,
                const __nv_bfloat16* __restrict__ Bh, const __nv_bfloat16* __restrict__ Bl, size_t sBz,
                __nv_bfloat16* __restrict__ Ch, __nv_bfloat16* __restrict__ Cl, int ldc, size_t sCz,
                int K)
{
    extern __shared__ char smem[];
    const int z = blockIdx.z;
    const int m0 = blockIdx.y * 128, n0 = blockIdx.x * 128;
    Ah += (size_t)z * sAz;  Al += (size_t)z * sAz;
    Bh += (size_t)z * sBz;  Bl += (size_t)z * sBz;
    Ch += (size_t)z * sCz;  Cl += (size_t)z * sCz;
    DECL_COMMON
    const __nv_bfloat16* srcs[4];
    srcs[0] = Ah + (size_t)(m0 + lrow) * K;
    srcs[1] = Al + (size_t)(m0 + lrow) * K;
    srcs[2] = Bh + (size_t)(n0 + lrow) * K;
    srcs[3] = Bl + (size_t)(n0 + lrow) * K;
    const int nch = K >> 6;
    MAINLOOP_128(nch)
    const int r0 = lane >> 2, c0 = (lane & 3) * 2;
#pragma unroll
    for (int mf = 0; mf < 4; mf++) {
        const int mA = m0 + wm + mf * 16 + r0;
#pragma unroll
        for (int nf = 0; nf < 4; nf++) {
            const int n = n0 + wn + nf * 8 + c0;
            const size_t i0 = (size_t)mA * ldc + n;
            const size_t i1 = (size_t)(mA + 8) * ldc + n;
            split_write(acc[mf][nf][0], Ch, Cl, i0);
            split_write(acc[mf][nf][1], Ch, Cl, i0 + 1);
            split_write(acc[mf][nf][2], Ch, Cl, i1);
            split_write(acc[mf][nf][3], Ch, Cl, i1 + 1);
        }
    }
}

// ====== qabs: per-head q_nrope @ w_nr^T -> split bf16 into qcat ==============
__global__ void __launch_bounds__(256)
qabs_mma()
{
    extern __shared__ char smem[];
    const int h = blockIdx.z;
    const int m0 = blockIdx.y * 128, n0 = blockIdx.x * 128;
    DECL_COMMON
    const __nv_bfloat16* srcs[4];
    srcs[0] = g_qh + (size_t)(m0 + lrow) * (NH * QKD) + h * QKD;
    srcs[1] = g_ql + (size_t)(m0 + lrow) * (NH * QKD) + h * QKD;
    srcs[2] = g_wnrth + (size_t)h * KVR * DNR + (size_t)(n0 + lrow) * DNR;
    srcs[3] = g_wnrtl + (size_t)h * KVR * DNR + (size_t)(n0 + lrow) * DNR;
    MAINLOOP_128(2)
    const int r0 = lane >> 2, c0 = (lane & 3) * 2;
#pragma unroll
    for (int mf = 0; mf < 4; mf++) {
        const int mA = m0 + wm + mf * 16 + r0;
        const int rowA = ((mA >> 5) * ROWSPB) + (mA & 31) * NH + h;
        const int rowB = (((mA + 8) >> 5) * ROWSPB) + ((mA + 8) & 31) * NH + h;
#pragma unroll
        for (int nf = 0; nf < 4; nf++) {
            const int n = n0 + wn + nf * 8 + c0;
            const size_t i0 = (size_t)rowA * CATD + n;
            const size_t i1 = (size_t)rowB * CATD + n;
            split_write(acc[mf][nf][0], g_qc_h, g_qc_l, i0);
            split_write(acc[mf][nf][1], g_qc_h, g_qc_l, i0 + 1);
            split_write(acc[mf][nf][2], g_qc_h, g_qc_l, i1);
            split_write(acc[mf][nf][3], g_qc_h, g_qc_l, i1 + 1);
        }
    }
}

// ====== oup: per-head O @ w_v^T -> split bf16 into o2 ========================
__global__ void __launch_bounds__(256)
oup_mma()
{
    extern __shared__ char smem[];
    const int h = blockIdx.z;
    const int m0 = blockIdx.y * 128, n0 = 0;
    DECL_COMMON
    const int mrow = m0 + lrow;
    const int arow = (mrow >> 5) * ROWSPB + (mrow & 31) * NH + h;
    const __nv_bfloat16* srcs[4];
    srcs[0] = g_Oh + (size_t)arow * KVR;
    srcs[1] = g_Ol + (size_t)arow * KVR;
    srcs[2] = g_wvh + (size_t)(h * 256 + DNR + n0 + lrow) * KVR;
    srcs[3] = g_wvl + (size_t)(h * 256 + DNR + n0 + lrow) * KVR;
    MAINLOOP_128(8)
    const int r0 = lane >> 2, c0 = (lane & 3) * 2;
#pragma unroll
    for (int mf = 0; mf < 4; mf++) {
        const int mA = m0 + wm + mf * 16 + r0;
#pragma unroll
        for (int nf = 0; nf < 4; nf++) {
            const int n = n0 + wn + nf * 8 + c0;
            const size_t i0 = (size_t)mA * (NH * DV) + h * DV + n;
            const size_t i1 = (size_t)(mA + 8) * (NH * DV) + h * DV + n;
            split_write(acc[mf][nf][0], g_o2h, g_o2l, i0);
            split_write(acc[mf][nf][1], g_o2h, g_o2l, i0 + 1);
            split_write(acc[mf][nf][2], g_o2h, g_o2l, i1);
            split_write(acc[mf][nf][3], g_o2h, g_o2l, i1 + 1);
        }
    }
}

// ====== split-K projections: fp32 atomicAdd epilogue =========================
__global__ void __launch_bounds__(256)
gemm_mma_sk(const __nv_bfloat16* __restrict__ Ah, const __nv_bfloat16* __restrict__ Al,
            const __nv_bfloat16* __restrict__ Bh, const __nv_bfloat16* __restrict__ Bl,
            float* __restrict__ C, int ldc, int K, int kpart, int N)
{
    extern __shared__ char smem[];
    const int m0 = blockIdx.y * 128, n0 = blockIdx.x * 128;
    const int kb = blockIdx.z * kpart;
    DECL_COMMON
    const __nv_bfloat16* srcs[4];
    srcs[0] = Ah + (size_t)(m0 + lrow) * K + kb;
    srcs[1] = Al + (size_t)(m0 + lrow) * K + kb;
    srcs[2] = Bh + (size_t)(n0 + lrow) * K + kb;
    srcs[3] = Bl + (size_t)(n0 + lrow) * K + kb;
    const int nch = kpart >> 6;
    MAINLOOP_128(nch)
    const int r0 = lane >> 2, c0 = (lane & 3) * 2;
#pragma unroll
    for (int mf = 0; mf < 4; mf++) {
        const int mA = m0 + wm + mf * 16 + r0;
#pragma unroll
        for (int nf = 0; nf < 4; nf++) {
            const int n = n0 + wn + nf * 8 + c0;
            if (n < N) {
                atomicAdd(&C[(size_t)mA * ldc + n],           acc[mf][nf][0]);
                atomicAdd(&C[(size_t)mA * ldc + n + 1],       acc[mf][nf][1]);
                atomicAdd(&C[(size_t)(mA + 8) * ldc + n],     acc[mf][nf][2]);
                atomicAdd(&C[(size_t)(mA + 8) * ldc + n + 1], acc[mf][nf][3]);
            }
        }
    }
}

// ====== wide 128x256 scores kernel (2-stage, one barrier per chunk) ==========
#define WSTAGE_B 98304
__global__ void __launch_bounds__(256)
gemm_mma_wide(const __nv_bfloat16* __restrict__ Ah, const __nv_bfloat16* __restrict__ Al, size_t sAz,
              const __nv_bfloat16* __restrict__ Bh, const __nv_bfloat16* __restrict__ Bl, size_t sBz,
              float* __restrict__ C, int ldc, size_t sCz,
              int K, const float* __restrict__ mask, float scale)
{
    extern __shared__ char smem[];
    const int z = blockIdx.z;
    const int m0 = blockIdx.y * 128, n0 = blockIdx.x * 256;
    Ah += (size_t)z * sAz;  Al += (size_t)z * sAz;
    Bh += (size_t)z * sBz;  Bl += (size_t)z * sBz;
    C  += (size_t)z * sCz;

    const int tid = threadIdx.x;
    const int warp = tid >> 5, lane = tid & 31;
    const int wm = (warp >> 2) * 64, wn = (warp & 3) * 64;

    const __nv_bfloat16* gsrc[6];
    uint32_t swb[6];
#pragma unroll
    for (int j = 0; j < 6; j++) {
        const int h = tid + j * 256;
        int t, r;
        if (h < 256)       { t = 0; r = h >> 1; }
        else if (h < 512)  { t = 1; r = (h - 256) >> 1; }
        else if (h < 1024) { t = 2; r = (h - 512) >> 1; }
        else               { t = 3; r = (h - 1024) >> 1; }
        const int half = h & 1;
        const uint32_t tbase = (t == 0) ? 0u : (t == 1) ? 16384u : (t == 2) ? 32768u : 65536u;
        swb[j] = tbase + sw128((uint32_t)r * 128u + half * 64u);
        const __nv_bfloat16* base =
            (t == 0) ? Ah + (size_t)(m0 + r) * K :
            (t == 1) ? Al + (size_t)(m0 + r) * K :
            (t == 2) ? Bh + (size_t)(n0 + r) * K :
                       Bl + (size_t)(n0 + r) * K;
        gsrc[j] = base + half * 32;
    }
    const uint32_t smem32 = smem_u32(smem);
    const int qrow = lane & 15, qsel = lane >> 4;

    float acc[4][8][4];
#pragma unroll
    for (int i = 0; i < 4; i++)
#pragma unroll
        for (int j = 0; j < 8; j++)
#pragma unroll
            for (int r = 0; r < 4; r++) acc[i][j][r] = 0.f;

    const int nch = K >> 6;
    {
#pragma unroll
        for (int j = 0; j < 6; j++)
#pragma unroll
            for (int i = 0; i < 4; i++)
                cpa16(smem32 + (swb[j] ^ (i * 16u)), gsrc[j] + i * 8);
        cpa_commit();
    }
    for (int c = 0; c < nch; c++) {
        cpa_wait0();
        __syncthreads();
        if (c + 1 < nch) {
            const int ke = (c + 1) * 64;
            const uint32_t sb = smem32 + ((c + 1) & 1) * WSTAGE_B;
#pragma unroll
            for (int j = 0; j < 6; j++)
#pragma unroll
                for (int i = 0; i < 4; i++)
                    cpa16(sb + (swb[j] ^ (i * 16u)), gsrc[j] + ke + i * 8);
            cpa_commit();
        }

        const uint32_t st = smem32 + (c & 1) * WSTAGE_B;
        const uint32_t Ah32 = st, Al32 = st + 16384, Bh32 = st + 32768, Bl32 = st + 65536;
#pragma unroll
        for (int ks = 0; ks < 4; ks++) {
            const uint32_t kofs = ks * 32u + qsel * 16u;
            uint32_t ah[4][4], al[4][4];
#pragma unroll
            for (int mf = 0; mf < 4; mf++) {
                int row = wm + mf * 16 + qrow;
                ldm_x4(ah[mf], Ah32 + sw128((uint32_t)row * 128u + kofs));
            }
            uint32_t bh[8][2], bl[8][2];
#pragma unroll
            for (int nh = 0; nh < 4; nh++) {
                int row = wn + nh * 16 + qrow;
                uint32_t t[4];
                ldm_x4(t, Bh32 + sw128((uint32_t)row * 128u + kofs));
                bh[nh * 2 + 0][0] = t[0]; bh[nh * 2 + 0][1] = t[2];
                bh[nh * 2 + 1][0] = t[1]; bh[nh * 2 + 1][1] = t[3];
                ldm_x4(t, Bl32 + sw128((uint32_t)row * 128u + kofs));
                bl[nh * 2 + 0][0] = t[0]; bl[nh * 2 + 0][1] = t[2];
                bl[nh * 2 + 1][0] = t[1]; bl[nh * 2 + 1][1] = t[3];
            }
#pragma unroll
            for (int mf = 0; mf < 4; mf++) {
                int row = wm + mf * 16 + qrow;
                ldm_x4(al[mf], Al32 + sw128((uint32_t)row * 128u + kofs));
            }
#pragma unroll
            for (int mf = 0; mf < 4; mf++)
#pragma unroll
                for (int nf = 0; nf < 8; nf++)
                    mma_bf16(acc[mf][nf], ah[mf], bh[nf]);
#pragma unroll
            for (int mf = 0; mf < 4; mf++)
#pragma unroll
                for (int nf = 0; nf < 8; nf++)
                    mma_bf16(acc[mf][nf], ah[mf], bl[nf]);
#pragma unroll
            for (int mf = 0; mf < 4; mf++)
#pragma unroll
                for (int nf = 0; nf < 8; nf++)
                    mma_bf16(acc[mf][nf], al[mf], bh[nf]);
        }
    }

    const int r0 = lane >> 2, c0 = (lane & 3) * 2;
#pragma unroll
    for (int mf = 0; mf < 4; mf++) {
        const int mA = m0 + wm + mf * 16 + r0;
        const float* mrow = mask + (size_t)(mA >> 4) * MAXT;
#pragma unroll
        for (int nf = 0; nf < 8; nf++) {
            const int n = n0 + wn + nf * 8 + c0;
            float v0 = acc[mf][nf][0] * scale + mrow[n];
            float v1 = acc[mf][nf][1] * scale + mrow[n + 1];
            float v2 = acc[mf][nf][2] * scale + mrow[n];
            float v3 = acc[mf][nf][3] * scale + mrow[n + 1];
            *(float2*)&C[(size_t)mA * ldc + n]       = make_float2(v0, v1);
            *(float2*)&C[(size_t)(mA + 8) * ldc + n] = make_float2(v2, v3);
        }
    }
}

// ================= merged weight/x conversion ================================
#define C4_X    131072
#define C4_QD   (C4_X + 393216)
#define C4_QU   (C4_QD + 589824)
#define C4_KVD  (C4_QU + 327680)
#define C4_OUT  (C4_KVD + 1048576)
#define C4_WKVU (C4_OUT + 524288)
#define KVD_SRC4 294912
__global__ void conv_all(const float4* __restrict__ x, const float4* __restrict__ wqd,
                         const float4* __restrict__ wqu, const float4* __restrict__ wkvd,
                         const float4* __restrict__ wout, const float4* __restrict__ wkvu) {
    const int i = blockIdx.x * 256 + threadIdx.x;
    if (i < C4_X) {
        split4(x[i], g_xh, g_xl, i);
    } else if (i < C4_QD) {
        const int j = i - C4_X;
        split4(wqd[j], g_wqdh, g_wqdl, j);
    } else if (i < C4_QU) {
        const int j = i - C4_QD;
        split4(wqu[j], g_wquh, g_wqul, j);
    } else if (i < C4_KVD) {
        const int j = i - C4_QU;
        float4 v = (j < KVD_SRC4) ? wkvd[j] : make_float4(0.f, 0.f, 0.f, 0.f);
        split4(v, g_wkvdh, g_wkvdl, j);
    } else if (i < C4_OUT) {
        const int j = i - C4_KVD;
        split4(wout[j], g_wouth, g_woutl, j);
    } else if (i < C4_WKVU) {
        const int j = i - C4_OUT;
        split4(wkvu[j], g_wvh, g_wvl, j);
    }
}

// transpose nr part of w_kvu: out[h][n][d] = w_kvu[(h*256+d)*512 + n]
__global__ void build_wnrt(const float* __restrict__ wkvu) {
    __shared__ float tile[32][33];
    const int h = blockIdx.z;
    const int n0 = blockIdx.x * 32, d0 = blockIdx.y * 32;
    const int tx = threadIdx.x, ty = threadIdx.y;
#pragma unroll
    for (int i = 0; i < 4; i++) {
        const int d = d0 + ty + i * 8;
        tile[ty + i * 8][tx] = wkvu[(size_t)(h * 256 + d) * KVR + n0 + tx];
    }
    __syncthreads();
#pragma unroll
    for (int i = 0; i < 4; i++) {
        const int n = n0 + ty + i * 8;
        const float v = tile[tx][ty + i * 8];
        const size_t o = (size_t)h * KVR * DNR + (size_t)n * DNR + d0 + tx;
        split_write(v, g_wnrth, g_wnrtl, o);
    }
}

// ====== merged kv builder: writes kc (t-major) and kt (n-major) in one pass ==
__global__ void build_kv2(const float* __restrict__ kvc, const float* __restrict__ krc) {
    __shared__ float tile[32][33];
    const int b = blockIdx.z;
    const int t0 = blockIdx.x * 32;
    const int y = blockIdx.y;
    const int tx = threadIdx.x, ty = threadIdx.y;
    if (y < 16) {
        const int n0 = y * 32;
#pragma unroll
        for (int i = 0; i < 4; i++) {
            const int t = t0 + ty + i * 8;
            float v;
            if (t >= START_P)
                v = g_kv[(size_t)((b << 5) + (t - START_P)) * CATD + n0 + tx];
            else
                v = kvc[((size_t)b * MAXT + t) * KVR + n0 + tx];
            tile[ty + i * 8][tx] = v;
            split_write(v, g_kc_h, g_kc_l, ((size_t)b * MAXT + t) * CATD + n0 + tx);
        }
        __syncthreads();
#pragma unroll
        for (int i = 0; i < 4; i++) {
            const int n = n0 + ty + i * 8;
            const float v = tile[tx][ty + i * 8];
            split_write(v, g_kt_h, g_kt_l, ((size_t)(b * KVR + n)) * MAXT + t0 + tx);
        }
    } else {
        const int c0 = KVR + (y - 16) * 32;
#pragma unroll
        for (int i = 0; i < 4; i++) {
            const int t = t0 + ty + i * 8;
            const int c = c0 + tx;
            float v;
            if (t >= START_P)
                v = g_kv[(size_t)((b << 5) + (t - START_P)) * CATD + c];
            else
                v = krc[((size_t)b * MAXT + t) * DR + (c - KVR)];
            split_write(v, g_kc_h, g_kc_l, ((size_t)b * MAXT + t) * CATD + c);
        }
    }
}

// ================= RMSNorm ===================================================
__global__ void rms_kernel(const float* __restrict__ w) {
    const int row = blockIdx.x;
    const float* xr = g_qd + row * QR;
    __shared__ float red[256];
    const int tid = threadIdx.x;
    float v[3], s = 0.f;
#pragma unroll
    for (int i = 0; i < 3; i++) { v[i] = xr[tid + i * 256]; s += v[i] * v[i]; }
    red[tid] = s; __syncthreads();
    for (int o = 128; o > 0; o >>= 1) {
        if (tid < o) red[tid] += red[tid + o];
        __syncthreads();
    }
    const float r = rsqrtf(red[0] / (float)QR + 1.1920929e-07f);
    __syncthreads();
#pragma unroll
    for (int i = 0; i < 3; i++) {
        const float y = v[i] * r * w[tid + i * 256];
        split_write(y, g_qnh, g_qnl, (size_t)row * QR + tid + i * 256);
    }
}

// ================= rope ======================================================
__global__ void rope_q(const float* __restrict__ fc, const float* __restrict__ fs) {
    const int idx = blockIdx.x * 256 + threadIdx.x;
    const int j = idx & 31, h = (idx >> 5) & 15, l = (idx >> 9) & 31, b = idx >> 14;
    const size_t si = (size_t)(b * SEQ_L + l) * (NH * QKD) + h * QKD + DNR + 2 * j;
    const float xr = __bfloat162float(g_qh[si])     + __bfloat162float(g_ql[si]);
    const float xi = __bfloat162float(g_qh[si + 1]) + __bfloat162float(g_ql[si + 1]);
    const float c = fc[l * 32 + j], s = fs[l * 32 + j];
    const size_t o = (size_t)(b * ROWSPB + l * NH + h) * CATD + KVR + 2 * j;
    split_write(xr * c - xi * s, g_qc_h, g_qc_l, o);
    split_write(xr * s + xi * c, g_qc_h, g_qc_l, o + 1);
}
__global__ void rope_k(const float* __restrict__ fc, const float* __restrict__ fs) {
    const int k = blockIdx.x * 256 + threadIdx.x;
    const int j = k & 31, l = (k >> 5) & 31, b = k >> 10;
    float* p = &g_kv[(size_t)(b * SEQ_L + l) * CATD + KVR + 2 * j];
    const float xr = p[0], xi = p[1];
    const float c = fc[l * 32 + j], s = fs[l * 32 + j];
    p[0] = xr * c - xi * s;
    p[1] = xr * s + xi * c;
}

// ================= softmax -> bf16 hi/lo P ===================================
__global__ void softmax_split() {
    const int row = blockIdx.x;
    float* s = g_S + (size_t)row * MAXT;
    __shared__ float red[256];
    const int tid = threadIdx.x;
    float4 v[4];
    float mx = -INFINITY;
#pragma unroll
    for (int g = 0; g < 4; g++) {
        v[g] = *(float4*)&s[tid * 4 + g * 1024];
        mx = fmaxf(mx, fmaxf(fmaxf(v[g].x, v[g].y), fmaxf(v[g].z, v[g].w)));
    }
    red[tid] = mx; __syncthreads();
    for (int o = 128; o > 0; o >>= 1) {
        if (tid < o) red[tid] = fmaxf(red[tid], red[tid + o]);
        __syncthreads();
    }
    mx = red[0]; __syncthreads();
    float sum = 0.f;
#pragma unroll
    for (int g = 0; g < 4; g++) {
        v[g].x = __expf(v[g].x - mx); v[g].y = __expf(v[g].y - mx);
        v[g].z = __expf(v[g].z - mx); v[g].w = __expf(v[g].w - mx);
        sum += v[g].x + v[g].y + v[g].z + v[g].w;
    }
    red[tid] = sum; __syncthreads();
    for (int o = 128; o > 0; o >>= 1) {
        if (tid < o) red[tid] += red[tid + o];
        __syncthreads();
    }
    const float inv = 1.f / red[0];
#pragma unroll
    for (int g = 0; g < 4; g++) {
        float4 p = make_float4(v[g].x * inv, v[g].y * inv, v[g].z * inv, v[g].w * inv);
        split4(p, g_p_h, g_p_l, ((size_t)row * MAXT + tid * 4 + g * 1024) >> 2);
    }
}

// ============================== launcher =====================================
extern "C" void kernel_launch(void* const* d_in, const int* in_sizes, int n_in,
                              void* d_out, int out_size) {
    const float* x      = (const float*)d_in[0];
    const float* fc     = (const float*)d_in[2];
    const float* fs     = (const float*)d_in[3];
    const float* mask   = (const float*)d_in[4];
    const float* kvc    = (const float*)d_in[5];
    const float* krc    = (const float*)d_in[6];
    const float* w_kvd  = (const float*)d_in[7];
    const float* w_qd   = (const float*)d_in[8];
    const float* rms_w  = (const float*)d_in[9];
    const float* w_qu   = (const float*)d_in[10];
    const float* w_kvu  = (const float*)d_in[11];
    const float* w_out  = (const float*)d_in[12];
    float* out = (float*)d_out;

    float *p_qd, *p_kv, *p_S;
    cudaGetSymbolAddress((void**)&p_qd, g_qd);
    cudaGetSymbolAddress((void**)&p_kv, g_kv);
    cudaGetSymbolAddress((void**)&p_S, g_S);

    __nv_bfloat16 *xh, *xl, *qnh, *qnl, *qh, *ql, *o2h, *o2l, *Oh, *Ol;
    __nv_bfloat16 *wqdh, *wqdl, *wquh, *wqul, *wkvdh, *wkvdl, *wouth, *woutl;
    __nv_bfloat16 *qch, *qcl, *kch, *kcl, *kth, *ktl, *ph, *pl;
    cudaGetSymbolAddress((void**)&xh, g_xh);     cudaGetSymbolAddress((void**)&xl, g_xl);
    cudaGetSymbolAddress((void**)&qnh, g_qnh);   cudaGetSymbolAddress((void**)&qnl, g_qnl);
    cudaGetSymbolAddress((void**)&qh, g_qh);     cudaGetSymbolAddress((void**)&ql, g_ql);
    cudaGetSymbolAddress((void**)&o2h, g_o2h);   cudaGetSymbolAddress((void**)&o2l, g_o2l);
    cudaGetSymbolAddress((void**)&Oh, g_Oh);     cudaGetSymbolAddress((void**)&Ol, g_Ol);
    cudaGetSymbolAddress((void**)&wqdh, g_wqdh); cudaGetSymbolAddress((void**)&wqdl, g_wqdl);
    cudaGetSymbolAddress((void**)&wquh, g_wquh); cudaGetSymbolAddress((void**)&wqul, g_wqul);
    cudaGetSymbolAddress((void**)&wkvdh, g_wkvdh); cudaGetSymbolAddress((void**)&wkvdl, g_wkvdl);
    cudaGetSymbolAddress((void**)&wouth, g_wouth); cudaGetSymbolAddress((void**)&woutl, g_woutl);
    cudaGetSymbolAddress((void**)&qch, g_qc_h);  cudaGetSymbolAddress((void**)&qcl, g_qc_l);
    cudaGetSymbolAddress((void**)&kch, g_kc_h);  cudaGetSymbolAddress((void**)&kcl, g_kc_l);
    cudaGetSymbolAddress((void**)&kth, g_kt_h);  cudaGetSymbolAddress((void**)&ktl, g_kt_l);
    cudaGetSymbolAddress((void**)&ph, g_p_h);    cudaGetSymbolAddress((void**)&pl, g_p_l);

    static cudaStream_t s_kv = nullptr;
    static cudaEvent_t ev_fork = nullptr, ev_join = nullptr;
    if (!s_kv) {
        cudaStreamCreateWithFlags(&s_kv, cudaStreamNonBlocking);
        cudaEventCreateWithFlags(&ev_fork, cudaEventDisableTiming);
        cudaEventCreateWithFlags(&ev_join, cudaEventDisableTiming);
        cudaFuncSetAttribute(gemm_mma_osplit, cudaFuncAttributeMaxDynamicSharedMemorySize, 3 * STAGE_B);
        cudaFuncSetAttribute(gemm_mma_sk, cudaFuncAttributeMaxDynamicSharedMemorySize, 3 * STAGE_B);
        cudaFuncSetAttribute(qabs_mma, cudaFuncAttributeMaxDynamicSharedMemorySize, 3 * STAGE_B);
        cudaFuncSetAttribute(oup_mma, cudaFuncAttributeMaxDynamicSharedMemorySize, 3 * STAGE_B);
        cudaFuncSetAttribute(gemm_mma_wide, cudaFuncAttributeMaxDynamicSharedMemorySize, 2 * WSTAGE_B);
    }
    const int DSM = 3 * STAGE_B;
    const int WDSM = 2 * WSTAGE_B;

    // ---- root conversions ----
    conv_all<<<C4_WKVU / 256, 256>>>((const float4*)x, (const float4*)w_qd, (const float4*)w_qu,
                                     (const float4*)w_kvd, (const float4*)w_out, (const float4*)w_kvu);
    build_wnrt<<<dim3(KVR / 32, DNR / 32, NH), dim3(32, 8)>>>(w_kvu);

    // ---- fork: kv-path on s_kv, q-path on default ----
    cudaEventRecord(ev_fork, 0);
    cudaStreamWaitEvent(s_kv, ev_fork, 0);

    // kv path
    cudaMemsetAsync(p_kv, 0, (size_t)MBL * CATD * 4, s_kv);
    gemm_mma_sk<<<dim3(KVD_PAD / 128, MBL / 128, 8), 256, DSM, s_kv>>>(xh, xl, wkvdh, wkvdl,
        p_kv, CATD, DIM, DIM / 8, CATD);
    rope_k<<<BATCH * SEQ_L * 32 / 256, 256, 0, s_kv>>>(fc, fs);
    build_kv2<<<dim3(MAXT / 32, 18, BATCH), dim3(32, 8), 0, s_kv>>>(kvc, krc);
    cudaEventRecord(ev_join, s_kv);

    // q path
    cudaMemsetAsync(p_qd, 0, (size_t)MBL * QR * 4);
    gemm_mma_sk<<<dim3(QR / 128, MBL / 128, 8), 256, DSM>>>(xh, xl, wqdh, wqdl,
        p_qd, QR, DIM, DIM / 8, QR);
    rms_kernel<<<MBL, 256>>>(rms_w);
    gemm_mma_osplit<<<dim3(NH * QKD / 128, MBL / 128, 1), 256, DSM>>>(qnh, qnl, 0,
        wquh, wqul, 0, qh, ql, NH * QKD, 0, QR);
    rope_q<<<BATCH * SEQ_L * NH * 32 / 256, 256>>>(fc, fs);
    qabs_mma<<<dim3(KVR / 128, MBL / 128, NH), 256, DSM>>>();

    // ---- join q/kv ----
    cudaStreamWaitEvent(0, ev_join, 0);

    // ---- attention (single stream, full batch) ----
    gemm_mma_wide<<<dim3(MAXT / 256, ROWSPB / 128, BATCH), 256, WDSM>>>(
        qch, qcl, (size_t)ROWSPB * CATD, kch, kcl, (size_t)MAXT * CATD,
        p_S, MAXT, (size_t)ROWSPB * MAXT, CATD, mask, SCALE_F);
    softmax_split<<<BATCH * ROWSPB, 256>>>();
    gemm_mma_osplit<<<dim3(KVR / 128, ROWSPB / 128, BATCH), 256, DSM>>>(
        ph, pl, (size_t)ROWSPB * MAXT, kth, ktl, (size_t)KVR * MAXT,
        Oh, Ol, KVR, (size_t)ROWSPB * KVR, MAXT);

    // ---- output path ----
    oup_mma<<<dim3(1, MBL / 128, NH), 256, DSM>>>();
    cudaMemsetAsync(out, 0, (size_t)MBL * DIM * 4);
    gemm_mma_sk<<<dim3(DIM / 128, MBL / 128, 8), 256, DSM>>>(o2h, o2l, wouth, woutl,
        out, DIM, NH * DV, NH * DV / 8, DIM);
}

// round 10
// speedup vs baseline: 1.5813x; 1.5813x over previous
#include <cuda_runtime.h>
#include <cuda_bf16.h>
#include <cuda_fp16.h>
#include <math.h>
#include <stdint.h>

// ---------------- problem constants -----------------------------------------
#define BATCH   8
#define SEQ_L   32
#define DIM     2048
#define KVR     512
#define QR      768
#define NH      16
#define DNR     128
#define DR      64
#define DV      128
#define MAXT    4096
#define START_P 4064
#define QKD     192
#define CATD    576
#define MBL     256
#define ROWSPB  512
#define SCALE_F 0.07216878364870323f
#define KVD_PAD 640

// ---------------- fp32 scratch ----------------------------------------------
__device__ __align__(16) float g_qd  [MBL * QR];
__device__ __align__(16) float g_q   [MBL * NH * QKD];
__device__ __align__(16) float g_kv  [MBL * CATD];
__device__ __align__(16) float g_S   [(size_t)BATCH * ROWSPB * MAXT];
// ---------------- fp16 attention operands ------------------------------------
__device__ __align__(16) __half g_qc [BATCH * ROWSPB * CATD];
__device__ __align__(16) __half g_kc [(size_t)BATCH * MAXT * CATD];
__device__ __align__(16) __half g_kt [(size_t)BATCH * KVR * MAXT];
__device__ __align__(16) __half g_p  [(size_t)BATCH * ROWSPB * MAXT];
// ---------------- bf16 hi/lo projection operands ------------------------------
__device__ __align__(16) __nv_bfloat16 g_xh  [MBL * DIM];
__device__ __align__(16) __nv_bfloat16 g_xl  [MBL * DIM];
__device__ __align__(16) __nv_bfloat16 g_qnh [MBL * QR];
__device__ __align__(16) __nv_bfloat16 g_qnl [MBL * QR];
__device__ __align__(16) __nv_bfloat16 g_qh  [MBL * NH * QKD];
__device__ __align__(16) __nv_bfloat16 g_ql  [MBL * NH * QKD];
__device__ __align__(16) __nv_bfloat16 g_Oh  [BATCH * ROWSPB * KVR];
__device__ __align__(16) __nv_bfloat16 g_Ol  [BATCH * ROWSPB * KVR];
__device__ __align__(16) __nv_bfloat16 g_o2h [MBL * NH * DV];
__device__ __align__(16) __nv_bfloat16 g_o2l [MBL * NH * DV];
__device__ __align__(16) __nv_bfloat16 g_wqdh[QR * DIM];
__device__ __align__(16) __nv_bfloat16 g_wqdl[QR * DIM];
__device__ __align__(16) __nv_bfloat16 g_wquh[NH * QKD * QR];
__device__ __align__(16) __nv_bfloat16 g_wqul[NH * QKD * QR];
__device__ __align__(16) __nv_bfloat16 g_wkvdh[KVD_PAD * DIM];
__device__ __align__(16) __nv_bfloat16 g_wkvdl[KVD_PAD * DIM];
__device__ __align__(16) __nv_bfloat16 g_wouth[DIM * NH * DV];
__device__ __align__(16) __nv_bfloat16 g_woutl[DIM * NH * DV];
__device__ __align__(16) __nv_bfloat16 g_wvh [NH * 256 * KVR];
__device__ __align__(16) __nv_bfloat16 g_wvl [NH * 256 * KVR];
__device__ __align__(16) __nv_bfloat16 g_wnrth[NH * KVR * DNR];
__device__ __align__(16) __nv_bfloat16 g_wnrtl[NH * KVR * DNR];

// ================= helpers ===================================================
__device__ __forceinline__ uint32_t smem_u32(const void* p) {
    uint32_t a;
    asm("{ .reg .u64 t; cvta.to.shared.u64 t, %1; cvt.u32.u64 %0, t; }" : "=r"(a) : "l"(p));
    return a;
}
__device__ __forceinline__ uint32_t sw128(uint32_t o) { return o ^ ((o >> 3) & 0x70); }
__device__ __forceinline__ void cpa16(uint32_t saddr, const void* g) {
    asm volatile("cp.async.cg.shared.global [%0], [%1], 16;" :: "r"(saddr), "l"(g));
}
__device__ __forceinline__ void cpa_commit() { asm volatile("cp.async.commit_group;" ::: "memory"); }
__device__ __forceinline__ void cpa_wait2()  { asm volatile("cp.async.wait_group 2;" ::: "memory"); }
__device__ __forceinline__ void cpa_wait1()  { asm volatile("cp.async.wait_group 1;" ::: "memory"); }
__device__ __forceinline__ void cpa_wait0()  { asm volatile("cp.async.wait_group 0;" ::: "memory"); }
__device__ __forceinline__ void ldm_x4(uint32_t* r, uint32_t addr) {
    asm volatile("ldmatrix.sync.aligned.m8n8.x4.shared.b16 {%0,%1,%2,%3}, [%4];"
                 : "=r"(r[0]), "=r"(r[1]), "=r"(r[2]), "=r"(r[3]) : "r"(addr));
}
__device__ __forceinline__ void mma_bf16(float* c, const uint32_t* a, const uint32_t* b) {
    asm volatile("mma.sync.aligned.m16n8k16.row.col.f32.bf16.bf16.f32 "
                 "{%0,%1,%2,%3}, {%4,%5,%6,%7}, {%8,%9}, {%0,%1,%2,%3};"
                 : "+f"(c[0]), "+f"(c[1]), "+f"(c[2]), "+f"(c[3])
                 : "r"(a[0]), "r"(a[1]), "r"(a[2]), "r"(a[3]), "r"(b[0]), "r"(b[1]));
}
__device__ __forceinline__ void mma_f16(float* c, const uint32_t* a, const uint32_t* b) {
    asm volatile("mma.sync.aligned.m16n8k16.row.col.f32.f16.f16.f32 "
                 "{%0,%1,%2,%3}, {%4,%5,%6,%7}, {%8,%9}, {%0,%1,%2,%3};"
                 : "+f"(c[0]), "+f"(c[1]), "+f"(c[2]), "+f"(c[3])
                 : "r"(a[0]), "r"(a[1]), "r"(a[2]), "r"(a[3]), "r"(b[0]), "r"(b[1]));
}
__device__ __forceinline__ void split_write(float x, __nv_bfloat16* h, __nv_bfloat16* l, size_t i) {
    __nv_bfloat16 hv = __float2bfloat16(x);
    h[i] = hv;
    l[i] = __float2bfloat16(x - __bfloat162float(hv));
}
__device__ __forceinline__ void split4(float4 v, __nv_bfloat16* h, __nv_bfloat16* l, size_t i4) {
    __nv_bfloat16 h0 = __float2bfloat16(v.x), h1 = __float2bfloat16(v.y);
    __nv_bfloat16 h2 = __float2bfloat16(v.z), h3 = __float2bfloat16(v.w);
    __nv_bfloat16 l0 = __float2bfloat16(v.x - __bfloat162float(h0));
    __nv_bfloat16 l1 = __float2bfloat16(v.y - __bfloat162float(h1));
    __nv_bfloat16 l2 = __float2bfloat16(v.z - __bfloat162float(h2));
    __nv_bfloat16 l3 = __float2bfloat16(v.w - __bfloat162float(h3));
    __nv_bfloat162 hh0 = {h0, h1}, hh1 = {h2, h3};
    __nv_bfloat162 ll0 = {l0, l1}, ll1 = {l2, l3};
    uint2 hw = make_uint2(*(uint32_t*)&hh0, *(uint32_t*)&hh1);
    uint2 lw = make_uint2(*(uint32_t*)&ll0, *(uint32_t*)&ll1);
    *(uint2*)&h[i4 * 4] = hw;
    *(uint2*)&l[i4 * 4] = lw;
}
__device__ __forceinline__ void half4_write(float4 v, __half* dst, size_t i4) {
    __half2 a = __floats2half2_rn(v.x, v.y);
    __half2 b = __floats2half2_rn(v.z, v.w);
    *(uint2*)&dst[i4 * 4] = make_uint2(*(uint32_t*)&a, *(uint32_t*)&b);
}

#define STAGE_B 65536

// ======== R7 3-stage bf16-split mainloop (two barriers, wait2 pattern) =======
#define PREFETCH_CHUNK(SB, KE)                                                       \
    _Pragma("unroll") for (int t = 0; t < 4; t++)                                    \
        _Pragma("unroll") for (int i = 0; i < 4; i++)                                \
            cpa16((SB) + soff[t][i], srcs[t] + (KE) + i * 8);                        \
    cpa_commit();

#define MAINLOOP_128(NCH)                                                            \
    {                                                                                \
        const int pre = ((NCH) < 2) ? (NCH) : 2;                                     \
        for (int s = 0; s < pre; s++) {                                              \
            const int ke = s * 64 + lhalf * 32;                                      \
            const uint32_t sb = smem32 + (uint32_t)s * STAGE_B;                      \
            PREFETCH_CHUNK(sb, ke)                                                   \
        }                                                                            \
    }                                                                                \
    for (int c = 0; c < (NCH); c++) {                                                \
        if (c + 2 < (NCH)) {                                                         \
            const int ke = (c + 2) * 64 + lhalf * 32;                                \
            const uint32_t sb = smem32 + (uint32_t)((c + 2) % 3) * STAGE_B;          \
            PREFETCH_CHUNK(sb, ke)                                                   \
            cpa_wait2();                                                             \
        } else if (c + 1 < (NCH)) {                                                  \
            cpa_wait1();                                                             \
        } else {                                                                     \
            cpa_wait0();                                                             \
        }                                                                            \
        __syncthreads();                                                             \
        const uint32_t st = smem32 + (uint32_t)(c % 3) * STAGE_B;                    \
        const uint32_t Ah32 = st, Al32 = st + 16384, Bh32 = st + 32768, Bl32 = st + 49152; \
        _Pragma("unroll") for (int ks = 0; ks < 4; ks++) {                           \
            const uint32_t kofs = ks * 32u + qsel * 16u;                             \
            uint32_t ah[4][4], al[4][4];                                             \
            _Pragma("unroll") for (int mf = 0; mf < 4; mf++) {                       \
                int row = wm + mf * 16 + qrow;                                       \
                ldm_x4(ah[mf], Ah32 + sw128((uint32_t)row * 128u + kofs));           \
            }                                                                        \
            uint32_t bh[4][2], bl[4][2];                                             \
            _Pragma("unroll") for (int nh = 0; nh < 2; nh++) {                       \
                int row = wn + nh * 16 + qrow;                                       \
                uint32_t t[4];                                                       \
                ldm_x4(t, Bh32 + sw128((uint32_t)row * 128u + kofs));                \
                bh[nh * 2 + 0][0] = t[0]; bh[nh * 2 + 0][1] = t[2];                  \
                bh[nh * 2 + 1][0] = t[1]; bh[nh * 2 + 1][1] = t[3];                  \
                ldm_x4(t, Bl32 + sw128((uint32_t)row * 128u + kofs));                \
                bl[nh * 2 + 0][0] = t[0]; bl[nh * 2 + 0][1] = t[2];                  \
                bl[nh * 2 + 1][0] = t[1]; bl[nh * 2 + 1][1] = t[3];                  \
            }                                                                        \
            _Pragma("unroll") for (int mf = 0; mf < 4; mf++) {                       \
                int row = wm + mf * 16 + qrow;                                       \
                ldm_x4(al[mf], Al32 + sw128((uint32_t)row * 128u + kofs));           \
            }                                                                        \
            _Pragma("unroll") for (int mf = 0; mf < 4; mf++)                         \
                _Pragma("unroll") for (int nf = 0; nf < 4; nf++)                     \
                    mma_bf16(acc[mf][nf], ah[mf], bh[nf]);                           \
            _Pragma("unroll") for (int mf = 0; mf < 4; mf++)                         \
                _Pragma("unroll") for (int nf = 0; nf < 4; nf++)                     \
                    mma_bf16(acc[mf][nf], ah[mf], bl[nf]);                           \
            _Pragma("unroll") for (int mf = 0; mf < 4; mf++)                         \
                _Pragma("unroll") for (int nf = 0; nf < 4; nf++)                     \
                    mma_bf16(acc[mf][nf], al[mf], bh[nf]);                           \
        }                                                                            \
        __syncthreads();                                                             \
    }

#define DECL_COMMON                                                                  \
    const int tid = threadIdx.x;                                                     \
    const int warp = tid >> 5, lane = tid & 31;                                      \
    const int wm = (warp >> 2) * 64, wn = (warp & 3) * 32;                           \
    const int lrow = tid >> 1, lhalf = tid & 1;                                      \
    const uint32_t smem32 = smem_u32(smem);                                          \
    const int qrow = lane & 15, qsel = lane >> 4;                                    \
    float acc[4][4][4];                                                              \
    _Pragma("unroll") for (int i = 0; i < 4; i++)                                    \
        _Pragma("unroll") for (int j = 0; j < 4; j++)                                \
            _Pragma("unroll") for (int r = 0; r < 4; r++) acc[i][j][r] = 0.f;        \
    uint32_t soff[4][4];                                                             \
    _Pragma("unroll") for (int t = 0; t < 4; t++)                                    \
        _Pragma("unroll") for (int i = 0; i < 4; i++)                                \
            soff[t][i] = (uint32_t)t * 16384u + sw128((uint32_t)lrow * 128u + lhalf * 64u + i * 16u);

// ====== qabs: per-head q_nrope @ w_nr^T (bf16 3-term) -> fp16 qcat ==========
__global__ void __launch_bounds__(256)
qabs_mma()
{
    extern __shared__ char smem[];
    const int h = blockIdx.z;
    const int m0 = blockIdx.y * 128, n0 = blockIdx.x * 128;
    DECL_COMMON
    const __nv_bfloat16* srcs[4];
    srcs[0] = g_qh + (size_t)(m0 + lrow) * (NH * QKD) + h * QKD;
    srcs[1] = g_ql + (size_t)(m0 + lrow) * (NH * QKD) + h * QKD;
    srcs[2] = g_wnrth + (size_t)h * KVR * DNR + (size_t)(n0 + lrow) * DNR;
    srcs[3] = g_wnrtl + (size_t)h * KVR * DNR + (size_t)(n0 + lrow) * DNR;
    MAINLOOP_128(2)
    const int r0 = lane >> 2, c0 = (lane & 3) * 2;
#pragma unroll
    for (int mf = 0; mf < 4; mf++) {
        const int mA = m0 + wm + mf * 16 + r0;
        const int rowA = ((mA >> 5) * ROWSPB) + (mA & 31) * NH + h;
        const int rowB = (((mA + 8) >> 5) * ROWSPB) + ((mA + 8) & 31) * NH + h;
#pragma unroll
        for (int nf = 0; nf < 4; nf++) {
            const int n = n0 + wn + nf * 8 + c0;
            __half2 pa = __floats2half2_rn(acc[mf][nf][0], acc[mf][nf][1]);
            __half2 pb = __floats2half2_rn(acc[mf][nf][2], acc[mf][nf][3]);
            *(__half2*)&g_qc[(size_t)rowA * CATD + n] = pa;
            *(__half2*)&g_qc[(size_t)rowB * CATD + n] = pb;
        }
    }
}

// ====== oup: per-head O @ w_v^T (bf16 3-term) -> split bf16 o2 ===============
__global__ void __launch_bounds__(256)
oup_mma()
{
    extern __shared__ char smem[];
    const int h = blockIdx.z;
    const int m0 = blockIdx.y * 128, n0 = 0;
    DECL_COMMON
    const int mrow = m0 + lrow;
    const int arow = (mrow >> 5) * ROWSPB + (mrow & 31) * NH + h;
    const __nv_bfloat16* srcs[4];
    srcs[0] = g_Oh + (size_t)arow * KVR;
    srcs[1] = g_Ol + (size_t)arow * KVR;
    srcs[2] = g_wvh + (size_t)(h * 256 + DNR + n0 + lrow) * KVR;
    srcs[3] = g_wvl + (size_t)(h * 256 + DNR + n0 + lrow) * KVR;
    MAINLOOP_128(8)
    const int r0 = lane >> 2, c0 = (lane & 3) * 2;
#pragma unroll
    for (int mf = 0; mf < 4; mf++) {
        const int mA = m0 + wm + mf * 16 + r0;
#pragma unroll
        for (int nf = 0; nf < 4; nf++) {
            const int n = n0 + wn + nf * 8 + c0;
            const size_t i0 = (size_t)mA * (NH * DV) + h * DV + n;
            const size_t i1 = (size_t)(mA + 8) * (NH * DV) + h * DV + n;
            split_write(acc[mf][nf][0], g_o2h, g_o2l, i0);
            split_write(acc[mf][nf][1], g_o2h, g_o2l, i0 + 1);
            split_write(acc[mf][nf][2], g_o2h, g_o2l, i1);
            split_write(acc[mf][nf][3], g_o2h, g_o2l, i1 + 1);
        }
    }
}

// ====== split-K projections (bf16 3-term, fp32 atomicAdd) ====================
__global__ void __launch_bounds__(256)
gemm_mma_sk(const __nv_bfloat16* __restrict__ Ah, const __nv_bfloat16* __restrict__ Al,
            const __nv_bfloat16* __restrict__ Bh, const __nv_bfloat16* __restrict__ Bl,
            float* __restrict__ C, int ldc, int K, int kpart, int N)
{
    extern __shared__ char smem[];
    const int m0 = blockIdx.y * 128, n0 = blockIdx.x * 128;
    const int kb = blockIdx.z * kpart;
    DECL_COMMON
    const __nv_bfloat16* srcs[4];
    srcs[0] = Ah + (size_t)(m0 + lrow) * K + kb;
    srcs[1] = Al + (size_t)(m0 + lrow) * K + kb;
    srcs[2] = Bh + (size_t)(n0 + lrow) * K + kb;
    srcs[3] = Bl + (size_t)(n0 + lrow) * K + kb;
    const int nch = kpart >> 6;
    MAINLOOP_128(nch)
    const int r0 = lane >> 2, c0 = (lane & 3) * 2;
#pragma unroll
    for (int mf = 0; mf < 4; mf++) {
        const int mA = m0 + wm + mf * 16 + r0;
#pragma unroll
        for (int nf = 0; nf < 4; nf++) {
            const int n = n0 + wn + nf * 8 + c0;
            if (n < N) {
                atomicAdd(&C[(size_t)mA * ldc + n],           acc[mf][nf][0]);
                atomicAdd(&C[(size_t)mA * ldc + n + 1],       acc[mf][nf][1]);
                atomicAdd(&C[(size_t)(mA + 8) * ldc + n],     acc[mf][nf][2]);
                atomicAdd(&C[(size_t)(mA + 8) * ldc + n + 1], acc[mf][nf][3]);
            }
        }
    }
}

// ====== fp16 single-term scores: 128x256 tile, 2-stage =======================
#define SF_STAGE 49152   // A 16KB @0, B 32KB @16384
__global__ void __launch_bounds__(256)
scores_f16(const __half* __restrict__ Q, size_t sQz,
           const __half* __restrict__ Kc, size_t sKz,
           float* __restrict__ C, int ldc, size_t sCz,
           int K, const float* __restrict__ mask, float scale)
{
    extern __shared__ char smem[];
    const int z = blockIdx.z;
    const int m0 = blockIdx.y * 128, n0 = blockIdx.x * 256;
    Q += (size_t)z * sQz;  Kc += (size_t)z * sKz;  C += (size_t)z * sCz;

    const int tid = threadIdx.x;
    const int warp = tid >> 5, lane = tid & 31;
    const int wm = (warp >> 2) * 64, wn = (warp & 3) * 64;
    const uint32_t smem32 = smem_u32(smem);
    const int qrow = lane & 15, qsel = lane >> 4;

    // 384 rows (A 128 + B 256) as 768 half-rows of 64B; 3 per thread
    const __half* gsrc[3];
    uint32_t swb[3];
#pragma unroll
    for (int j = 0; j < 3; j++) {
        const int h = tid + j * 256;
        const int half = h & 1;
        int r;
        uint32_t tbase;
        const __half* base;
        if (h < 256) { r = h >> 1; tbase = 0u; base = Q + (size_t)(m0 + r) * K; }
        else { r = (h - 256) >> 1; tbase = 16384u; base = Kc + (size_t)(n0 + r) * K; }
        swb[j] = tbase + sw128((uint32_t)r * 128u + half * 64u);
        gsrc[j] = base + half * 32;
    }

    float acc[4][8][4];
#pragma unroll
    for (int i = 0; i < 4; i++)
#pragma unroll
        for (int j = 0; j < 8; j++)
#pragma unroll
            for (int r = 0; r < 4; r++) acc[i][j][r] = 0.f;

    const int nch = K >> 6;
    {
#pragma unroll
        for (int j = 0; j < 3; j++)
#pragma unroll
            for (int i = 0; i < 4; i++)
                cpa16(smem32 + (swb[j] ^ (i * 16u)), gsrc[j] + i * 8);
        cpa_commit();
    }
    for (int c = 0; c < nch; c++) {
        if (c + 1 < nch) {
            const int ke = (c + 1) * 64;
            const uint32_t sb = smem32 + ((c + 1) & 1) * SF_STAGE;
#pragma unroll
            for (int j = 0; j < 3; j++)
#pragma unroll
                for (int i = 0; i < 4; i++)
                    cpa16(sb + (swb[j] ^ (i * 16u)), gsrc[j] + ke + i * 8);
            cpa_commit();
            cpa_wait1();
        } else {
            cpa_wait0();
        }
        __syncthreads();

        const uint32_t st = smem32 + (c & 1) * SF_STAGE;
        const uint32_t A32 = st, B32 = st + 16384;
#pragma unroll
        for (int ks = 0; ks < 4; ks++) {
            const uint32_t kofs = ks * 32u + qsel * 16u;
            uint32_t a[4][4];
#pragma unroll
            for (int mf = 0; mf < 4; mf++) {
                int row = wm + mf * 16 + qrow;
                ldm_x4(a[mf], A32 + sw128((uint32_t)row * 128u + kofs));
            }
            uint32_t b[8][2];
#pragma unroll
            for (int nh = 0; nh < 4; nh++) {
                int row = wn + nh * 16 + qrow;
                uint32_t t[4];
                ldm_x4(t, B32 + sw128((uint32_t)row * 128u + kofs));
                b[nh * 2 + 0][0] = t[0]; b[nh * 2 + 0][1] = t[2];
                b[nh * 2 + 1][0] = t[1]; b[nh * 2 + 1][1] = t[3];
            }
#pragma unroll
            for (int mf = 0; mf < 4; mf++)
#pragma unroll
                for (int nf = 0; nf < 8; nf++)
                    mma_f16(acc[mf][nf], a[mf], b[nf]);
        }
        __syncthreads();
    }

    const int r0 = lane >> 2, c0 = (lane & 3) * 2;
#pragma unroll
    for (int mf = 0; mf < 4; mf++) {
        const int mA = m0 + wm + mf * 16 + r0;
        const float* mrow = mask + (size_t)(mA >> 4) * MAXT;
#pragma unroll
        for (int nf = 0; nf < 8; nf++) {
            const int n = n0 + wn + nf * 8 + c0;
            float v0 = acc[mf][nf][0] * scale + mrow[n];
            float v1 = acc[mf][nf][1] * scale + mrow[n + 1];
            float v2 = acc[mf][nf][2] * scale + mrow[n];
            float v3 = acc[mf][nf][3] * scale + mrow[n + 1];
            *(float2*)&C[(size_t)mA * ldc + n]       = make_float2(v0, v1);
            *(float2*)&C[(size_t)(mA + 8) * ldc + n] = make_float2(v2, v3);
        }
    }
}

// ====== fp16 single-term ogemm: 128x128, 3-stage, split-bf16 out =============
#define OF_STAGE 32768   // A 16KB @0, B 16KB @16384
__global__ void __launch_bounds__(256)
ogemm_f16(const __half* __restrict__ P, size_t sPz,
          const __half* __restrict__ Kt, size_t sKz,
          __nv_bfloat16* __restrict__ Ch, __nv_bfloat16* __restrict__ Cl,
          int ldc, size_t sCz, int K)
{
    extern __shared__ char smem[];
    const int z = blockIdx.z;
    const int m0 = blockIdx.y * 128, n0 = blockIdx.x * 128;
    P += (size_t)z * sPz;  Kt += (size_t)z * sKz;
    Ch += (size_t)z * sCz; Cl += (size_t)z * sCz;

    const int tid = threadIdx.x;
    const int warp = tid >> 5, lane = tid & 31;
    const int wm = (warp >> 2) * 64, wn = (warp & 3) * 32;
    const uint32_t smem32 = smem_u32(smem);
    const int qrow = lane & 15, qsel = lane >> 4;

    const bool isB = tid >= 128;
    const int lrow = tid & 127;
    const __half* src = isB ? (Kt + (size_t)(n0 + lrow) * K)
                            : (P + (size_t)(m0 + lrow) * K);
    uint32_t soff[8];
#pragma unroll
    for (int i = 0; i < 8; i++)
        soff[i] = (isB ? 16384u : 0u) + sw128((uint32_t)lrow * 128u + i * 16u);

    float acc[4][4][4];
#pragma unroll
    for (int i = 0; i < 4; i++)
#pragma unroll
        for (int j = 0; j < 4; j++)
#pragma unroll
            for (int r = 0; r < 4; r++) acc[i][j][r] = 0.f;

    const int nch = K >> 6;
    for (int s = 0; s < 2; s++) {
        const uint32_t sb = smem32 + (uint32_t)s * OF_STAGE;
#pragma unroll
        for (int i = 0; i < 8; i++)
            cpa16(sb + soff[i], src + s * 64 + i * 8);
        cpa_commit();
    }
    for (int c = 0; c < nch; c++) {
        if (c + 2 < nch) {
            const uint32_t sb = smem32 + (uint32_t)((c + 2) % 3) * OF_STAGE;
#pragma unroll
            for (int i = 0; i < 8; i++)
                cpa16(sb + soff[i], src + (c + 2) * 64 + i * 8);
            cpa_commit();
            cpa_wait2();
        } else if (c + 1 < nch) {
            cpa_wait1();
        } else {
            cpa_wait0();
        }
        __syncthreads();

        const uint32_t st = smem32 + (uint32_t)(c % 3) * OF_STAGE;
        const uint32_t A32 = st, B32 = st + 16384;
#pragma unroll
        for (int ks = 0; ks < 4; ks++) {
            const uint32_t kofs = ks * 32u + qsel * 16u;
            uint32_t a[4][4];
#pragma unroll
            for (int mf = 0; mf < 4; mf++) {
                int row = wm + mf * 16 + qrow;
                ldm_x4(a[mf], A32 + sw128((uint32_t)row * 128u + kofs));
            }
            uint32_t b[4][2];
#pragma unroll
            for (int nh = 0; nh < 2; nh++) {
                int row = wn + nh * 16 + qrow;
                uint32_t t[4];
                ldm_x4(t, B32 + sw128((uint32_t)row * 128u + kofs));
                b[nh * 2 + 0][0] = t[0]; b[nh * 2 + 0][1] = t[2];
                b[nh * 2 + 1][0] = t[1]; b[nh * 2 + 1][1] = t[3];
            }
#pragma unroll
            for (int mf = 0; mf < 4; mf++)
#pragma unroll
                for (int nf = 0; nf < 4; nf++)
                    mma_f16(acc[mf][nf], a[mf], b[nf]);
        }
        __syncthreads();
    }

    const int r0 = lane >> 2, c0 = (lane & 3) * 2;
#pragma unroll
    for (int mf = 0; mf < 4; mf++) {
        const int mA = m0 + wm + mf * 16 + r0;
#pragma unroll
        for (int nf = 0; nf < 4; nf++) {
            const int n = n0 + wn + nf * 8 + c0;
            const size_t i0 = (size_t)mA * ldc + n;
            const size_t i1 = (size_t)(mA + 8) * ldc + n;
            split_write(acc[mf][nf][0], Ch, Cl, i0);
            split_write(acc[mf][nf][1], Ch, Cl, i0 + 1);
            split_write(acc[mf][nf][2], Ch, Cl, i1);
            split_write(acc[mf][nf][3], Ch, Cl, i1 + 1);
        }
    }
}

// ================= merged weight/x conversion ================================
#define C4_X    131072
#define C4_QD   (C4_X + 393216)
#define C4_QU   (C4_QD + 589824)
#define C4_KVD  (C4_QU + 327680)
#define C4_OUT  (C4_KVD + 1048576)
#define C4_WKVU (C4_OUT + 524288)
#define KVD_SRC4 294912
__global__ void conv_all(const float4* __restrict__ x, const float4* __restrict__ wqd,
                         const float4* __restrict__ wqu, const float4* __restrict__ wkvd,
                         const float4* __restrict__ wout, const float4* __restrict__ wkvu) {
    const int i = blockIdx.x * 256 + threadIdx.x;
    if (i < C4_X) {
        split4(x[i], g_xh, g_xl, i);
    } else if (i < C4_QD) {
        const int j = i - C4_X;
        split4(wqd[j], g_wqdh, g_wqdl, j);
    } else if (i < C4_QU) {
        const int j = i - C4_QD;
        split4(wqu[j], g_wquh, g_wqul, j);
    } else if (i < C4_KVD) {
        const int j = i - C4_QU;
        float4 v = (j < KVD_SRC4) ? wkvd[j] : make_float4(0.f, 0.f, 0.f, 0.f);
        split4(v, g_wkvdh, g_wkvdl, j);
    } else if (i < C4_OUT) {
        const int j = i - C4_KVD;
        split4(wout[j], g_wouth, g_woutl, j);
    } else if (i < C4_WKVU) {
        const int j = i - C4_OUT;
        split4(wkvu[j], g_wvh, g_wvl, j);
    }
}

// transpose nr part of w_kvu
__global__ void build_wnrt(const float* __restrict__ wkvu) {
    __shared__ float tile[32][33];
    const int h = blockIdx.z;
    const int n0 = blockIdx.x * 32, d0 = blockIdx.y * 32;
    const int tx = threadIdx.x, ty = threadIdx.y;
#pragma unroll
    for (int i = 0; i < 4; i++) {
        const int d = d0 + ty + i * 8;
        tile[ty + i * 8][tx] = wkvu[(size_t)(h * 256 + d) * KVR + n0 + tx];
    }
    __syncthreads();
#pragma unroll
    for (int i = 0; i < 4; i++) {
        const int n = n0 + ty + i * 8;
        const float v = tile[tx][ty + i * 8];
        const size_t o = (size_t)h * KVR * DNR + (size_t)n * DNR + d0 + tx;
        split_write(v, g_wnrth, g_wnrtl, o);
    }
}

// ================= small conversions ========================================
__global__ void conv_split4(const float4* __restrict__ src, __nv_bfloat16* h, __nv_bfloat16* l, int n4) {
    const int i = blockIdx.x * 256 + threadIdx.x;
    if (i < n4) split4(src[i], h, l, i);
}
__global__ void build_kvcat4(const float* __restrict__ kvc, const float* __restrict__ krc) {
    const size_t i4 = (size_t)blockIdx.x * 256 + threadIdx.x;
    const size_t idx = i4 * 4;
    const int c = (int)(idx % CATD);
    const size_t bt = idx / CATD;
    const int t = (int)(bt % MAXT);
    const int b = (int)(bt / MAXT);
    float4 v;
    if (t >= START_P)
        v = *(const float4*)&g_kv[(size_t)((b << 5) + (t - START_P)) * CATD + c];
    else if (c < KVR)
        v = *(const float4*)&kvc[((size_t)b * MAXT + t) * KVR + c];
    else
        v = *(const float4*)&krc[((size_t)b * MAXT + t) * DR + (c - KVR)];
    half4_write(v, g_kc, i4);
}
__global__ void build_kvt(const float* __restrict__ kvc) {
    __shared__ float tile[32][33];
    const int b = blockIdx.z;
    const int t0 = blockIdx.x * 32, n0 = blockIdx.y * 32;
    const int tx = threadIdx.x, ty = threadIdx.y;
#pragma unroll
    for (int i = 0; i < 4; i++) {
        const int t = t0 + ty + i * 8;
        float v;
        if (t >= START_P)
            v = g_kv[(size_t)((b << 5) + (t - START_P)) * CATD + n0 + tx];
        else
            v = kvc[((size_t)b * MAXT + t) * KVR + n0 + tx];
        tile[ty + i * 8][tx] = v;
    }
    __syncthreads();
#pragma unroll
    for (int i = 0; i < 4; i++) {
        const int n = n0 + ty + i * 8;
        const float x = tile[tx][ty + i * 8];
        g_kt[((size_t)(b * KVR + n)) * MAXT + t0 + tx] = __float2half_rn(x);
    }
}

// ================= RMSNorm ===================================================
__global__ void rms_kernel(const float* __restrict__ w) {
    const int row = blockIdx.x;
    const float* xr = g_qd + row * QR;
    __shared__ float red[256];
    const int tid = threadIdx.x;
    float v[3], s = 0.f;
#pragma unroll
    for (int i = 0; i < 3; i++) { v[i] = xr[tid + i * 256]; s += v[i] * v[i]; }
    red[tid] = s; __syncthreads();
    for (int o = 128; o > 0; o >>= 1) {
        if (tid < o) red[tid] += red[tid + o];
        __syncthreads();
    }
    const float r = rsqrtf(red[0] / (float)QR + 1.1920929e-07f);
    __syncthreads();
#pragma unroll
    for (int i = 0; i < 3; i++) {
        const float y = v[i] * r * w[tid + i * 256];
        split_write(y, g_qnh, g_qnl, (size_t)row * QR + tid + i * 256);
    }
}

// ================= rope ======================================================
__global__ void rope_q(const float* __restrict__ fc, const float* __restrict__ fs) {
    const int idx = blockIdx.x * 256 + threadIdx.x;
    const int j = idx & 31, h = (idx >> 5) & 15, l = (idx >> 9) & 31, b = idx >> 14;
    const size_t si = (size_t)(b * SEQ_L + l) * (NH * QKD) + h * QKD + DNR + 2 * j;
    const float xr = __bfloat162float(g_qh[si])     + __bfloat162float(g_ql[si]);
    const float xi = __bfloat162float(g_qh[si + 1]) + __bfloat162float(g_ql[si + 1]);
    const float c = fc[l * 32 + j], s = fs[l * 32 + j];
    const size_t o = (size_t)(b * ROWSPB + l * NH + h) * CATD + KVR + 2 * j;
    *(__half2*)&g_qc[o] = __floats2half2_rn(xr * c - xi * s, xr * s + xi * c);
}
__global__ void rope_k(const float* __restrict__ fc, const float* __restrict__ fs) {
    const int k = blockIdx.x * 256 + threadIdx.x;
    const int j = k & 31, l = (k >> 5) & 31, b = k >> 10;
    float* p = &g_kv[(size_t)(b * SEQ_L + l) * CATD + KVR + 2 * j];
    const float xr = p[0], xi = p[1];
    const float c = fc[l * 32 + j], s = fs[l * 32 + j];
    p[0] = xr * c - xi * s;
    p[1] = xr * s + xi * c;
}

// ================= softmax -> fp16 P =========================================
__global__ void softmax_split() {
    const int row = blockIdx.x;
    float* s = g_S + (size_t)row * MAXT;
    __shared__ float red[256];
    const int tid = threadIdx.x;
    float4 v[4];
    float mx = -INFINITY;
#pragma unroll
    for (int g = 0; g < 4; g++) {
        v[g] = *(float4*)&s[tid * 4 + g * 1024];
        mx = fmaxf(mx, fmaxf(fmaxf(v[g].x, v[g].y), fmaxf(v[g].z, v[g].w)));
    }
    red[tid] = mx; __syncthreads();
    for (int o = 128; o > 0; o >>= 1) {
        if (tid < o) red[tid] = fmaxf(red[tid], red[tid + o]);
        __syncthreads();
    }
    mx = red[0]; __syncthreads();
    float sum = 0.f;
#pragma unroll
    for (int g = 0; g < 4; g++) {
        v[g].x = __expf(v[g].x - mx); v[g].y = __expf(v[g].y - mx);
        v[g].z = __expf(v[g].z - mx); v[g].w = __expf(v[g].w - mx);
        sum += v[g].x + v[g].y + v[g].z + v[g].w;
    }
    red[tid] = sum; __syncthreads();
    for (int o = 128; o > 0; o >>= 1) {
        if (tid < o) red[tid] += red[tid + o];
        __syncthreads();
    }
    const float inv = 1.f / red[0];
#pragma unroll
    for (int g = 0; g < 4; g++) {
        float4 p = make_float4(v[g].x * inv, v[g].y * inv, v[g].z * inv, v[g].w * inv);
        half4_write(p, g_p, ((size_t)row * MAXT + tid * 4 + g * 1024) >> 2);
    }
}

// ============================== launcher =====================================
extern "C" void kernel_launch(void* const* d_in, const int* in_sizes, int n_in,
                              void* d_out, int out_size) {
    const float* x      = (const float*)d_in[0];
    const float* fc     = (const float*)d_in[2];
    const float* fs     = (const float*)d_in[3];
    const float* mask   = (const float*)d_in[4];
    const float* kvc    = (const float*)d_in[5];
    const float* krc    = (const float*)d_in[6];
    const float* w_kvd  = (const float*)d_in[7];
    const float* w_qd   = (const float*)d_in[8];
    const float* rms_w  = (const float*)d_in[9];
    const float* w_qu   = (const float*)d_in[10];
    const float* w_kvu  = (const float*)d_in[11];
    const float* w_out  = (const float*)d_in[12];
    float* out = (float*)d_out;

    float *p_qd, *p_q, *p_kv, *p_S;
    cudaGetSymbolAddress((void**)&p_qd, g_qd);
    cudaGetSymbolAddress((void**)&p_q,  g_q);
    cudaGetSymbolAddress((void**)&p_kv, g_kv);
    cudaGetSymbolAddress((void**)&p_S, g_S);

    __half *qc, *kc, *kt, *pp;
    cudaGetSymbolAddress((void**)&qc, g_qc);
    cudaGetSymbolAddress((void**)&kc, g_kc);
    cudaGetSymbolAddress((void**)&kt, g_kt);
    cudaGetSymbolAddress((void**)&pp, g_p);

    __nv_bfloat16 *xh, *xl, *qnh, *qnl, *qh, *ql, *o2h, *o2l, *Oh, *Ol;
    __nv_bfloat16 *wqdh, *wqdl, *wquh, *wqul, *wkvdh, *wkvdl, *wouth, *woutl;
    cudaGetSymbolAddress((void**)&xh, g_xh);     cudaGetSymbolAddress((void**)&xl, g_xl);
    cudaGetSymbolAddress((void**)&qnh, g_qnh);   cudaGetSymbolAddress((void**)&qnl, g_qnl);
    cudaGetSymbolAddress((void**)&qh, g_qh);     cudaGetSymbolAddress((void**)&ql, g_ql);
    cudaGetSymbolAddress((void**)&o2h, g_o2h);   cudaGetSymbolAddress((void**)&o2l, g_o2l);
    cudaGetSymbolAddress((void**)&Oh, g_Oh);     cudaGetSymbolAddress((void**)&Ol, g_Ol);
    cudaGetSymbolAddress((void**)&wqdh, g_wqdh); cudaGetSymbolAddress((void**)&wqdl, g_wqdl);
    cudaGetSymbolAddress((void**)&wquh, g_wquh); cudaGetSymbolAddress((void**)&wqul, g_wqul);
    cudaGetSymbolAddress((void**)&wkvdh, g_wkvdh); cudaGetSymbolAddress((void**)&wkvdl, g_wkvdl);
    cudaGetSymbolAddress((void**)&wouth, g_wouth); cudaGetSymbolAddress((void**)&woutl, g_woutl);

    static cudaStream_t s_kv = nullptr;
    static cudaEvent_t ev_fork = nullptr, ev_join = nullptr;
    if (!s_kv) {
        cudaStreamCreateWithFlags(&s_kv, cudaStreamNonBlocking);
        cudaEventCreateWithFlags(&ev_fork, cudaEventDisableTiming);
        cudaEventCreateWithFlags(&ev_join, cudaEventDisableTiming);
        cudaFuncSetAttribute(gemm_mma_sk, cudaFuncAttributeMaxDynamicSharedMemorySize, 3 * STAGE_B);
        cudaFuncSetAttribute(qabs_mma, cudaFuncAttributeMaxDynamicSharedMemorySize, 3 * STAGE_B);
        cudaFuncSetAttribute(oup_mma, cudaFuncAttributeMaxDynamicSharedMemorySize, 3 * STAGE_B);
        cudaFuncSetAttribute(scores_f16, cudaFuncAttributeMaxDynamicSharedMemorySize, 2 * SF_STAGE);
        cudaFuncSetAttribute(ogemm_f16, cudaFuncAttributeMaxDynamicSharedMemorySize, 3 * OF_STAGE);
    }
    const int DSM = 3 * STAGE_B;

    // ---- root conversions ----
    conv_all<<<C4_WKVU / 256, 256>>>((const float4*)x, (const float4*)w_qd, (const float4*)w_qu,
                                     (const float4*)w_kvd, (const float4*)w_out, (const float4*)w_kvu);
    build_wnrt<<<dim3(KVR / 32, DNR / 32, NH), dim3(32, 8)>>>(w_kvu);

    // ---- fork: kv-path on s_kv, q-path on default ----
    cudaEventRecord(ev_fork, 0);
    cudaStreamWaitEvent(s_kv, ev_fork, 0);

    // kv path
    cudaMemsetAsync(p_kv, 0, (size_t)MBL * CATD * 4, s_kv);
    gemm_mma_sk<<<dim3(KVD_PAD / 128, MBL / 128, 8), 256, DSM, s_kv>>>(xh, xl, wkvdh, wkvdl,
        p_kv, CATD, DIM, DIM / 8, CATD);
    rope_k<<<BATCH * SEQ_L * 32 / 256, 256, 0, s_kv>>>(fc, fs);
    build_kvcat4<<<(int)(((size_t)BATCH * MAXT * CATD / 4) / 256), 256, 0, s_kv>>>(kvc, krc);
    build_kvt<<<dim3(MAXT / 32, KVR / 32, BATCH), dim3(32, 8), 0, s_kv>>>(kvc);
    cudaEventRecord(ev_join, s_kv);

    // q path
    cudaMemsetAsync(p_qd, 0, (size_t)MBL * QR * 4);
    cudaMemsetAsync(p_q, 0, (size_t)MBL * NH * QKD * 4);
    gemm_mma_sk<<<dim3(QR / 128, MBL / 128, 8), 256, DSM>>>(xh, xl, wqdh, wqdl,
        p_qd, QR, DIM, DIM / 8, QR);
    rms_kernel<<<MBL, 256>>>(rms_w);
    gemm_mma_sk<<<dim3(NH * QKD / 128, MBL / 128, 2), 256, DSM>>>(qnh, qnl, wquh, wqul,
        p_q, NH * QKD, QR, QR / 2, NH * QKD);
    conv_split4<<<(MBL * NH * QKD / 4 + 255) / 256, 256>>>((const float4*)p_q, qh, ql, MBL * NH * QKD / 4);
    rope_q<<<BATCH * SEQ_L * NH * 32 / 256, 256>>>(fc, fs);
    qabs_mma<<<dim3(KVR / 128, MBL / 128, NH), 256, DSM>>>();

    // ---- join q/kv ----
    cudaStreamWaitEvent(0, ev_join, 0);

    // ---- attention (fp16 single-term) ----
    scores_f16<<<dim3(MAXT / 256, ROWSPB / 128, BATCH), 256, 2 * SF_STAGE>>>(
        qc, (size_t)ROWSPB * CATD, kc, (size_t)MAXT * CATD,
        p_S, MAXT, (size_t)ROWSPB * MAXT, CATD, mask, SCALE_F);
    softmax_split<<<BATCH * ROWSPB, 256>>>();
    ogemm_f16<<<dim3(KVR / 128, ROWSPB / 128, BATCH), 256, 3 * OF_STAGE>>>(
        pp, (size_t)ROWSPB * MAXT, kt, (size_t)KVR * MAXT,
        Oh, Ol, KVR, (size_t)ROWSPB * KVR, MAXT);

    // ---- output path ----
    oup_mma<<<dim3(1, MBL / 128, NH), 256, DSM>>>();
    cudaMemsetAsync(out, 0, (size_t)MBL * DIM * 4);
    gemm_mma_sk<<<dim3(DIM / 128, MBL / 128, 8), 256, DSM>>>(o2h, o2l, wouth, woutl,
        out, DIM, NH * DV, NH * DV / 8, DIM);
}

// round 11
// speedup vs baseline: 1.6236x; 1.0268x over previous
#include <cuda_runtime.h>
#include <cuda_bf16.h>
#include <cuda_fp16.h>
#include <math.h>
#include <stdint.h>

// ---------------- problem constants -----------------------------------------
#define BATCH   8
#define SEQ_L   32
#define DIM     2048
#define KVR     512
#define QR      768
#define NH      16
#define DNR     128
#define DR      64
#define DV      128
#define MAXT    4096
#define START_P 4064
#define QKD     192
#define CATD    576
#define MBL     256
#define ROWSPB  512
#define SCALE_F 0.07216878364870323f
#define KVD_PAD 640

// ---------------- fp32 scratch ----------------------------------------------
__device__ __align__(16) float g_qd  [MBL * QR];
__device__ __align__(16) float g_q   [MBL * NH * QKD];
__device__ __align__(16) float g_kv  [MBL * CATD];
// ---------------- fp16 operands ----------------------------------------------
__device__ __align__(16) __half g_S16[(size_t)BATCH * ROWSPB * MAXT];
__device__ __align__(16) __half g_qc [BATCH * ROWSPB * CATD];
__device__ __align__(16) __half g_kc [(size_t)BATCH * MAXT * CATD];
__device__ __align__(16) __half g_kt [(size_t)BATCH * KVR * MAXT];
__device__ __align__(16) __half g_p  [(size_t)BATCH * ROWSPB * MAXT];
__device__ __align__(16) __half g_xf [MBL * DIM];
__device__ __align__(16) __half g_qf [MBL * NH * QKD];
__device__ __align__(16) __half g_wqdf [QR * DIM];
__device__ __align__(16) __half g_wkvdf[KVD_PAD * DIM];
__device__ __align__(16) __half g_wnrtf[NH * KVR * DNR];
// ---------------- bf16 hi/lo (accuracy-critical path) -------------------------
__device__ __align__(16) __nv_bfloat16 g_qnh [MBL * QR];
__device__ __align__(16) __nv_bfloat16 g_qnl [MBL * QR];
__device__ __align__(16) __nv_bfloat16 g_Oh  [BATCH * ROWSPB * KVR];
__device__ __align__(16) __nv_bfloat16 g_Ol  [BATCH * ROWSPB * KVR];
__device__ __align__(16) __nv_bfloat16 g_o2h [MBL * NH * DV];
__device__ __align__(16) __nv_bfloat16 g_o2l [MBL * NH * DV];
__device__ __align__(16) __nv_bfloat16 g_wquh[NH * QKD * QR];
__device__ __align__(16) __nv_bfloat16 g_wqul[NH * QKD * QR];
__device__ __align__(16) __nv_bfloat16 g_wouth[DIM * NH * DV];
__device__ __align__(16) __nv_bfloat16 g_woutl[DIM * NH * DV];
__device__ __align__(16) __nv_bfloat16 g_wvh [NH * 256 * KVR];
__device__ __align__(16) __nv_bfloat16 g_wvl [NH * 256 * KVR];

// ================= helpers ===================================================
__device__ __forceinline__ uint32_t smem_u32(const void* p) {
    uint32_t a;
    asm("{ .reg .u64 t; cvta.to.shared.u64 t, %1; cvt.u32.u64 %0, t; }" : "=r"(a) : "l"(p));
    return a;
}
__device__ __forceinline__ uint32_t sw128(uint32_t o) { return o ^ ((o >> 3) & 0x70); }
__device__ __forceinline__ void cpa16(uint32_t saddr, const void* g) {
    asm volatile("cp.async.cg.shared.global [%0], [%1], 16;" :: "r"(saddr), "l"(g));
}
__device__ __forceinline__ void cpa_commit() { asm volatile("cp.async.commit_group;" ::: "memory"); }
__device__ __forceinline__ void cpa_wait2()  { asm volatile("cp.async.wait_group 2;" ::: "memory"); }
__device__ __forceinline__ void cpa_wait1()  { asm volatile("cp.async.wait_group 1;" ::: "memory"); }
__device__ __forceinline__ void cpa_wait0()  { asm volatile("cp.async.wait_group 0;" ::: "memory"); }
__device__ __forceinline__ void ldm_x4(uint32_t* r, uint32_t addr) {
    asm volatile("ldmatrix.sync.aligned.m8n8.x4.shared.b16 {%0,%1,%2,%3}, [%4];"
                 : "=r"(r[0]), "=r"(r[1]), "=r"(r[2]), "=r"(r[3]) : "r"(addr));
}
__device__ __forceinline__ void mma_bf16(float* c, const uint32_t* a, const uint32_t* b) {
    asm volatile("mma.sync.aligned.m16n8k16.row.col.f32.bf16.bf16.f32 "
                 "{%0,%1,%2,%3}, {%4,%5,%6,%7}, {%8,%9}, {%0,%1,%2,%3};"
                 : "+f"(c[0]), "+f"(c[1]), "+f"(c[2]), "+f"(c[3])
                 : "r"(a[0]), "r"(a[1]), "r"(a[2]), "r"(a[3]), "r"(b[0]), "r"(b[1]));
}
__device__ __forceinline__ void mma_f16(float* c, const uint32_t* a, const uint32_t* b) {
    asm volatile("mma.sync.aligned.m16n8k16.row.col.f32.f16.f16.f32 "
                 "{%0,%1,%2,%3}, {%4,%5,%6,%7}, {%8,%9}, {%0,%1,%2,%3};"
                 : "+f"(c[0]), "+f"(c[1]), "+f"(c[2]), "+f"(c[3])
                 : "r"(a[0]), "r"(a[1]), "r"(a[2]), "r"(a[3]), "r"(b[0]), "r"(b[1]));
}
__device__ __forceinline__ void split_write(float x, __nv_bfloat16* h, __nv_bfloat16* l, size_t i) {
    __nv_bfloat16 hv = __float2bfloat16(x);
    h[i] = hv;
    l[i] = __float2bfloat16(x - __bfloat162float(hv));
}
__device__ __forceinline__ void split4(float4 v, __nv_bfloat16* h, __nv_bfloat16* l, size_t i4) {
    __nv_bfloat16 h0 = __float2bfloat16(v.x), h1 = __float2bfloat16(v.y);
    __nv_bfloat16 h2 = __float2bfloat16(v.z), h3 = __float2bfloat16(v.w);
    __nv_bfloat16 l0 = __float2bfloat16(v.x - __bfloat162float(h0));
    __nv_bfloat16 l1 = __float2bfloat16(v.y - __bfloat162float(h1));
    __nv_bfloat16 l2 = __float2bfloat16(v.z - __bfloat162float(h2));
    __nv_bfloat16 l3 = __float2bfloat16(v.w - __bfloat162float(h3));
    __nv_bfloat162 hh0 = {h0, h1}, hh1 = {h2, h3};
    __nv_bfloat162 ll0 = {l0, l1}, ll1 = {l2, l3};
    uint2 hw = make_uint2(*(uint32_t*)&hh0, *(uint32_t*)&hh1);
    uint2 lw = make_uint2(*(uint32_t*)&ll0, *(uint32_t*)&ll1);
    *(uint2*)&h[i4 * 4] = hw;
    *(uint2*)&l[i4 * 4] = lw;
}
__device__ __forceinline__ void half4_write(float4 v, __half* dst, size_t i4) {
    __half2 a = __floats2half2_rn(v.x, v.y);
    __half2 b = __floats2half2_rn(v.z, v.w);
    *(uint2*)&dst[i4 * 4] = make_uint2(*(uint32_t*)&a, *(uint32_t*)&b);
}

#define STAGE_B 65536
#define OF_STAGE 32768   // fp16 128x128: A 16KB @0, B 16KB @16384

// ======== bf16 3-term mainloop (R7-proven; qu, oup, out-proj) ================
#define PREFETCH_CHUNK(SB, KE)                                                       \
    _Pragma("unroll") for (int t = 0; t < 4; t++)                                    \
        _Pragma("unroll") for (int i = 0; i < 4; i++)                                \
            cpa16((SB) + soff[t][i], srcs[t] + (KE) + i * 8);                        \
    cpa_commit();

#define MAINLOOP_128(NCH)                                                            \
    {                                                                                \
        const int pre = ((NCH) < 2) ? (NCH) : 2;                                     \
        for (int s = 0; s < pre; s++) {                                              \
            const int ke = s * 64 + lhalf * 32;                                      \
            const uint32_t sb = smem32 + (uint32_t)s * STAGE_B;                      \
            PREFETCH_CHUNK(sb, ke)                                                   \
        }                                                                            \
    }                                                                                \
    for (int c = 0; c < (NCH); c++) {                                                \
        if (c + 2 < (NCH)) {                                                         \
            const int ke = (c + 2) * 64 + lhalf * 32;                                \
            const uint32_t sb = smem32 + (uint32_t)((c + 2) % 3) * STAGE_B;          \
            PREFETCH_CHUNK(sb, ke)                                                   \
            cpa_wait2();                                                             \
        } else if (c + 1 < (NCH)) {                                                  \
            cpa_wait1();                                                             \
        } else {                                                                     \
            cpa_wait0();                                                             \
        }                                                                            \
        __syncthreads();                                                             \
        const uint32_t st = smem32 + (uint32_t)(c % 3) * STAGE_B;                    \
        const uint32_t Ah32 = st, Al32 = st + 16384, Bh32 = st + 32768, Bl32 = st + 49152; \
        _Pragma("unroll") for (int ks = 0; ks < 4; ks++) {                           \
            const uint32_t kofs = ks * 32u + qsel * 16u;                             \
            uint32_t ah[4][4], al[4][4];                                             \
            _Pragma("unroll") for (int mf = 0; mf < 4; mf++) {                       \
                int row = wm + mf * 16 + qrow;                                       \
                ldm_x4(ah[mf], Ah32 + sw128((uint32_t)row * 128u + kofs));           \
            }                                                                        \
            uint32_t bh[4][2], bl[4][2];                                             \
            _Pragma("unroll") for (int nh = 0; nh < 2; nh++) {                       \
                int row = wn + nh * 16 + qrow;                                       \
                uint32_t t[4];                                                       \
                ldm_x4(t, Bh32 + sw128((uint32_t)row * 128u + kofs));                \
                bh[nh * 2 + 0][0] = t[0]; bh[nh * 2 + 0][1] = t[2];                  \
                bh[nh * 2 + 1][0] = t[1]; bh[nh * 2 + 1][1] = t[3];                  \
                ldm_x4(t, Bl32 + sw128((uint32_t)row * 128u + kofs));                \
                bl[nh * 2 + 0][0] = t[0]; bl[nh * 2 + 0][1] = t[2];                  \
                bl[nh * 2 + 1][0] = t[1]; bl[nh * 2 + 1][1] = t[3];                  \
            }                                                                        \
            _Pragma("unroll") for (int mf = 0; mf < 4; mf++) {                       \
                int row = wm + mf * 16 + qrow;                                       \
                ldm_x4(al[mf], Al32 + sw128((uint32_t)row * 128u + kofs));           \
            }                                                                        \
            _Pragma("unroll") for (int mf = 0; mf < 4; mf++)                         \
                _Pragma("unroll") for (int nf = 0; nf < 4; nf++)                     \
                    mma_bf16(acc[mf][nf], ah[mf], bh[nf]);                           \
            _Pragma("unroll") for (int mf = 0; mf < 4; mf++)                         \
                _Pragma("unroll") for (int nf = 0; nf < 4; nf++)                     \
                    mma_bf16(acc[mf][nf], ah[mf], bl[nf]);                           \
            _Pragma("unroll") for (int mf = 0; mf < 4; mf++)                         \
                _Pragma("unroll") for (int nf = 0; nf < 4; nf++)                     \
                    mma_bf16(acc[mf][nf], al[mf], bh[nf]);                           \
        }                                                                            \
        __syncthreads();                                                             \
    }

#define DECL_COMMON                                                                  \
    const int tid = threadIdx.x;                                                     \
    const int warp = tid >> 5, lane = tid & 31;                                      \
    const int wm = (warp >> 2) * 64, wn = (warp & 3) * 32;                           \
    const int lrow = tid >> 1, lhalf = tid & 1;                                      \
    const uint32_t smem32 = smem_u32(smem);                                          \
    const int qrow = lane & 15, qsel = lane >> 4;                                    \
    float acc[4][4][4];                                                              \
    _Pragma("unroll") for (int i = 0; i < 4; i++)                                    \
        _Pragma("unroll") for (int j = 0; j < 4; j++)                                \
            _Pragma("unroll") for (int r = 0; r < 4; r++) acc[i][j][r] = 0.f;        \
    uint32_t soff[4][4];                                                             \
    _Pragma("unroll") for (int t = 0; t < 4; t++)                                    \
        _Pragma("unroll") for (int i = 0; i < 4; i++)                                \
            soff[t][i] = (uint32_t)t * 16384u + sw128((uint32_t)lrow * 128u + lhalf * 64u + i * 16u);

// ======== fp16 128x128 single-term mainloop (one row / thread loader) ========
#define F16_PREFETCH(STAGE, CH)                                                      \
    {                                                                                \
        const uint32_t sb = smem32 + (uint32_t)(STAGE) * OF_STAGE;                   \
        _Pragma("unroll") for (int i = 0; i < 8; i++)                                \
            cpa16(sb + soff[i], src + (CH) * 64 + i * 8);                            \
        cpa_commit();                                                                \
    }

#define F16_MAINLOOP(NCH)                                                            \
    {                                                                                \
        const int pre = ((NCH) < 2) ? (NCH) : 2;                                     \
        for (int s = 0; s < pre; s++) F16_PREFETCH(s, s)                             \
    }                                                                                \
    for (int c = 0; c < (NCH); c++) {                                                \
        if (c + 2 < (NCH)) {                                                         \
            F16_PREFETCH((c + 2) % 3, c + 2)                                         \
            cpa_wait2();                                                             \
        } else if (c + 1 < (NCH)) {                                                  \
            cpa_wait1();                                                             \
        } else {                                                                     \
            cpa_wait0();                                                             \
        }                                                                            \
        __syncthreads();                                                             \
        const uint32_t st = smem32 + (uint32_t)(c % 3) * OF_STAGE;                   \
        const uint32_t A32 = st, B32 = st + 16384;                                   \
        _Pragma("unroll") for (int ks = 0; ks < 4; ks++) {                           \
            const uint32_t kofs = ks * 32u + qsel * 16u;                             \
            uint32_t a[4][4];                                                        \
            _Pragma("unroll") for (int mf = 0; mf < 4; mf++) {                       \
                int row = wm + mf * 16 + qrow;                                       \
                ldm_x4(a[mf], A32 + sw128((uint32_t)row * 128u + kofs));             \
            }                                                                        \
            uint32_t b[4][2];                                                        \
            _Pragma("unroll") for (int nh = 0; nh < 2; nh++) {                       \
                int row = wn + nh * 16 + qrow;                                       \
                uint32_t t[4];                                                       \
                ldm_x4(t, B32 + sw128((uint32_t)row * 128u + kofs));                 \
                b[nh * 2 + 0][0] = t[0]; b[nh * 2 + 0][1] = t[2];                    \
                b[nh * 2 + 1][0] = t[1]; b[nh * 2 + 1][1] = t[3];                    \
            }                                                                        \
            _Pragma("unroll") for (int mf = 0; mf < 4; mf++)                         \
                _Pragma("unroll") for (int nf = 0; nf < 4; nf++)                     \
                    mma_f16(acc[mf][nf], a[mf], b[nf]);                              \
        }                                                                            \
        __syncthreads();                                                             \
    }

#define F16_DECL                                                                     \
    const int tid = threadIdx.x;                                                     \
    const int warp = tid >> 5, lane = tid & 31;                                      \
    const int wm = (warp >> 2) * 64, wn = (warp & 3) * 32;                           \
    const uint32_t smem32 = smem_u32(smem);                                          \
    const int qrow = lane & 15, qsel = lane >> 4;                                    \
    const bool isB = tid >= 128;                                                     \
    const int lrow = tid & 127;                                                      \
    uint32_t soff[8];                                                                \
    _Pragma("unroll") for (int i = 0; i < 8; i++)                                    \
        soff[i] = (isB ? 16384u : 0u) + sw128((uint32_t)lrow * 128u + i * 16u);      \
    float acc[4][4][4];                                                              \
    _Pragma("unroll") for (int i = 0; i < 4; i++)                                    \
        _Pragma("unroll") for (int j = 0; j < 4; j++)                                \
            _Pragma("unroll") for (int r = 0; r < 4; r++) acc[i][j][r] = 0.f;

// ====== fp16 split-K projections (qd, kvd): fp32 atomicAdd epilogue ==========
__global__ void __launch_bounds__(256)
gemm_f16_sk(const __half* __restrict__ A, const __half* __restrict__ B,
            float* __restrict__ C, int ldc, int K, int kpart, int N)
{
    extern __shared__ char smem[];
    const int m0 = blockIdx.y * 128, n0 = blockIdx.x * 128;
    const int kb = blockIdx.z * kpart;
    F16_DECL
    const __half* src = isB ? (B + (size_t)(n0 + lrow) * K + kb)
                            : (A + (size_t)(m0 + lrow) * K + kb);
    const int nch = kpart >> 6;
    F16_MAINLOOP(nch)
    const int r0 = lane >> 2, c0 = (lane & 3) * 2;
#pragma unroll
    for (int mf = 0; mf < 4; mf++) {
        const int mA = m0 + wm + mf * 16 + r0;
#pragma unroll
        for (int nf = 0; nf < 4; nf++) {
            const int n = n0 + wn + nf * 8 + c0;
            if (n < N) {
                atomicAdd(&C[(size_t)mA * ldc + n],           acc[mf][nf][0]);
                atomicAdd(&C[(size_t)mA * ldc + n + 1],       acc[mf][nf][1]);
                atomicAdd(&C[(size_t)(mA + 8) * ldc + n],     acc[mf][nf][2]);
                atomicAdd(&C[(size_t)(mA + 8) * ldc + n + 1], acc[mf][nf][3]);
            }
        }
    }
}

// ====== qabs fp16: per-head q_nrope @ w_nr^T -> fp16 qcat ====================
__global__ void __launch_bounds__(256)
qabs_f16()
{
    extern __shared__ char smem[];
    const int h = blockIdx.z;
    const int m0 = blockIdx.y * 128, n0 = blockIdx.x * 128;
    F16_DECL
    const __half* src = isB ? (g_wnrtf + (size_t)h * KVR * DNR + (size_t)(n0 + lrow) * DNR)
                            : (g_qf + (size_t)(m0 + lrow) * (NH * QKD) + h * QKD);
    F16_MAINLOOP(2)
    const int r0 = lane >> 2, c0 = (lane & 3) * 2;
#pragma unroll
    for (int mf = 0; mf < 4; mf++) {
        const int mA = m0 + wm + mf * 16 + r0;
        const int rowA = ((mA >> 5) * ROWSPB) + (mA & 31) * NH + h;
        const int rowB = (((mA + 8) >> 5) * ROWSPB) + ((mA + 8) & 31) * NH + h;
#pragma unroll
        for (int nf = 0; nf < 4; nf++) {
            const int n = n0 + wn + nf * 8 + c0;
            *(__half2*)&g_qc[(size_t)rowA * CATD + n] = __floats2half2_rn(acc[mf][nf][0], acc[mf][nf][1]);
            *(__half2*)&g_qc[(size_t)rowB * CATD + n] = __floats2half2_rn(acc[mf][nf][2], acc[mf][nf][3]);
        }
    }
}

// ====== fp16 single-term ogemm: 128x128, split-bf16 out ======================
__global__ void __launch_bounds__(256)
ogemm_f16(const __half* __restrict__ P, size_t sPz,
          const __half* __restrict__ Kt, size_t sKz,
          __nv_bfloat16* __restrict__ Ch, __nv_bfloat16* __restrict__ Cl,
          int ldc, size_t sCz, int K)
{
    extern __shared__ char smem[];
    const int z = blockIdx.z;
    const int m0 = blockIdx.y * 128, n0 = blockIdx.x * 128;
    P += (size_t)z * sPz;  Kt += (size_t)z * sKz;
    Ch += (size_t)z * sCz; Cl += (size_t)z * sCz;
    F16_DECL
    const __half* src = isB ? (Kt + (size_t)(n0 + lrow) * K)
                            : (P + (size_t)(m0 + lrow) * K);
    const int nch = K >> 6;
    F16_MAINLOOP(nch)
    const int r0 = lane >> 2, c0 = (lane & 3) * 2;
#pragma unroll
    for (int mf = 0; mf < 4; mf++) {
        const int mA = m0 + wm + mf * 16 + r0;
#pragma unroll
        for (int nf = 0; nf < 4; nf++) {
            const int n = n0 + wn + nf * 8 + c0;
            const size_t i0 = (size_t)mA * ldc + n;
            const size_t i1 = (size_t)(mA + 8) * ldc + n;
            split_write(acc[mf][nf][0], Ch, Cl, i0);
            split_write(acc[mf][nf][1], Ch, Cl, i0 + 1);
            split_write(acc[mf][nf][2], Ch, Cl, i1);
            split_write(acc[mf][nf][3], Ch, Cl, i1 + 1);
        }
    }
}

// ====== bf16 3-term split-K (qu, out-proj): fp32 atomicAdd ===================
__global__ void __launch_bounds__(256)
gemm_mma_sk(const __nv_bfloat16* __restrict__ Ah, const __nv_bfloat16* __restrict__ Al,
            const __nv_bfloat16* __restrict__ Bh, const __nv_bfloat16* __restrict__ Bl,
            float* __restrict__ C, int ldc, int K, int kpart, int N)
{
    extern __shared__ char smem[];
    const int m0 = blockIdx.y * 128, n0 = blockIdx.x * 128;
    const int kb = blockIdx.z * kpart;
    DECL_COMMON
    const __nv_bfloat16* srcs[4];
    srcs[0] = Ah + (size_t)(m0 + lrow) * K + kb;
    srcs[1] = Al + (size_t)(m0 + lrow) * K + kb;
    srcs[2] = Bh + (size_t)(n0 + lrow) * K + kb;
    srcs[3] = Bl + (size_t)(n0 + lrow) * K + kb;
    const int nch = kpart >> 6;
    MAINLOOP_128(nch)
    const int r0 = lane >> 2, c0 = (lane & 3) * 2;
#pragma unroll
    for (int mf = 0; mf < 4; mf++) {
        const int mA = m0 + wm + mf * 16 + r0;
#pragma unroll
        for (int nf = 0; nf < 4; nf++) {
            const int n = n0 + wn + nf * 8 + c0;
            if (n < N) {
                atomicAdd(&C[(size_t)mA * ldc + n],           acc[mf][nf][0]);
                atomicAdd(&C[(size_t)mA * ldc + n + 1],       acc[mf][nf][1]);
                atomicAdd(&C[(size_t)(mA + 8) * ldc + n],     acc[mf][nf][2]);
                atomicAdd(&C[(size_t)(mA + 8) * ldc + n + 1], acc[mf][nf][3]);
            }
        }
    }
}

// ====== oup: per-head O @ w_v^T (bf16 3-term) -> split bf16 o2 ===============
__global__ void __launch_bounds__(256)
oup_mma()
{
    extern __shared__ char smem[];
    const int h = blockIdx.z;
    const int m0 = blockIdx.y * 128, n0 = 0;
    DECL_COMMON
    const int mrow = m0 + lrow;
    const int arow = (mrow >> 5) * ROWSPB + (mrow & 31) * NH + h;
    const __nv_bfloat16* srcs[4];
    srcs[0] = g_Oh + (size_t)arow * KVR;
    srcs[1] = g_Ol + (size_t)arow * KVR;
    srcs[2] = g_wvh + (size_t)(h * 256 + DNR + n0 + lrow) * KVR;
    srcs[3] = g_wvl + (size_t)(h * 256 + DNR + n0 + lrow) * KVR;
    MAINLOOP_128(8)
    const int r0 = lane >> 2, c0 = (lane & 3) * 2;
#pragma unroll
    for (int mf = 0; mf < 4; mf++) {
        const int mA = m0 + wm + mf * 16 + r0;
#pragma unroll
        for (int nf = 0; nf < 4; nf++) {
            const int n = n0 + wn + nf * 8 + c0;
            const size_t i0 = (size_t)mA * (NH * DV) + h * DV + n;
            const size_t i1 = (size_t)(mA + 8) * (NH * DV) + h * DV + n;
            split_write(acc[mf][nf][0], g_o2h, g_o2l, i0);
            split_write(acc[mf][nf][1], g_o2h, g_o2l, i0 + 1);
            split_write(acc[mf][nf][2], g_o2h, g_o2l, i1);
            split_write(acc[mf][nf][3], g_o2h, g_o2l, i1 + 1);
        }
    }
}

// ====== fp16 scores 128x256 tile, 2-stage, fp16 S output =====================
#define SF_STAGE 49152
__global__ void __launch_bounds__(256)
scores_f16(const __half* __restrict__ Q, size_t sQz,
           const __half* __restrict__ Kc, size_t sKz,
           __half* __restrict__ C, int ldc, size_t sCz,
           int K, const float* __restrict__ mask, float scale)
{
    extern __shared__ char smem[];
    const int z = blockIdx.z;
    const int m0 = blockIdx.y * 128, n0 = blockIdx.x * 256;
    Q += (size_t)z * sQz;  Kc += (size_t)z * sKz;  C += (size_t)z * sCz;

    const int tid = threadIdx.x;
    const int warp = tid >> 5, lane = tid & 31;
    const int wm = (warp >> 2) * 64, wn = (warp & 3) * 64;
    const uint32_t smem32 = smem_u32(smem);
    const int qrow = lane & 15, qsel = lane >> 4;

    const __half* gsrc[3];
    uint32_t swb[3];
#pragma unroll
    for (int j = 0; j < 3; j++) {
        const int h = tid + j * 256;
        const int half = h & 1;
        int r;
        uint32_t tbase;
        const __half* base;
        if (h < 256) { r = h >> 1; tbase = 0u; base = Q + (size_t)(m0 + r) * K; }
        else { r = (h - 256) >> 1; tbase = 16384u; base = Kc + (size_t)(n0 + r) * K; }
        swb[j] = tbase + sw128((uint32_t)r * 128u + half * 64u);
        gsrc[j] = base + half * 32;
    }

    float acc[4][8][4];
#pragma unroll
    for (int i = 0; i < 4; i++)
#pragma unroll
        for (int j = 0; j < 8; j++)
#pragma unroll
            for (int r = 0; r < 4; r++) acc[i][j][r] = 0.f;

    const int nch = K >> 6;
    {
#pragma unroll
        for (int j = 0; j < 3; j++)
#pragma unroll
            for (int i = 0; i < 4; i++)
                cpa16(smem32 + (swb[j] ^ (i * 16u)), gsrc[j] + i * 8);
        cpa_commit();
    }
    for (int c = 0; c < nch; c++) {
        if (c + 1 < nch) {
            const int ke = (c + 1) * 64;
            const uint32_t sb = smem32 + ((c + 1) & 1) * SF_STAGE;
#pragma unroll
            for (int j = 0; j < 3; j++)
#pragma unroll
                for (int i = 0; i < 4; i++)
                    cpa16(sb + (swb[j] ^ (i * 16u)), gsrc[j] + ke + i * 8);
            cpa_commit();
            cpa_wait1();
        } else {
            cpa_wait0();
        }
        __syncthreads();

        const uint32_t st = smem32 + (c & 1) * SF_STAGE;
        const uint32_t A32 = st, B32 = st + 16384;
#pragma unroll
        for (int ks = 0; ks < 4; ks++) {
            const uint32_t kofs = ks * 32u + qsel * 16u;
            uint32_t a[4][4];
#pragma unroll
            for (int mf = 0; mf < 4; mf++) {
                int row = wm + mf * 16 + qrow;
                ldm_x4(a[mf], A32 + sw128((uint32_t)row * 128u + kofs));
            }
            uint32_t b[8][2];
#pragma unroll
            for (int nh = 0; nh < 4; nh++) {
                int row = wn + nh * 16 + qrow;
                uint32_t t[4];
                ldm_x4(t, B32 + sw128((uint32_t)row * 128u + kofs));
                b[nh * 2 + 0][0] = t[0]; b[nh * 2 + 0][1] = t[2];
                b[nh * 2 + 1][0] = t[1]; b[nh * 2 + 1][1] = t[3];
            }
#pragma unroll
            for (int mf = 0; mf < 4; mf++)
#pragma unroll
                for (int nf = 0; nf < 8; nf++)
                    mma_f16(acc[mf][nf], a[mf], b[nf]);
        }
        __syncthreads();
    }

    const int r0 = lane >> 2, c0 = (lane & 3) * 2;
#pragma unroll
    for (int mf = 0; mf < 4; mf++) {
        const int mA = m0 + wm + mf * 16 + r0;
        const float* mrow = mask + (size_t)(mA >> 4) * MAXT;
#pragma unroll
        for (int nf = 0; nf < 8; nf++) {
            const int n = n0 + wn + nf * 8 + c0;
            float v0 = acc[mf][nf][0] * scale + mrow[n];
            float v1 = acc[mf][nf][1] * scale + mrow[n + 1];
            float v2 = acc[mf][nf][2] * scale + mrow[n];
            float v3 = acc[mf][nf][3] * scale + mrow[n + 1];
            *(__half2*)&C[(size_t)mA * ldc + n]       = __floats2half2_rn(v0, v1);
            *(__half2*)&C[(size_t)(mA + 8) * ldc + n] = __floats2half2_rn(v2, v3);
        }
    }
}

// ================= merged weight/x conversion ================================
#define C4_X    131072
#define C4_QD   (C4_X + 393216)
#define C4_QU   (C4_QD + 589824)
#define C4_KVD  (C4_QU + 327680)
#define C4_OUT  (C4_KVD + 1048576)
#define C4_WKVU (C4_OUT + 524288)
#define KVD_SRC4 294912
__global__ void conv_all(const float4* __restrict__ x, const float4* __restrict__ wqd,
                         const float4* __restrict__ wqu, const float4* __restrict__ wkvd,
                         const float4* __restrict__ wout, const float4* __restrict__ wkvu) {
    const int i = blockIdx.x * 256 + threadIdx.x;
    if (i < C4_X) {
        half4_write(x[i], g_xf, i);
    } else if (i < C4_QD) {
        const int j = i - C4_X;
        half4_write(wqd[j], g_wqdf, j);
    } else if (i < C4_QU) {
        const int j = i - C4_QD;
        split4(wqu[j], g_wquh, g_wqul, j);
    } else if (i < C4_KVD) {
        const int j = i - C4_QU;
        float4 v = (j < KVD_SRC4) ? wkvd[j] : make_float4(0.f, 0.f, 0.f, 0.f);
        half4_write(v, g_wkvdf, j);
    } else if (i < C4_OUT) {
        const int j = i - C4_KVD;
        split4(wout[j], g_wouth, g_woutl, j);
    } else if (i < C4_WKVU) {
        const int j = i - C4_OUT;
        split4(wkvu[j], g_wvh, g_wvl, j);
    }
}

// transpose nr part of w_kvu -> fp16
__global__ void build_wnrt(const float* __restrict__ wkvu) {
    __shared__ float tile[32][33];
    const int h = blockIdx.z;
    const int n0 = blockIdx.x * 32, d0 = blockIdx.y * 32;
    const int tx = threadIdx.x, ty = threadIdx.y;
#pragma unroll
    for (int i = 0; i < 4; i++) {
        const int d = d0 + ty + i * 8;
        tile[ty + i * 8][tx] = wkvu[(size_t)(h * 256 + d) * KVR + n0 + tx];
    }
    __syncthreads();
#pragma unroll
    for (int i = 0; i < 4; i++) {
        const int n = n0 + ty + i * 8;
        const float v = tile[tx][ty + i * 8];
        g_wnrtf[(size_t)h * KVR * DNR + (size_t)n * DNR + d0 + tx] = __float2half_rn(v);
    }
}

// ================= small conversions ========================================
__global__ void conv_f16(const float4* __restrict__ src, __half* dst, int n4) {
    const int i = blockIdx.x * 256 + threadIdx.x;
    if (i < n4) half4_write(src[i], dst, i);
}
__global__ void build_kvcat4(const float* __restrict__ kvc, const float* __restrict__ krc) {
    const size_t i4 = (size_t)blockIdx.x * 256 + threadIdx.x;
    const size_t idx = i4 * 4;
    const int c = (int)(idx % CATD);
    const size_t bt = idx / CATD;
    const int t = (int)(bt % MAXT);
    const int b = (int)(bt / MAXT);
    float4 v;
    if (t >= START_P)
        v = *(const float4*)&g_kv[(size_t)((b << 5) + (t - START_P)) * CATD + c];
    else if (c < KVR)
        v = *(const float4*)&kvc[((size_t)b * MAXT + t) * KVR + c];
    else
        v = *(const float4*)&krc[((size_t)b * MAXT + t) * DR + (c - KVR)];
    half4_write(v, g_kc, i4);
}
__global__ void build_kvt(const float* __restrict__ kvc) {
    __shared__ float tile[32][33];
    const int b = blockIdx.z;
    const int t0 = blockIdx.x * 32, n0 = blockIdx.y * 32;
    const int tx = threadIdx.x, ty = threadIdx.y;
#pragma unroll
    for (int i = 0; i < 4; i++) {
        const int t = t0 + ty + i * 8;
        float v;
        if (t >= START_P)
            v = g_kv[(size_t)((b << 5) + (t - START_P)) * CATD + n0 + tx];
        else
            v = kvc[((size_t)b * MAXT + t) * KVR + n0 + tx];
        tile[ty + i * 8][tx] = v;
    }
    __syncthreads();
#pragma unroll
    for (int i = 0; i < 4; i++) {
        const int n = n0 + ty + i * 8;
        const float x = tile[tx][ty + i * 8];
        g_kt[((size_t)(b * KVR + n)) * MAXT + t0 + tx] = __float2half_rn(x);
    }
}

// ================= RMSNorm (bf16 split out for qu) ===========================
__global__ void rms_kernel(const float* __restrict__ w) {
    const int row = blockIdx.x;
    const float* xr = g_qd + row * QR;
    __shared__ float red[256];
    const int tid = threadIdx.x;
    float v[3], s = 0.f;
#pragma unroll
    for (int i = 0; i < 3; i++) { v[i] = xr[tid + i * 256]; s += v[i] * v[i]; }
    red[tid] = s; __syncthreads();
    for (int o = 128; o > 0; o >>= 1) {
        if (tid < o) red[tid] += red[tid + o];
        __syncthreads();
    }
    const float r = rsqrtf(red[0] / (float)QR + 1.1920929e-07f);
    __syncthreads();
#pragma unroll
    for (int i = 0; i < 3; i++) {
        const float y = v[i] * r * w[tid + i * 256];
        split_write(y, g_qnh, g_qnl, (size_t)row * QR + tid + i * 256);
    }
}

// ================= rope ======================================================
__global__ void rope_q(const float* __restrict__ fc, const float* __restrict__ fs) {
    const int idx = blockIdx.x * 256 + threadIdx.x;
    const int j = idx & 31, h = (idx >> 5) & 15, l = (idx >> 9) & 31, b = idx >> 14;
    const size_t si = (size_t)(b * SEQ_L + l) * (NH * QKD) + h * QKD + DNR + 2 * j;
    const float xr = __half2float(g_qf[si]);
    const float xi = __half2float(g_qf[si + 1]);
    const float c = fc[l * 32 + j], s = fs[l * 32 + j];
    const size_t o = (size_t)(b * ROWSPB + l * NH + h) * CATD + KVR + 2 * j;
    *(__half2*)&g_qc[o] = __floats2half2_rn(xr * c - xi * s, xr * s + xi * c);
}
__global__ void rope_k(const float* __restrict__ fc, const float* __restrict__ fs) {
    const int k = blockIdx.x * 256 + threadIdx.x;
    const int j = k & 31, l = (k >> 5) & 31, b = k >> 10;
    float* p = &g_kv[(size_t)(b * SEQ_L + l) * CATD + KVR + 2 * j];
    const float xr = p[0], xi = p[1];
    const float c = fc[l * 32 + j], s = fs[l * 32 + j];
    p[0] = xr * c - xi * s;
    p[1] = xr * s + xi * c;
}

// ================= softmax (fp16 in) -> fp16 P ===============================
__global__ void softmax_split() {
    const int row = blockIdx.x;
    const __half* srow = g_S16 + (size_t)row * MAXT;
    __shared__ float red[256];
    const int tid = threadIdx.x;
    float4 v[4];
    float mx = -INFINITY;
#pragma unroll
    for (int g = 0; g < 4; g++) {
        uint2 r = *(const uint2*)&srow[tid * 4 + g * 1024];
        float2 fa = __half22float2(*(__half2*)&r.x);
        float2 fb = __half22float2(*(__half2*)&r.y);
        v[g] = make_float4(fa.x, fa.y, fb.x, fb.y);
        mx = fmaxf(mx, fmaxf(fmaxf(v[g].x, v[g].y), fmaxf(v[g].z, v[g].w)));
    }
    red[tid] = mx; __syncthreads();
    for (int o = 128; o > 0; o >>= 1) {
        if (tid < o) red[tid] = fmaxf(red[tid], red[tid + o]);
        __syncthreads();
    }
    mx = red[0]; __syncthreads();
    float sum = 0.f;
#pragma unroll
    for (int g = 0; g < 4; g++) {
        v[g].x = __expf(v[g].x - mx); v[g].y = __expf(v[g].y - mx);
        v[g].z = __expf(v[g].z - mx); v[g].w = __expf(v[g].w - mx);
        sum += v[g].x + v[g].y + v[g].z + v[g].w;
    }
    red[tid] = sum; __syncthreads();
    for (int o = 128; o > 0; o >>= 1) {
        if (tid < o) red[tid] += red[tid + o];
        __syncthreads();
    }
    const float inv = 1.f / red[0];
#pragma unroll
    for (int g = 0; g < 4; g++) {
        float4 p = make_float4(v[g].x * inv, v[g].y * inv, v[g].z * inv, v[g].w * inv);
        half4_write(p, g_p, ((size_t)row * MAXT + tid * 4 + g * 1024) >> 2);
    }
}

// ============================== launcher =====================================
extern "C" void kernel_launch(void* const* d_in, const int* in_sizes, int n_in,
                              void* d_out, int out_size) {
    const float* x      = (const float*)d_in[0];
    const float* fc     = (const float*)d_in[2];
    const float* fs     = (const float*)d_in[3];
    const float* mask   = (const float*)d_in[4];
    const float* kvc    = (const float*)d_in[5];
    const float* krc    = (const float*)d_in[6];
    const float* w_kvd  = (const float*)d_in[7];
    const float* w_qd   = (const float*)d_in[8];
    const float* rms_w  = (const float*)d_in[9];
    const float* w_qu   = (const float*)d_in[10];
    const float* w_kvu  = (const float*)d_in[11];
    const float* w_out  = (const float*)d_in[12];
    float* out = (float*)d_out;

    float *p_qd, *p_q, *p_kv;
    cudaGetSymbolAddress((void**)&p_qd, g_qd);
    cudaGetSymbolAddress((void**)&p_q,  g_q);
    cudaGetSymbolAddress((void**)&p_kv, g_kv);

    __half *qc, *kc, *kt, *pp, *S16, *xf, *qf, *wqdf, *wkvdf;
    cudaGetSymbolAddress((void**)&qc, g_qc);
    cudaGetSymbolAddress((void**)&kc, g_kc);
    cudaGetSymbolAddress((void**)&kt, g_kt);
    cudaGetSymbolAddress((void**)&pp, g_p);
    cudaGetSymbolAddress((void**)&S16, g_S16);
    cudaGetSymbolAddress((void**)&xf, g_xf);
    cudaGetSymbolAddress((void**)&qf, g_qf);
    cudaGetSymbolAddress((void**)&wqdf, g_wqdf);
    cudaGetSymbolAddress((void**)&wkvdf, g_wkvdf);

    __nv_bfloat16 *qnh, *qnl, *o2h, *o2l, *Oh, *Ol;
    __nv_bfloat16 *wquh, *wqul, *wouth, *woutl;
    cudaGetSymbolAddress((void**)&qnh, g_qnh);   cudaGetSymbolAddress((void**)&qnl, g_qnl);
    cudaGetSymbolAddress((void**)&o2h, g_o2h);   cudaGetSymbolAddress((void**)&o2l, g_o2l);
    cudaGetSymbolAddress((void**)&Oh, g_Oh);     cudaGetSymbolAddress((void**)&Ol, g_Ol);
    cudaGetSymbolAddress((void**)&wquh, g_wquh); cudaGetSymbolAddress((void**)&wqul, g_wqul);
    cudaGetSymbolAddress((void**)&wouth, g_wouth); cudaGetSymbolAddress((void**)&woutl, g_woutl);

    static cudaStream_t s_kv = nullptr;
    static cudaEvent_t ev_fork = nullptr, ev_join = nullptr;
    if (!s_kv) {
        cudaStreamCreateWithFlags(&s_kv, cudaStreamNonBlocking);
        cudaEventCreateWithFlags(&ev_fork, cudaEventDisableTiming);
        cudaEventCreateWithFlags(&ev_join, cudaEventDisableTiming);
        cudaFuncSetAttribute(gemm_mma_sk, cudaFuncAttributeMaxDynamicSharedMemorySize, 3 * STAGE_B);
        cudaFuncSetAttribute(oup_mma, cudaFuncAttributeMaxDynamicSharedMemorySize, 3 * STAGE_B);
        cudaFuncSetAttribute(gemm_f16_sk, cudaFuncAttributeMaxDynamicSharedMemorySize, 3 * OF_STAGE);
        cudaFuncSetAttribute(qabs_f16, cudaFuncAttributeMaxDynamicSharedMemorySize, 2 * OF_STAGE);
        cudaFuncSetAttribute(scores_f16, cudaFuncAttributeMaxDynamicSharedMemorySize, 2 * SF_STAGE);
        cudaFuncSetAttribute(ogemm_f16, cudaFuncAttributeMaxDynamicSharedMemorySize, 3 * OF_STAGE);
    }
    const int DSM = 3 * STAGE_B;

    // ---- root conversions ----
    conv_all<<<C4_WKVU / 256, 256>>>((const float4*)x, (const float4*)w_qd, (const float4*)w_qu,
                                     (const float4*)w_kvd, (const float4*)w_out, (const float4*)w_kvu);
    build_wnrt<<<dim3(KVR / 32, DNR / 32, NH), dim3(32, 8)>>>(w_kvu);

    // ---- fork: kv-path on s_kv, q-path on default ----
    cudaEventRecord(ev_fork, 0);
    cudaStreamWaitEvent(s_kv, ev_fork, 0);

    // kv path (fp16 single-term kvd)
    cudaMemsetAsync(p_kv, 0, (size_t)MBL * CATD * 4, s_kv);
    gemm_f16_sk<<<dim3(KVD_PAD / 128, MBL / 128, 8), 256, 3 * OF_STAGE, s_kv>>>(
        xf, wkvdf, p_kv, CATD, DIM, DIM / 8, CATD);
    rope_k<<<BATCH * SEQ_L * 32 / 256, 256, 0, s_kv>>>(fc, fs);
    build_kvcat4<<<(int)(((size_t)BATCH * MAXT * CATD / 4) / 256), 256, 0, s_kv>>>(kvc, krc);
    build_kvt<<<dim3(MAXT / 32, KVR / 32, BATCH), dim3(32, 8), 0, s_kv>>>(kvc);
    cudaEventRecord(ev_join, s_kv);

    // q path (fp16 qd; bf16 qu; fp16 qabs)
    cudaMemsetAsync(p_qd, 0, (size_t)MBL * QR * 4);
    cudaMemsetAsync(p_q, 0, (size_t)MBL * NH * QKD * 4);
    gemm_f16_sk<<<dim3(QR / 128, MBL / 128, 8), 256, 3 * OF_STAGE>>>(
        xf, wqdf, p_qd, QR, DIM, DIM / 8, QR);
    rms_kernel<<<MBL, 256>>>(rms_w);
    gemm_mma_sk<<<dim3(NH * QKD / 128, MBL / 128, 2), 256, DSM>>>(qnh, qnl, wquh, wqul,
        p_q, NH * QKD, QR, QR / 2, NH * QKD);
    conv_f16<<<(MBL * NH * QKD / 4 + 255) / 256, 256>>>((const float4*)p_q, qf, MBL * NH * QKD / 4);
    rope_q<<<BATCH * SEQ_L * NH * 32 / 256, 256>>>(fc, fs);
    qabs_f16<<<dim3(KVR / 128, MBL / 128, NH), 256, 2 * OF_STAGE>>>();

    // ---- join q/kv ----
    cudaStreamWaitEvent(0, ev_join, 0);

    // ---- attention (fp16 single-term) ----
    scores_f16<<<dim3(MAXT / 256, ROWSPB / 128, BATCH), 256, 2 * SF_STAGE>>>(
        qc, (size_t)ROWSPB * CATD, kc, (size_t)MAXT * CATD,
        S16, MAXT, (size_t)ROWSPB * MAXT, CATD, mask, SCALE_F);
    softmax_split<<<BATCH * ROWSPB, 256>>>();
    ogemm_f16<<<dim3(KVR / 128, ROWSPB / 128, BATCH), 256, 3 * OF_STAGE>>>(
        pp, (size_t)ROWSPB * MAXT, kt, (size_t)KVR * MAXT,
        Oh, Ol, KVR, (size_t)ROWSPB * KVR, MAXT);

    // ---- output path (bf16 3-term for accuracy) ----
    oup_mma<<<dim3(1, MBL / 128, NH), 256, DSM>>>();
    cudaMemsetAsync(out, 0, (size_t)MBL * DIM * 4);
    gemm_mma_sk<<<dim3(DIM / 128, MBL / 128, 8), 256, DSM>>>(o2h, o2l, wouth, woutl,
        out, DIM, NH * DV, NH * DV / 8, DIM);
}

// round 12
// speedup vs baseline: 1.8161x; 1.1186x over previous
#include <cuda_runtime.h>
#include <cuda_fp16.h>
#include <math.h>
#include <stdint.h>

// ---------------- problem constants -----------------------------------------
#define BATCH   8
#define SEQ_L   32
#define DIM     2048
#define KVR     512
#define QR      768
#define NH      16
#define DNR     128
#define DR      64
#define DV      128
#define MAXT    4096
#define START_P 4064
#define QKD     192
#define CATD    576
#define MBL     256
#define ROWSPB  512
#define SCALE_F 0.07216878364870323f
#define KVD_PAD 640

// ---------------- fp32 scratch ----------------------------------------------
__device__ __align__(16) float g_qd  [MBL * QR];
__device__ __align__(16) float g_q   [MBL * NH * QKD];
__device__ __align__(16) float g_kv  [MBL * CATD];
// ---------------- fp16 operands ----------------------------------------------
__device__ __align__(16) __half g_S16[(size_t)BATCH * ROWSPB * MAXT];
__device__ __align__(16) __half g_qc [BATCH * ROWSPB * CATD];
__device__ __align__(16) __half g_kc [(size_t)BATCH * MAXT * CATD];
__device__ __align__(16) __half g_kt [(size_t)BATCH * KVR * MAXT];
__device__ __align__(16) __half g_p  [(size_t)BATCH * ROWSPB * MAXT];
__device__ __align__(16) __half g_Of [BATCH * ROWSPB * KVR];
__device__ __align__(16) __half g_o2f[MBL * NH * DV];
__device__ __align__(16) __half g_xf [MBL * DIM];
__device__ __align__(16) __half g_qnf[MBL * QR];
__device__ __align__(16) __half g_qf [MBL * NH * QKD];
__device__ __align__(16) __half g_wqdf [QR * DIM];
__device__ __align__(16) __half g_wquf [NH * QKD * QR];
__device__ __align__(16) __half g_wkvdf[KVD_PAD * DIM];
__device__ __align__(16) __half g_woutf[DIM * NH * DV];
__device__ __align__(16) __half g_wvf  [NH * 256 * KVR];
__device__ __align__(16) __half g_wnrtf[NH * KVR * DNR];

// ================= helpers ===================================================
__device__ __forceinline__ uint32_t smem_u32(const void* p) {
    uint32_t a;
    asm("{ .reg .u64 t; cvta.to.shared.u64 t, %1; cvt.u32.u64 %0, t; }" : "=r"(a) : "l"(p));
    return a;
}
__device__ __forceinline__ uint32_t sw128(uint32_t o) { return o ^ ((o >> 3) & 0x70); }
__device__ __forceinline__ void cpa16(uint32_t saddr, const void* g) {
    asm volatile("cp.async.cg.shared.global [%0], [%1], 16;" :: "r"(saddr), "l"(g));
}
__device__ __forceinline__ void cpa_commit() { asm volatile("cp.async.commit_group;" ::: "memory"); }
__device__ __forceinline__ void cpa_wait2()  { asm volatile("cp.async.wait_group 2;" ::: "memory"); }
__device__ __forceinline__ void cpa_wait1()  { asm volatile("cp.async.wait_group 1;" ::: "memory"); }
__device__ __forceinline__ void cpa_wait0()  { asm volatile("cp.async.wait_group 0;" ::: "memory"); }
__device__ __forceinline__ void ldm_x4(uint32_t* r, uint32_t addr) {
    asm volatile("ldmatrix.sync.aligned.m8n8.x4.shared.b16 {%0,%1,%2,%3}, [%4];"
                 : "=r"(r[0]), "=r"(r[1]), "=r"(r[2]), "=r"(r[3]) : "r"(addr));
}
__device__ __forceinline__ void mma_f16(float* c, const uint32_t* a, const uint32_t* b) {
    asm volatile("mma.sync.aligned.m16n8k16.row.col.f32.f16.f16.f32 "
                 "{%0,%1,%2,%3}, {%4,%5,%6,%7}, {%8,%9}, {%0,%1,%2,%3};"
                 : "+f"(c[0]), "+f"(c[1]), "+f"(c[2]), "+f"(c[3])
                 : "r"(a[0]), "r"(a[1]), "r"(a[2]), "r"(a[3]), "r"(b[0]), "r"(b[1]));
}
__device__ __forceinline__ void half4_write(float4 v, __half* dst, size_t i4) {
    __half2 a = __floats2half2_rn(v.x, v.y);
    __half2 b = __floats2half2_rn(v.z, v.w);
    *(uint2*)&dst[i4 * 4] = make_uint2(*(uint32_t*)&a, *(uint32_t*)&b);
}

#define OF_STAGE 32768   // fp16 128x128: A 16KB @0, B 16KB @16384
#define SF_STAGE 49152   // fp16 128x256: A 16KB @0, B 32KB @16384

// ======== fp16 128x128 single-term mainloop (one row / thread loader) ========
#define F16_PREFETCH(STAGE, CH)                                                      \
    {                                                                                \
        const uint32_t sb = smem32 + (uint32_t)(STAGE) * OF_STAGE;                   \
        _Pragma("unroll") for (int i = 0; i < 8; i++)                                \
            cpa16(sb + soff[i], src + (CH) * 64 + i * 8);                            \
        cpa_commit();                                                                \
    }

#define F16_MAINLOOP(NCH)                                                            \
    {                                                                                \
        const int pre = ((NCH) < 2) ? (NCH) : 2;                                     \
        for (int s = 0; s < pre; s++) F16_PREFETCH(s, s)                             \
    }                                                                                \
    for (int c = 0; c < (NCH); c++) {                                                \
        if (c + 2 < (NCH)) {                                                         \
            F16_PREFETCH((c + 2) % 3, c + 2)                                         \
            cpa_wait2();                                                             \
        } else if (c + 1 < (NCH)) {                                                  \
            cpa_wait1();                                                             \
        } else {                                                                     \
            cpa_wait0();                                                             \
        }                                                                            \
        __syncthreads();                                                             \
        const uint32_t st = smem32 + (uint32_t)(c % 3) * OF_STAGE;                   \
        const uint32_t A32 = st, B32 = st + 16384;                                   \
        _Pragma("unroll") for (int ks = 0; ks < 4; ks++) {                           \
            const uint32_t kofs = ks * 32u + qsel * 16u;                             \
            uint32_t a[4][4];                                                        \
            _Pragma("unroll") for (int mf = 0; mf < 4; mf++) {                       \
                int row = wm + mf * 16 + qrow;                                       \
                ldm_x4(a[mf], A32 + sw128((uint32_t)row * 128u + kofs));             \
            }                                                                        \
            uint32_t b[4][2];                                                        \
            _Pragma("unroll") for (int nh = 0; nh < 2; nh++) {                       \
                int row = wn + nh * 16 + qrow;                                       \
                uint32_t t[4];                                                       \
                ldm_x4(t, B32 + sw128((uint32_t)row * 128u + kofs));                 \
                b[nh * 2 + 0][0] = t[0]; b[nh * 2 + 0][1] = t[2];                    \
                b[nh * 2 + 1][0] = t[1]; b[nh * 2 + 1][1] = t[3];                    \
            }                                                                        \
            _Pragma("unroll") for (int mf = 0; mf < 4; mf++)                         \
                _Pragma("unroll") for (int nf = 0; nf < 4; nf++)                     \
                    mma_f16(acc[mf][nf], a[mf], b[nf]);                              \
        }                                                                            \
        __syncthreads();                                                             \
    }

#define F16_DECL                                                                     \
    const int tid = threadIdx.x;                                                     \
    const int warp = tid >> 5, lane = tid & 31;                                      \
    const int wm = (warp >> 2) * 64, wn = (warp & 3) * 32;                           \
    const uint32_t smem32 = smem_u32(smem);                                          \
    const int qrow = lane & 15, qsel = lane >> 4;                                    \
    const bool isB = tid >= 128;                                                     \
    const int lrow = tid & 127;                                                      \
    uint32_t soff[8];                                                                \
    _Pragma("unroll") for (int i = 0; i < 8; i++)                                    \
        soff[i] = (isB ? 16384u : 0u) + sw128((uint32_t)lrow * 128u + i * 16u);      \
    float acc[4][4][4];                                                              \
    _Pragma("unroll") for (int i = 0; i < 4; i++)                                    \
        _Pragma("unroll") for (int j = 0; j < 4; j++)                                \
            _Pragma("unroll") for (int r = 0; r < 4; r++) acc[i][j][r] = 0.f;

// ====== fp16 split-K GEMM (qd, kvd, qu, out-proj): fp32 atomicAdd ============
__global__ void __launch_bounds__(256)
gemm_f16_sk(const __half* __restrict__ A, const __half* __restrict__ B,
            float* __restrict__ C, int ldc, int K, int kpart, int N)
{
    extern __shared__ char smem[];
    const int m0 = blockIdx.y * 128, n0 = blockIdx.x * 128;
    const int kb = blockIdx.z * kpart;
    F16_DECL
    const __half* src = isB ? (B + (size_t)(n0 + lrow) * K + kb)
                            : (A + (size_t)(m0 + lrow) * K + kb);
    const int nch = kpart >> 6;
    F16_MAINLOOP(nch)
    const int r0 = lane >> 2, c0 = (lane & 3) * 2;
#pragma unroll
    for (int mf = 0; mf < 4; mf++) {
        const int mA = m0 + wm + mf * 16 + r0;
#pragma unroll
        for (int nf = 0; nf < 4; nf++) {
            const int n = n0 + wn + nf * 8 + c0;
            if (n < N) {
                atomicAdd(&C[(size_t)mA * ldc + n],           acc[mf][nf][0]);
                atomicAdd(&C[(size_t)mA * ldc + n + 1],       acc[mf][nf][1]);
                atomicAdd(&C[(size_t)(mA + 8) * ldc + n],     acc[mf][nf][2]);
                atomicAdd(&C[(size_t)(mA + 8) * ldc + n + 1], acc[mf][nf][3]);
            }
        }
    }
}

// ====== qabs fp16: per-head q_nrope @ w_nr^T -> fp16 qcat ====================
__global__ void __launch_bounds__(256)
qabs_f16()
{
    extern __shared__ char smem[];
    const int h = blockIdx.z;
    const int m0 = blockIdx.y * 128, n0 = blockIdx.x * 128;
    F16_DECL
    const __half* src = isB ? (g_wnrtf + (size_t)h * KVR * DNR + (size_t)(n0 + lrow) * DNR)
                            : (g_qf + (size_t)(m0 + lrow) * (NH * QKD) + h * QKD);
    F16_MAINLOOP(2)
    const int r0 = lane >> 2, c0 = (lane & 3) * 2;
#pragma unroll
    for (int mf = 0; mf < 4; mf++) {
        const int mA = m0 + wm + mf * 16 + r0;
        const int rowA = ((mA >> 5) * ROWSPB) + (mA & 31) * NH + h;
        const int rowB = (((mA + 8) >> 5) * ROWSPB) + ((mA + 8) & 31) * NH + h;
#pragma unroll
        for (int nf = 0; nf < 4; nf++) {
            const int n = n0 + wn + nf * 8 + c0;
            *(__half2*)&g_qc[(size_t)rowA * CATD + n] = __floats2half2_rn(acc[mf][nf][0], acc[mf][nf][1]);
            *(__half2*)&g_qc[(size_t)rowB * CATD + n] = __floats2half2_rn(acc[mf][nf][2], acc[mf][nf][3]);
        }
    }
}

// ====== ogemm fp16: O = P*KV^T -> fp16 O =====================================
__global__ void __launch_bounds__(256)
ogemm_f16(const __half* __restrict__ P, size_t sPz,
          const __half* __restrict__ Kt, size_t sKz,
          __half* __restrict__ C, int ldc, size_t sCz, int K)
{
    extern __shared__ char smem[];
    const int z = blockIdx.z;
    const int m0 = blockIdx.y * 128, n0 = blockIdx.x * 128;
    P += (size_t)z * sPz;  Kt += (size_t)z * sKz;  C += (size_t)z * sCz;
    F16_DECL
    const __half* src = isB ? (Kt + (size_t)(n0 + lrow) * K)
                            : (P + (size_t)(m0 + lrow) * K);
    const int nch = K >> 6;
    F16_MAINLOOP(nch)
    const int r0 = lane >> 2, c0 = (lane & 3) * 2;
#pragma unroll
    for (int mf = 0; mf < 4; mf++) {
        const int mA = m0 + wm + mf * 16 + r0;
#pragma unroll
        for (int nf = 0; nf < 4; nf++) {
            const int n = n0 + wn + nf * 8 + c0;
            *(__half2*)&C[(size_t)mA * ldc + n]       = __floats2half2_rn(acc[mf][nf][0], acc[mf][nf][1]);
            *(__half2*)&C[(size_t)(mA + 8) * ldc + n] = __floats2half2_rn(acc[mf][nf][2], acc[mf][nf][3]);
        }
    }
}

// ====== oup fp16: per-head O @ w_v^T -> fp16 o2 ==============================
__global__ void __launch_bounds__(256)
oup_f16()
{
    extern __shared__ char smem[];
    const int h = blockIdx.z;
    const int m0 = blockIdx.y * 128, n0 = 0;
    F16_DECL
    const int mrow = m0 + lrow;
    const int arow = (mrow >> 5) * ROWSPB + (mrow & 31) * NH + h;
    const __half* src = isB ? (g_wvf + (size_t)(h * 256 + DNR + n0 + lrow) * KVR)
                            : (g_Of + (size_t)arow * KVR);
    F16_MAINLOOP(8)
    const int r0 = lane >> 2, c0 = (lane & 3) * 2;
#pragma unroll
    for (int mf = 0; mf < 4; mf++) {
        const int mA = m0 + wm + mf * 16 + r0;
#pragma unroll
        for (int nf = 0; nf < 4; nf++) {
            const int n = n0 + wn + nf * 8 + c0;
            const size_t i0 = (size_t)mA * (NH * DV) + h * DV + n;
            const size_t i1 = (size_t)(mA + 8) * (NH * DV) + h * DV + n;
            *(__half2*)&g_o2f[i0] = __floats2half2_rn(acc[mf][nf][0], acc[mf][nf][1]);
            *(__half2*)&g_o2f[i1] = __floats2half2_rn(acc[mf][nf][2], acc[mf][nf][3]);
        }
    }
}

// ====== fp16 scores 128x256 tile, 2-stage, fp16 S output =====================
__global__ void __launch_bounds__(256)
scores_f16(const __half* __restrict__ Q, size_t sQz,
           const __half* __restrict__ Kc, size_t sKz,
           __half* __restrict__ C, int ldc, size_t sCz,
           int K, const float* __restrict__ mask, float scale)
{
    extern __shared__ char smem[];
    const int z = blockIdx.z;
    const int m0 = blockIdx.y * 128, n0 = blockIdx.x * 256;
    Q += (size_t)z * sQz;  Kc += (size_t)z * sKz;  C += (size_t)z * sCz;

    const int tid = threadIdx.x;
    const int warp = tid >> 5, lane = tid & 31;
    const int wm = (warp >> 2) * 64, wn = (warp & 3) * 64;
    const uint32_t smem32 = smem_u32(smem);
    const int qrow = lane & 15, qsel = lane >> 4;

    const __half* gsrc[3];
    uint32_t swb[3];
#pragma unroll
    for (int j = 0; j < 3; j++) {
        const int h = tid + j * 256;
        const int half = h & 1;
        int r;
        uint32_t tbase;
        const __half* base;
        if (h < 256) { r = h >> 1; tbase = 0u; base = Q + (size_t)(m0 + r) * K; }
        else { r = (h - 256) >> 1; tbase = 16384u; base = Kc + (size_t)(n0 + r) * K; }
        swb[j] = tbase + sw128((uint32_t)r * 128u + half * 64u);
        gsrc[j] = base + half * 32;
    }

    float acc[4][8][4];
#pragma unroll
    for (int i = 0; i < 4; i++)
#pragma unroll
        for (int j = 0; j < 8; j++)
#pragma unroll
            for (int r = 0; r < 4; r++) acc[i][j][r] = 0.f;

    const int nch = K >> 6;
    {
#pragma unroll
        for (int j = 0; j < 3; j++)
#pragma unroll
            for (int i = 0; i < 4; i++)
                cpa16(smem32 + (swb[j] ^ (i * 16u)), gsrc[j] + i * 8);
        cpa_commit();
    }
    for (int c = 0; c < nch; c++) {
        if (c + 1 < nch) {
            const int ke = (c + 1) * 64;
            const uint32_t sb = smem32 + ((c + 1) & 1) * SF_STAGE;
#pragma unroll
            for (int j = 0; j < 3; j++)
#pragma unroll
                for (int i = 0; i < 4; i++)
                    cpa16(sb + (swb[j] ^ (i * 16u)), gsrc[j] + ke + i * 8);
            cpa_commit();
            cpa_wait1();
        } else {
            cpa_wait0();
        }
        __syncthreads();

        const uint32_t st = smem32 + (c & 1) * SF_STAGE;
        const uint32_t A32 = st, B32 = st + 16384;
#pragma unroll
        for (int ks = 0; ks < 4; ks++) {
            const uint32_t kofs = ks * 32u + qsel * 16u;
            uint32_t a[4][4];
#pragma unroll
            for (int mf = 0; mf < 4; mf++) {
                int row = wm + mf * 16 + qrow;
                ldm_x4(a[mf], A32 + sw128((uint32_t)row * 128u + kofs));
            }
            uint32_t b[8][2];
#pragma unroll
            for (int nh = 0; nh < 4; nh++) {
                int row = wn + nh * 16 + qrow;
                uint32_t t[4];
                ldm_x4(t, B32 + sw128((uint32_t)row * 128u + kofs));
                b[nh * 2 + 0][0] = t[0]; b[nh * 2 + 0][1] = t[2];
                b[nh * 2 + 1][0] = t[1]; b[nh * 2 + 1][1] = t[3];
            }
#pragma unroll
            for (int mf = 0; mf < 4; mf++)
#pragma unroll
                for (int nf = 0; nf < 8; nf++)
                    mma_f16(acc[mf][nf], a[mf], b[nf]);
        }
        __syncthreads();
    }

    const int r0 = lane >> 2, c0 = (lane & 3) * 2;
#pragma unroll
    for (int mf = 0; mf < 4; mf++) {
        const int mA = m0 + wm + mf * 16 + r0;
        const float* mrow = mask + (size_t)(mA >> 4) * MAXT;
#pragma unroll
        for (int nf = 0; nf < 8; nf++) {
            const int n = n0 + wn + nf * 8 + c0;
            float v0 = acc[mf][nf][0] * scale + mrow[n];
            float v1 = acc[mf][nf][1] * scale + mrow[n + 1];
            float v2 = acc[mf][nf][2] * scale + mrow[n];
            float v3 = acc[mf][nf][3] * scale + mrow[n + 1];
            *(__half2*)&C[(size_t)mA * ldc + n]       = __floats2half2_rn(v0, v1);
            *(__half2*)&C[(size_t)(mA + 8) * ldc + n] = __floats2half2_rn(v2, v3);
        }
    }
}

// ================= merged weight/x conversion (all fp16) =====================
#define C4_X    131072
#define C4_QD   (C4_X + 393216)
#define C4_QU   (C4_QD + 589824)
#define C4_KVD  (C4_QU + 327680)
#define C4_OUT  (C4_KVD + 1048576)
#define C4_WKVU (C4_OUT + 524288)
#define KVD_SRC4 294912
__global__ void conv_all(const float4* __restrict__ x, const float4* __restrict__ wqd,
                         const float4* __restrict__ wqu, const float4* __restrict__ wkvd,
                         const float4* __restrict__ wout, const float4* __restrict__ wkvu) {
    const int i = blockIdx.x * 256 + threadIdx.x;
    if (i < C4_X) {
        half4_write(x[i], g_xf, i);
    } else if (i < C4_QD) {
        const int j = i - C4_X;
        half4_write(wqd[j], g_wqdf, j);
    } else if (i < C4_QU) {
        const int j = i - C4_QD;
        half4_write(wqu[j], g_wquf, j);
    } else if (i < C4_KVD) {
        const int j = i - C4_QU;
        float4 v = (j < KVD_SRC4) ? wkvd[j] : make_float4(0.f, 0.f, 0.f, 0.f);
        half4_write(v, g_wkvdf, j);
    } else if (i < C4_OUT) {
        const int j = i - C4_KVD;
        half4_write(wout[j], g_woutf, j);
    } else if (i < C4_WKVU) {
        const int j = i - C4_OUT;
        half4_write(wkvu[j], g_wvf, j);
    }
}

// transpose nr part of w_kvu -> fp16
__global__ void build_wnrt(const float* __restrict__ wkvu) {
    __shared__ float tile[32][33];
    const int h = blockIdx.z;
    const int n0 = blockIdx.x * 32, d0 = blockIdx.y * 32;
    const int tx = threadIdx.x, ty = threadIdx.y;
#pragma unroll
    for (int i = 0; i < 4; i++) {
        const int d = d0 + ty + i * 8;
        tile[ty + i * 8][tx] = wkvu[(size_t)(h * 256 + d) * KVR + n0 + tx];
    }
    __syncthreads();
#pragma unroll
    for (int i = 0; i < 4; i++) {
        const int n = n0 + ty + i * 8;
        const float v = tile[tx][ty + i * 8];
        g_wnrtf[(size_t)h * KVR * DNR + (size_t)n * DNR + d0 + tx] = __float2half_rn(v);
    }
}

// ================= small conversions ========================================
__global__ void conv_f16(const float4* __restrict__ src, __half* dst, int n4) {
    const int i = blockIdx.x * 256 + threadIdx.x;
    if (i < n4) half4_write(src[i], dst, i);
}
__global__ void build_kvcat4(const float* __restrict__ kvc, const float* __restrict__ krc) {
    const size_t i4 = (size_t)blockIdx.x * 256 + threadIdx.x;
    const size_t idx = i4 * 4;
    const int c = (int)(idx % CATD);
    const size_t bt = idx / CATD;
    const int t = (int)(bt % MAXT);
    const int b = (int)(bt / MAXT);
    float4 v;
    if (t >= START_P)
        v = *(const float4*)&g_kv[(size_t)((b << 5) + (t - START_P)) * CATD + c];
    else if (c < KVR)
        v = *(const float4*)&kvc[((size_t)b * MAXT + t) * KVR + c];
    else
        v = *(const float4*)&krc[((size_t)b * MAXT + t) * DR + (c - KVR)];
    half4_write(v, g_kc, i4);
}
__global__ void build_kvt(const float* __restrict__ kvc) {
    __shared__ float tile[32][33];
    const int b = blockIdx.z;
    const int t0 = blockIdx.x * 32, n0 = blockIdx.y * 32;
    const int tx = threadIdx.x, ty = threadIdx.y;
#pragma unroll
    for (int i = 0; i < 4; i++) {
        const int t = t0 + ty + i * 8;
        float v;
        if (t >= START_P)
            v = g_kv[(size_t)((b << 5) + (t - START_P)) * CATD + n0 + tx];
        else
            v = kvc[((size_t)b * MAXT + t) * KVR + n0 + tx];
        tile[ty + i * 8][tx] = v;
    }
    __syncthreads();
#pragma unroll
    for (int i = 0; i < 4; i++) {
        const int n = n0 + ty + i * 8;
        const float x = tile[tx][ty + i * 8];
        g_kt[((size_t)(b * KVR + n)) * MAXT + t0 + tx] = __float2half_rn(x);
    }
}

// ================= RMSNorm -> fp16 ===========================================
__global__ void rms_kernel(const float* __restrict__ w) {
    const int row = blockIdx.x;
    const float* xr = g_qd + row * QR;
    __shared__ float red[256];
    const int tid = threadIdx.x;
    float v[3], s = 0.f;
#pragma unroll
    for (int i = 0; i < 3; i++) { v[i] = xr[tid + i * 256]; s += v[i] * v[i]; }
    red[tid] = s; __syncthreads();
    for (int o = 128; o > 0; o >>= 1) {
        if (tid < o) red[tid] += red[tid + o];
        __syncthreads();
    }
    const float r = rsqrtf(red[0] / (float)QR + 1.1920929e-07f);
    __syncthreads();
#pragma unroll
    for (int i = 0; i < 3; i++) {
        const float y = v[i] * r * w[tid + i * 256];
        g_qnf[(size_t)row * QR + tid + i * 256] = __float2half_rn(y);
    }
}

// ================= rope ======================================================
__global__ void rope_q(const float* __restrict__ fc, const float* __restrict__ fs) {
    const int idx = blockIdx.x * 256 + threadIdx.x;
    const int j = idx & 31, h = (idx >> 5) & 15, l = (idx >> 9) & 31, b = idx >> 14;
    const size_t si = (size_t)(b * SEQ_L + l) * (NH * QKD) + h * QKD + DNR + 2 * j;
    const float xr = __half2float(g_qf[si]);
    const float xi = __half2float(g_qf[si + 1]);
    const float c = fc[l * 32 + j], s = fs[l * 32 + j];
    const size_t o = (size_t)(b * ROWSPB + l * NH + h) * CATD + KVR + 2 * j;
    *(__half2*)&g_qc[o] = __floats2half2_rn(xr * c - xi * s, xr * s + xi * c);
}
__global__ void rope_k(const float* __restrict__ fc, const float* __restrict__ fs) {
    const int k = blockIdx.x * 256 + threadIdx.x;
    const int j = k & 31, l = (k >> 5) & 31, b = k >> 10;
    float* p = &g_kv[(size_t)(b * SEQ_L + l) * CATD + KVR + 2 * j];
    const float xr = p[0], xi = p[1];
    const float c = fc[l * 32 + j], s = fs[l * 32 + j];
    p[0] = xr * c - xi * s;
    p[1] = xr * s + xi * c;
}

// ================= softmax (fp16 in) -> fp16 P ===============================
__global__ void softmax_split() {
    const int row = blockIdx.x;
    const __half* srow = g_S16 + (size_t)row * MAXT;
    __shared__ float red[256];
    const int tid = threadIdx.x;
    float4 v[4];
    float mx = -INFINITY;
#pragma unroll
    for (int g = 0; g < 4; g++) {
        uint2 r = *(const uint2*)&srow[tid * 4 + g * 1024];
        float2 fa = __half22float2(*(__half2*)&r.x);
        float2 fb = __half22float2(*(__half2*)&r.y);
        v[g] = make_float4(fa.x, fa.y, fb.x, fb.y);
        mx = fmaxf(mx, fmaxf(fmaxf(v[g].x, v[g].y), fmaxf(v[g].z, v[g].w)));
    }
    red[tid] = mx; __syncthreads();
    for (int o = 128; o > 0; o >>= 1) {
        if (tid < o) red[tid] = fmaxf(red[tid], red[tid + o]);
        __syncthreads();
    }
    mx = red[0]; __syncthreads();
    float sum = 0.f;
#pragma unroll
    for (int g = 0; g < 4; g++) {
        v[g].x = __expf(v[g].x - mx); v[g].y = __expf(v[g].y - mx);
        v[g].z = __expf(v[g].z - mx); v[g].w = __expf(v[g].w - mx);
        sum += v[g].x + v[g].y + v[g].z + v[g].w;
    }
    red[tid] = sum; __syncthreads();
    for (int o = 128; o > 0; o >>= 1) {
        if (tid < o) red[tid] += red[tid + o];
        __syncthreads();
    }
    const float inv = 1.f / red[0];
#pragma unroll
    for (int g = 0; g < 4; g++) {
        float4 p = make_float4(v[g].x * inv, v[g].y * inv, v[g].z * inv, v[g].w * inv);
        half4_write(p, g_p, ((size_t)row * MAXT + tid * 4 + g * 1024) >> 2);
    }
}

// ============================== launcher =====================================
extern "C" void kernel_launch(void* const* d_in, const int* in_sizes, int n_in,
                              void* d_out, int out_size) {
    const float* x      = (const float*)d_in[0];
    const float* fc     = (const float*)d_in[2];
    const float* fs     = (const float*)d_in[3];
    const float* mask   = (const float*)d_in[4];
    const float* kvc    = (const float*)d_in[5];
    const float* krc    = (const float*)d_in[6];
    const float* w_kvd  = (const float*)d_in[7];
    const float* w_qd   = (const float*)d_in[8];
    const float* rms_w  = (const float*)d_in[9];
    const float* w_qu   = (const float*)d_in[10];
    const float* w_kvu  = (const float*)d_in[11];
    const float* w_out  = (const float*)d_in[12];
    float* out = (float*)d_out;

    float *p_qd, *p_q, *p_kv;
    cudaGetSymbolAddress((void**)&p_qd, g_qd);
    cudaGetSymbolAddress((void**)&p_q,  g_q);
    cudaGetSymbolAddress((void**)&p_kv, g_kv);

    __half *qc, *kc, *kt, *pp, *S16, *xf, *qnf, *qf, *Of, *o2f;
    __half *wqdf, *wquf, *wkvdf, *woutf;
    cudaGetSymbolAddress((void**)&qc, g_qc);
    cudaGetSymbolAddress((void**)&kc, g_kc);
    cudaGetSymbolAddress((void**)&kt, g_kt);
    cudaGetSymbolAddress((void**)&pp, g_p);
    cudaGetSymbolAddress((void**)&S16, g_S16);
    cudaGetSymbolAddress((void**)&xf, g_xf);
    cudaGetSymbolAddress((void**)&qnf, g_qnf);
    cudaGetSymbolAddress((void**)&qf, g_qf);
    cudaGetSymbolAddress((void**)&Of, g_Of);
    cudaGetSymbolAddress((void**)&o2f, g_o2f);
    cudaGetSymbolAddress((void**)&wqdf, g_wqdf);
    cudaGetSymbolAddress((void**)&wquf, g_wquf);
    cudaGetSymbolAddress((void**)&wkvdf, g_wkvdf);
    cudaGetSymbolAddress((void**)&woutf, g_woutf);

    static cudaStream_t s_kv = nullptr;
    static cudaEvent_t ev_fork = nullptr, ev_join = nullptr;
    if (!s_kv) {
        cudaStreamCreateWithFlags(&s_kv, cudaStreamNonBlocking);
        cudaEventCreateWithFlags(&ev_fork, cudaEventDisableTiming);
        cudaEventCreateWithFlags(&ev_join, cudaEventDisableTiming);
        cudaFuncSetAttribute(gemm_f16_sk, cudaFuncAttributeMaxDynamicSharedMemorySize, 3 * OF_STAGE);
        cudaFuncSetAttribute(qabs_f16, cudaFuncAttributeMaxDynamicSharedMemorySize, 2 * OF_STAGE);
        cudaFuncSetAttribute(oup_f16, cudaFuncAttributeMaxDynamicSharedMemorySize, 3 * OF_STAGE);
        cudaFuncSetAttribute(scores_f16, cudaFuncAttributeMaxDynamicSharedMemorySize, 2 * SF_STAGE);
        cudaFuncSetAttribute(ogemm_f16, cudaFuncAttributeMaxDynamicSharedMemorySize, 3 * OF_STAGE);
    }

    // ---- root conversions ----
    conv_all<<<C4_WKVU / 256, 256>>>((const float4*)x, (const float4*)w_qd, (const float4*)w_qu,
                                     (const float4*)w_kvd, (const float4*)w_out, (const float4*)w_kvu);
    build_wnrt<<<dim3(KVR / 32, DNR / 32, NH), dim3(32, 8)>>>(w_kvu);

    // ---- fork: kv-path on s_kv, q-path on default ----
    cudaEventRecord(ev_fork, 0);
    cudaStreamWaitEvent(s_kv, ev_fork, 0);

    // kv path
    cudaMemsetAsync(p_kv, 0, (size_t)MBL * CATD * 4, s_kv);
    gemm_f16_sk<<<dim3(KVD_PAD / 128, MBL / 128, 8), 256, 3 * OF_STAGE, s_kv>>>(
        xf, wkvdf, p_kv, CATD, DIM, DIM / 8, CATD);
    rope_k<<<BATCH * SEQ_L * 32 / 256, 256, 0, s_kv>>>(fc, fs);
    build_kvcat4<<<(int)(((size_t)BATCH * MAXT * CATD / 4) / 256), 256, 0, s_kv>>>(kvc, krc);
    build_kvt<<<dim3(MAXT / 32, KVR / 32, BATCH), dim3(32, 8), 0, s_kv>>>(kvc);
    cudaEventRecord(ev_join, s_kv);

    // q path (all fp16)
    cudaMemsetAsync(p_qd, 0, (size_t)MBL * QR * 4);
    cudaMemsetAsync(p_q, 0, (size_t)MBL * NH * QKD * 4);
    gemm_f16_sk<<<dim3(QR / 128, MBL / 128, 8), 256, 3 * OF_STAGE>>>(
        xf, wqdf, p_qd, QR, DIM, DIM / 8, QR);
    rms_kernel<<<MBL, 256>>>(rms_w);
    gemm_f16_sk<<<dim3(NH * QKD / 128, MBL / 128, 4), 256, 3 * OF_STAGE>>>(
        qnf, wquf, p_q, NH * QKD, QR, QR / 4, NH * QKD);
    conv_f16<<<(MBL * NH * QKD / 4 + 255) / 256, 256>>>((const float4*)p_q, qf, MBL * NH * QKD / 4);
    rope_q<<<BATCH * SEQ_L * NH * 32 / 256, 256>>>(fc, fs);
    qabs_f16<<<dim3(KVR / 128, MBL / 128, NH), 256, 2 * OF_STAGE>>>();

    // ---- join q/kv ----
    cudaStreamWaitEvent(0, ev_join, 0);

    // ---- attention ----
    scores_f16<<<dim3(MAXT / 256, ROWSPB / 128, BATCH), 256, 2 * SF_STAGE>>>(
        qc, (size_t)ROWSPB * CATD, kc, (size_t)MAXT * CATD,
        S16, MAXT, (size_t)ROWSPB * MAXT, CATD, mask, SCALE_F);
    softmax_split<<<BATCH * ROWSPB, 256>>>();
    ogemm_f16<<<dim3(KVR / 128, ROWSPB / 128, BATCH), 256, 3 * OF_STAGE>>>(
        pp, (size_t)ROWSPB * MAXT, kt, (size_t)KVR * MAXT,
        Of, KVR, (size_t)ROWSPB * KVR, MAXT);

    // ---- output path (fp16) ----
    oup_f16<<<dim3(1, MBL / 128, NH), 256, 3 * OF_STAGE>>>();
    cudaMemsetAsync(out, 0, (size_t)MBL * DIM * 4);
    gemm_f16_sk<<<dim3(DIM / 128, MBL / 128, 8), 256, 3 * OF_STAGE>>>(
        o2f, woutf, out, DIM, NH * DV, NH * DV / 8, DIM);
}

// round 13
// speedup vs baseline: 1.8555x; 1.0217x over previous
#include <cuda_runtime.h>
#include <cuda_fp16.h>
#include <math.h>
#include <stdint.h>

// ---------------- problem constants -----------------------------------------
#define BATCH   8
#define SEQ_L   32
#define DIM     2048
#define KVR     512
#define QR      768
#define NH      16
#define DNR     128
#define DR      64
#define DV      128
#define MAXT    4096
#define START_P 4064
#define QKD     192
#define CATD    576
#define MBL     256
#define ROWSPB  512
#define SCALE_F 0.07216878364870323f
#define KVD_PAD 640

// ---------------- fp32 scratch ----------------------------------------------
__device__ __align__(16) float g_qd  [MBL * QR];
__device__ __align__(16) float g_q   [MBL * NH * QKD];
__device__ __align__(16) float g_kv  [MBL * CATD];
// ---------------- fp16 operands ----------------------------------------------
__device__ __align__(16) __half g_S16[(size_t)BATCH * ROWSPB * MAXT];
__device__ __align__(16) __half g_qc [BATCH * ROWSPB * CATD];
__device__ __align__(16) __half g_kc [(size_t)BATCH * MAXT * CATD];
__device__ __align__(16) __half g_kt [(size_t)BATCH * KVR * MAXT];
__device__ __align__(16) __half g_p  [(size_t)BATCH * ROWSPB * MAXT];
__device__ __align__(16) __half g_Of [BATCH * ROWSPB * KVR];
__device__ __align__(16) __half g_o2f[MBL * NH * DV];
__device__ __align__(16) __half g_xf [MBL * DIM];
__device__ __align__(16) __half g_qnf[MBL * QR];
__device__ __align__(16) __half g_qf [MBL * NH * QKD];
__device__ __align__(16) __half g_wqdf [QR * DIM];
__device__ __align__(16) __half g_wquf [NH * QKD * QR];
__device__ __align__(16) __half g_wkvdf[KVD_PAD * DIM];
__device__ __align__(16) __half g_woutf[DIM * NH * DV];
__device__ __align__(16) __half g_wvf  [NH * 256 * KVR];
__device__ __align__(16) __half g_wnrtf[NH * KVR * DNR];

// ================= helpers ===================================================
__device__ __forceinline__ uint32_t smem_u32(const void* p) {
    uint32_t a;
    asm("{ .reg .u64 t; cvta.to.shared.u64 t, %1; cvt.u32.u64 %0, t; }" : "=r"(a) : "l"(p));
    return a;
}
__device__ __forceinline__ uint32_t sw128(uint32_t o) { return o ^ ((o >> 3) & 0x70); }
__device__ __forceinline__ void cpa16(uint32_t saddr, const void* g) {
    asm volatile("cp.async.cg.shared.global [%0], [%1], 16;" :: "r"(saddr), "l"(g));
}
__device__ __forceinline__ void cpa_commit() { asm volatile("cp.async.commit_group;" ::: "memory"); }
__device__ __forceinline__ void cpa_wait2()  { asm volatile("cp.async.wait_group 2;" ::: "memory"); }
__device__ __forceinline__ void cpa_wait1()  { asm volatile("cp.async.wait_group 1;" ::: "memory"); }
__device__ __forceinline__ void cpa_wait0()  { asm volatile("cp.async.wait_group 0;" ::: "memory"); }
__device__ __forceinline__ void ldm_x4(uint32_t* r, uint32_t addr) {
    asm volatile("ldmatrix.sync.aligned.m8n8.x4.shared.b16 {%0,%1,%2,%3}, [%4];"
                 : "=r"(r[0]), "=r"(r[1]), "=r"(r[2]), "=r"(r[3]) : "r"(addr));
}
__device__ __forceinline__ void mma_f16(float* c, const uint32_t* a, const uint32_t* b) {
    asm volatile("mma.sync.aligned.m16n8k16.row.col.f32.f16.f16.f32 "
                 "{%0,%1,%2,%3}, {%4,%5,%6,%7}, {%8,%9}, {%0,%1,%2,%3};"
                 : "+f"(c[0]), "+f"(c[1]), "+f"(c[2]), "+f"(c[3])
                 : "r"(a[0]), "r"(a[1]), "r"(a[2]), "r"(a[3]), "r"(b[0]), "r"(b[1]));
}
__device__ __forceinline__ void half4_write(float4 v, __half* dst, size_t i4) {
    __half2 a = __floats2half2_rn(v.x, v.y);
    __half2 b = __floats2half2_rn(v.z, v.w);
    *(uint2*)&dst[i4 * 4] = make_uint2(*(uint32_t*)&a, *(uint32_t*)&b);
}

#define OF_STAGE 32768   // fp16 128x128: A 16KB @0, B 16KB @16384
#define SF_STAGE 49152   // fp16 128x256: A 16KB @0, B 32KB @16384

// ======== fp16 128x128 single-term mainloop (one row / thread loader) ========
#define F16_PREFETCH(STAGE, CH)                                                      \
    {                                                                                \
        const uint32_t sb = smem32 + (uint32_t)(STAGE) * OF_STAGE;                   \
        _Pragma("unroll") for (int i = 0; i < 8; i++)                                \
            cpa16(sb + soff[i], src + (CH) * 64 + i * 8);                            \
        cpa_commit();                                                                \
    }

#define F16_MAINLOOP(NCH)                                                            \
    {                                                                                \
        const int pre = ((NCH) < 2) ? (NCH) : 2;                                     \
        for (int s = 0; s < pre; s++) F16_PREFETCH(s, s)                             \
    }                                                                                \
    for (int c = 0; c < (NCH); c++) {                                                \
        if (c + 2 < (NCH)) {                                                         \
            F16_PREFETCH((c + 2) % 3, c + 2)                                         \
            cpa_wait2();                                                             \
        } else if (c + 1 < (NCH)) {                                                  \
            cpa_wait1();                                                             \
        } else {                                                                     \
            cpa_wait0();                                                             \
        }                                                                            \
        __syncthreads();                                                             \
        const uint32_t st = smem32 + (uint32_t)(c % 3) * OF_STAGE;                   \
        const uint32_t A32 = st, B32 = st + 16384;                                   \
        _Pragma("unroll") for (int ks = 0; ks < 4; ks++) {                           \
            const uint32_t kofs = ks * 32u + qsel * 16u;                             \
            uint32_t a[4][4];                                                        \
            _Pragma("unroll") for (int mf = 0; mf < 4; mf++) {                       \
                int row = wm + mf * 16 + qrow;                                       \
                ldm_x4(a[mf], A32 + sw128((uint32_t)row * 128u + kofs));             \
            }                                                                        \
            uint32_t b[4][2];                                                        \
            _Pragma("unroll") for (int nh = 0; nh < 2; nh++) {                       \
                int row = wn + nh * 16 + qrow;                                       \
                uint32_t t[4];                                                       \
                ldm_x4(t, B32 + sw128((uint32_t)row * 128u + kofs));                 \
                b[nh * 2 + 0][0] = t[0]; b[nh * 2 + 0][1] = t[2];                    \
                b[nh * 2 + 1][0] = t[1]; b[nh * 2 + 1][1] = t[3];                    \
            }                                                                        \
            _Pragma("unroll") for (int mf = 0; mf < 4; mf++)                         \
                _Pragma("unroll") for (int nf = 0; nf < 4; nf++)                     \
                    mma_f16(acc[mf][nf], a[mf], b[nf]);                              \
        }                                                                            \
        __syncthreads();                                                             \
    }

#define F16_DECL                                                                     \
    const int tid = threadIdx.x;                                                     \
    const int warp = tid >> 5, lane = tid & 31;                                      \
    const int wm = (warp >> 2) * 64, wn = (warp & 3) * 32;                           \
    const uint32_t smem32 = smem_u32(smem);                                          \
    const int qrow = lane & 15, qsel = lane >> 4;                                    \
    const bool isB = tid >= 128;                                                     \
    const int lrow = tid & 127;                                                      \
    uint32_t soff[8];                                                                \
    _Pragma("unroll") for (int i = 0; i < 8; i++)                                    \
        soff[i] = (isB ? 16384u : 0u) + sw128((uint32_t)lrow * 128u + i * 16u);      \
    float acc[4][4][4];                                                              \
    _Pragma("unroll") for (int i = 0; i < 4; i++)                                    \
        _Pragma("unroll") for (int j = 0; j < 4; j++)                                \
            _Pragma("unroll") for (int r = 0; r < 4; r++) acc[i][j][r] = 0.f;

// ====== fp16 split-K GEMM (qd, kvd, qu, out-proj): fp32 atomicAdd ============
__global__ void __launch_bounds__(256)
gemm_f16_sk(const __half* __restrict__ A, const __half* __restrict__ B,
            float* __restrict__ C, int ldc, int K, int kpart, int N)
{
    extern __shared__ char smem[];
    const int m0 = blockIdx.y * 128, n0 = blockIdx.x * 128;
    const int kb = blockIdx.z * kpart;
    F16_DECL
    const __half* src = isB ? (B + (size_t)(n0 + lrow) * K + kb)
                            : (A + (size_t)(m0 + lrow) * K + kb);
    const int nch = kpart >> 6;
    F16_MAINLOOP(nch)
    const int r0 = lane >> 2, c0 = (lane & 3) * 2;
#pragma unroll
    for (int mf = 0; mf < 4; mf++) {
        const int mA = m0 + wm + mf * 16 + r0;
#pragma unroll
        for (int nf = 0; nf < 4; nf++) {
            const int n = n0 + wn + nf * 8 + c0;
            if (n < N) {
                atomicAdd(&C[(size_t)mA * ldc + n],           acc[mf][nf][0]);
                atomicAdd(&C[(size_t)mA * ldc + n + 1],       acc[mf][nf][1]);
                atomicAdd(&C[(size_t)(mA + 8) * ldc + n],     acc[mf][nf][2]);
                atomicAdd(&C[(size_t)(mA + 8) * ldc + n + 1], acc[mf][nf][3]);
            }
        }
    }
}

// ====== qabs fp16: per-head q_nrope @ w_nr^T -> fp16 qcat ====================
__global__ void __launch_bounds__(256)
qabs_f16()
{
    extern __shared__ char smem[];
    const int h = blockIdx.z;
    const int m0 = blockIdx.y * 128, n0 = blockIdx.x * 128;
    F16_DECL
    const __half* src = isB ? (g_wnrtf + (size_t)h * KVR * DNR + (size_t)(n0 + lrow) * DNR)
                            : (g_qf + (size_t)(m0 + lrow) * (NH * QKD) + h * QKD);
    F16_MAINLOOP(2)
    const int r0 = lane >> 2, c0 = (lane & 3) * 2;
#pragma unroll
    for (int mf = 0; mf < 4; mf++) {
        const int mA = m0 + wm + mf * 16 + r0;
        const int rowA = ((mA >> 5) * ROWSPB) + (mA & 31) * NH + h;
        const int rowB = (((mA + 8) >> 5) * ROWSPB) + ((mA + 8) & 31) * NH + h;
#pragma unroll
        for (int nf = 0; nf < 4; nf++) {
            const int n = n0 + wn + nf * 8 + c0;
            *(__half2*)&g_qc[(size_t)rowA * CATD + n] = __floats2half2_rn(acc[mf][nf][0], acc[mf][nf][1]);
            *(__half2*)&g_qc[(size_t)rowB * CATD + n] = __floats2half2_rn(acc[mf][nf][2], acc[mf][nf][3]);
        }
    }
}

// ====== ogemm fp16: O = P*KV^T -> fp16 O =====================================
__global__ void __launch_bounds__(256)
ogemm_f16(const __half* __restrict__ P, size_t sPz,
          const __half* __restrict__ Kt, size_t sKz,
          __half* __restrict__ C, int ldc, size_t sCz, int K)
{
    extern __shared__ char smem[];
    const int z = blockIdx.z;
    const int m0 = blockIdx.y * 128, n0 = blockIdx.x * 128;
    P += (size_t)z * sPz;  Kt += (size_t)z * sKz;  C += (size_t)z * sCz;
    F16_DECL
    const __half* src = isB ? (Kt + (size_t)(n0 + lrow) * K)
                            : (P + (size_t)(m0 + lrow) * K);
    const int nch = K >> 6;
    F16_MAINLOOP(nch)
    const int r0 = lane >> 2, c0 = (lane & 3) * 2;
#pragma unroll
    for (int mf = 0; mf < 4; mf++) {
        const int mA = m0 + wm + mf * 16 + r0;
#pragma unroll
        for (int nf = 0; nf < 4; nf++) {
            const int n = n0 + wn + nf * 8 + c0;
            *(__half2*)&C[(size_t)mA * ldc + n]       = __floats2half2_rn(acc[mf][nf][0], acc[mf][nf][1]);
            *(__half2*)&C[(size_t)(mA + 8) * ldc + n] = __floats2half2_rn(acc[mf][nf][2], acc[mf][nf][3]);
        }
    }
}

// ====== oup fp16: per-head O @ w_v^T -> fp16 o2 ==============================
__global__ void __launch_bounds__(256)
oup_f16()
{
    extern __shared__ char smem[];
    const int h = blockIdx.z;
    const int m0 = blockIdx.y * 128, n0 = 0;
    F16_DECL
    const int mrow = m0 + lrow;
    const int arow = (mrow >> 5) * ROWSPB + (mrow & 31) * NH + h;
    const __half* src = isB ? (g_wvf + (size_t)(h * 256 + DNR + n0 + lrow) * KVR)
                            : (g_Of + (size_t)arow * KVR);
    F16_MAINLOOP(8)
    const int r0 = lane >> 2, c0 = (lane & 3) * 2;
#pragma unroll
    for (int mf = 0; mf < 4; mf++) {
        const int mA = m0 + wm + mf * 16 + r0;
#pragma unroll
        for (int nf = 0; nf < 4; nf++) {
            const int n = n0 + wn + nf * 8 + c0;
            const size_t i0 = (size_t)mA * (NH * DV) + h * DV + n;
            const size_t i1 = (size_t)(mA + 8) * (NH * DV) + h * DV + n;
            *(__half2*)&g_o2f[i0] = __floats2half2_rn(acc[mf][nf][0], acc[mf][nf][1]);
            *(__half2*)&g_o2f[i1] = __floats2half2_rn(acc[mf][nf][2], acc[mf][nf][3]);
        }
    }
}

// ====== fp16 scores 128x256 tile, 3-stage pipeline, fp16 S output ============
__global__ void __launch_bounds__(256)
scores_f16(const __half* __restrict__ Q, size_t sQz,
           const __half* __restrict__ Kc, size_t sKz,
           __half* __restrict__ C, int ldc, size_t sCz,
           int K, const float* __restrict__ mask, float scale)
{
    extern __shared__ char smem[];
    const int z = blockIdx.z;
    const int m0 = blockIdx.y * 128, n0 = blockIdx.x * 256;
    Q += (size_t)z * sQz;  Kc += (size_t)z * sKz;  C += (size_t)z * sCz;

    const int tid = threadIdx.x;
    const int warp = tid >> 5, lane = tid & 31;
    const int wm = (warp >> 2) * 64, wn = (warp & 3) * 64;
    const uint32_t smem32 = smem_u32(smem);
    const int qrow = lane & 15, qsel = lane >> 4;

    const __half* gsrc[3];
    uint32_t swb[3];
#pragma unroll
    for (int j = 0; j < 3; j++) {
        const int h = tid + j * 256;
        const int half = h & 1;
        int r;
        uint32_t tbase;
        const __half* base;
        if (h < 256) { r = h >> 1; tbase = 0u; base = Q + (size_t)(m0 + r) * K; }
        else { r = (h - 256) >> 1; tbase = 16384u; base = Kc + (size_t)(n0 + r) * K; }
        swb[j] = tbase + sw128((uint32_t)r * 128u + half * 64u);
        gsrc[j] = base + half * 32;
    }

    float acc[4][8][4];
#pragma unroll
    for (int i = 0; i < 4; i++)
#pragma unroll
        for (int j = 0; j < 8; j++)
#pragma unroll
            for (int r = 0; r < 4; r++) acc[i][j][r] = 0.f;

    const int nch = K >> 6;
#define SC_PREFETCH(STAGE, CH)                                                       \
    {                                                                                \
        const uint32_t sb = smem32 + (uint32_t)(STAGE) * SF_STAGE;                   \
        _Pragma("unroll") for (int j = 0; j < 3; j++)                                \
            _Pragma("unroll") for (int i = 0; i < 4; i++)                            \
                cpa16(sb + (swb[j] ^ (i * 16u)), gsrc[j] + (CH) * 64 + i * 8);       \
        cpa_commit();                                                                \
    }
    {
        const int pre = (nch < 2) ? nch : 2;
        for (int s = 0; s < pre; s++) SC_PREFETCH(s, s)
    }
    for (int c = 0; c < nch; c++) {
        if (c + 2 < nch) {
            SC_PREFETCH((c + 2) % 3, c + 2)
            cpa_wait2();
        } else if (c + 1 < nch) {
            cpa_wait1();
        } else {
            cpa_wait0();
        }
        __syncthreads();

        const uint32_t st = smem32 + (uint32_t)(c % 3) * SF_STAGE;
        const uint32_t A32 = st, B32 = st + 16384;
#pragma unroll
        for (int ks = 0; ks < 4; ks++) {
            const uint32_t kofs = ks * 32u + qsel * 16u;
            uint32_t a[4][4];
#pragma unroll
            for (int mf = 0; mf < 4; mf++) {
                int row = wm + mf * 16 + qrow;
                ldm_x4(a[mf], A32 + sw128((uint32_t)row * 128u + kofs));
            }
            uint32_t b[8][2];
#pragma unroll
            for (int nh = 0; nh < 4; nh++) {
                int row = wn + nh * 16 + qrow;
                uint32_t t[4];
                ldm_x4(t, B32 + sw128((uint32_t)row * 128u + kofs));
                b[nh * 2 + 0][0] = t[0]; b[nh * 2 + 0][1] = t[2];
                b[nh * 2 + 1][0] = t[1]; b[nh * 2 + 1][1] = t[3];
            }
#pragma unroll
            for (int mf = 0; mf < 4; mf++)
#pragma unroll
                for (int nf = 0; nf < 8; nf++)
                    mma_f16(acc[mf][nf], a[mf], b[nf]);
        }
        __syncthreads();
    }

    const int r0 = lane >> 2, c0 = (lane & 3) * 2;
#pragma unroll
    for (int mf = 0; mf < 4; mf++) {
        const int mA = m0 + wm + mf * 16 + r0;
        const float* mrow = mask + (size_t)(mA >> 4) * MAXT;
#pragma unroll
        for (int nf = 0; nf < 8; nf++) {
            const int n = n0 + wn + nf * 8 + c0;
            float v0 = acc[mf][nf][0] * scale + mrow[n];
            float v1 = acc[mf][nf][1] * scale + mrow[n + 1];
            float v2 = acc[mf][nf][2] * scale + mrow[n];
            float v3 = acc[mf][nf][3] * scale + mrow[n + 1];
            *(__half2*)&C[(size_t)mA * ldc + n]       = __floats2half2_rn(v0, v1);
            *(__half2*)&C[(size_t)(mA + 8) * ldc + n] = __floats2half2_rn(v2, v3);
        }
    }
}

// ================= merged weight/x conversion (all fp16) =====================
#define C4_X    131072
#define C4_QD   (C4_X + 393216)
#define C4_QU   (C4_QD + 589824)
#define C4_KVD  (C4_QU + 327680)
#define C4_OUT  (C4_KVD + 1048576)
#define C4_WKVU (C4_OUT + 524288)
#define KVD_SRC4 294912
__global__ void conv_all(const float4* __restrict__ x, const float4* __restrict__ wqd,
                         const float4* __restrict__ wqu, const float4* __restrict__ wkvd,
                         const float4* __restrict__ wout, const float4* __restrict__ wkvu) {
    const int i = blockIdx.x * 256 + threadIdx.x;
    if (i < C4_X) {
        half4_write(x[i], g_xf, i);
    } else if (i < C4_QD) {
        const int j = i - C4_X;
        half4_write(wqd[j], g_wqdf, j);
    } else if (i < C4_QU) {
        const int j = i - C4_QD;
        half4_write(wqu[j], g_wquf, j);
    } else if (i < C4_KVD) {
        const int j = i - C4_QU;
        float4 v = (j < KVD_SRC4) ? wkvd[j] : make_float4(0.f, 0.f, 0.f, 0.f);
        half4_write(v, g_wkvdf, j);
    } else if (i < C4_OUT) {
        const int j = i - C4_KVD;
        half4_write(wout[j], g_woutf, j);
    } else if (i < C4_WKVU) {
        const int j = i - C4_OUT;
        half4_write(wkvu[j], g_wvf, j);
    }
}

// transpose nr part of w_kvu -> fp16
__global__ void build_wnrt(const float* __restrict__ wkvu) {
    __shared__ float tile[32][33];
    const int h = blockIdx.z;
    const int n0 = blockIdx.x * 32, d0 = blockIdx.y * 32;
    const int tx = threadIdx.x, ty = threadIdx.y;
#pragma unroll
    for (int i = 0; i < 4; i++) {
        const int d = d0 + ty + i * 8;
        tile[ty + i * 8][tx] = wkvu[(size_t)(h * 256 + d) * KVR + n0 + tx];
    }
    __syncthreads();
#pragma unroll
    for (int i = 0; i < 4; i++) {
        const int n = n0 + ty + i * 8;
        const float v = tile[tx][ty + i * 8];
        g_wnrtf[(size_t)h * KVR * DNR + (size_t)n * DNR + d0 + tx] = __float2half_rn(v);
    }
}

// ====== merged kv builder: kc (t-major) + kt (n-major) + fused rope ==========
__global__ void build_kv2(const float* __restrict__ kvc, const float* __restrict__ krc,
                          const float* __restrict__ fc, const float* __restrict__ fs) {
    __shared__ float tile[32][33];
    const int b = blockIdx.z;
    const int t0 = blockIdx.x * 32;
    const int y = blockIdx.y;
    const int tx = threadIdx.x, ty = threadIdx.y;
    if (y < 16) {
        const int n0 = y * 32;
#pragma unroll
        for (int i = 0; i < 4; i++) {
            const int t = t0 + ty + i * 8;
            float v;
            if (t >= START_P)
                v = g_kv[(size_t)((b << 5) + (t - START_P)) * CATD + n0 + tx];
            else
                v = kvc[((size_t)b * MAXT + t) * KVR + n0 + tx];
            tile[ty + i * 8][tx] = v;
            g_kc[((size_t)b * MAXT + t) * CATD + n0 + tx] = __float2half_rn(v);
        }
        __syncthreads();
#pragma unroll
        for (int i = 0; i < 4; i++) {
            const int n = n0 + ty + i * 8;
            const float v = tile[tx][ty + i * 8];
            g_kt[((size_t)(b * KVR + n)) * MAXT + t0 + tx] = __float2half_rn(v);
        }
    } else {
        // rope columns c in [KVR, KVR+64)
        const int c0 = KVR + (y - 16) * 32;
#pragma unroll
        for (int i = 0; i < 4; i++) {
            const int t = t0 + ty + i * 8;
            const int c = c0 + tx;
            float v;
            if (t >= START_P) {
                const int l = t - START_P;
                const int j = (c - KVR) >> 1;
                const size_t base = (size_t)((b << 5) + l) * CATD + KVR + 2 * j;
                const float xr = g_kv[base], xi = g_kv[base + 1];
                const float cth = fc[l * 32 + j], sth = fs[l * 32 + j];
                v = ((c & 1) == 0) ? (xr * cth - xi * sth) : (xr * sth + xi * cth);
            } else {
                v = krc[((size_t)b * MAXT + t) * DR + (c - KVR)];
            }
            g_kc[((size_t)b * MAXT + t) * CATD + c] = __float2half_rn(v);
        }
    }
}

// ================= RMSNorm -> fp16 ===========================================
__global__ void rms_kernel(const float* __restrict__ w) {
    const int row = blockIdx.x;
    const float* xr = g_qd + row * QR;
    __shared__ float red[256];
    const int tid = threadIdx.x;
    float v[3], s = 0.f;
#pragma unroll
    for (int i = 0; i < 3; i++) { v[i] = xr[tid + i * 256]; s += v[i] * v[i]; }
    red[tid] = s; __syncthreads();
    for (int o = 128; o > 0; o >>= 1) {
        if (tid < o) red[tid] += red[tid + o];
        __syncthreads();
    }
    const float r = rsqrtf(red[0] / (float)QR + 1.1920929e-07f);
    __syncthreads();
#pragma unroll
    for (int i = 0; i < 3; i++) {
        const float y = v[i] * r * w[tid + i * 256];
        g_qnf[(size_t)row * QR + tid + i * 256] = __float2half_rn(y);
    }
}

// ====== fused q conversion + rope-q (reads p_q fp32 directly) ================
#define CQ_N1 (MBL * NH * QKD / 4)          // 196608 quad-convert threads
#define CQ_N2 (BATCH * SEQ_L * NH * 32)     // 131072 rope-pair threads
__global__ void conv_q(const float* __restrict__ fc, const float* __restrict__ fs) {
    const int idx = blockIdx.x * 256 + threadIdx.x;
    if (idx < CQ_N1) {
        half4_write(((const float4*)g_q)[idx], g_qf, idx);
    } else if (idx < CQ_N1 + CQ_N2) {
        const int k = idx - CQ_N1;
        const int j = k & 31, h = (k >> 5) & 15, l = (k >> 9) & 31, b = k >> 14;
        const size_t si = (size_t)(b * SEQ_L + l) * (NH * QKD) + h * QKD + DNR + 2 * j;
        const float xr = g_q[si], xi = g_q[si + 1];
        const float c = fc[l * 32 + j], s = fs[l * 32 + j];
        const size_t o = (size_t)(b * ROWSPB + l * NH + h) * CATD + KVR + 2 * j;
        *(__half2*)&g_qc[o] = __floats2half2_rn(xr * c - xi * s, xr * s + xi * c);
    }
}

// ================= softmax (fp16 in) -> fp16 P ===============================
__global__ void softmax_split() {
    const int row = blockIdx.x;
    const __half* srow = g_S16 + (size_t)row * MAXT;
    __shared__ float red[256];
    const int tid = threadIdx.x;
    float4 v[4];
    float mx = -INFINITY;
#pragma unroll
    for (int g = 0; g < 4; g++) {
        uint2 r = *(const uint2*)&srow[tid * 4 + g * 1024];
        float2 fa = __half22float2(*(__half2*)&r.x);
        float2 fb = __half22float2(*(__half2*)&r.y);
        v[g] = make_float4(fa.x, fa.y, fb.x, fb.y);
        mx = fmaxf(mx, fmaxf(fmaxf(v[g].x, v[g].y), fmaxf(v[g].z, v[g].w)));
    }
    red[tid] = mx; __syncthreads();
    for (int o = 128; o > 0; o >>= 1) {
        if (tid < o) red[tid] = fmaxf(red[tid], red[tid + o]);
        __syncthreads();
    }
    mx = red[0]; __syncthreads();
    float sum = 0.f;
#pragma unroll
    for (int g = 0; g < 4; g++) {
        v[g].x = __expf(v[g].x - mx); v[g].y = __expf(v[g].y - mx);
        v[g].z = __expf(v[g].z - mx); v[g].w = __expf(v[g].w - mx);
        sum += v[g].x + v[g].y + v[g].z + v[g].w;
    }
    red[tid] = sum; __syncthreads();
    for (int o = 128; o > 0; o >>= 1) {
        if (tid < o) red[tid] += red[tid + o];
        __syncthreads();
    }
    const float inv = 1.f / red[0];
#pragma unroll
    for (int g = 0; g < 4; g++) {
        float4 p = make_float4(v[g].x * inv, v[g].y * inv, v[g].z * inv, v[g].w * inv);
        half4_write(p, g_p, ((size_t)row * MAXT + tid * 4 + g * 1024) >> 2);
    }
}

// ============================== launcher =====================================
extern "C" void kernel_launch(void* const* d_in, const int* in_sizes, int n_in,
                              void* d_out, int out_size) {
    const float* x      = (const float*)d_in[0];
    const float* fc     = (const float*)d_in[2];
    const float* fs     = (const float*)d_in[3];
    const float* mask   = (const float*)d_in[4];
    const float* kvc    = (const float*)d_in[5];
    const float* krc    = (const float*)d_in[6];
    const float* w_kvd  = (const float*)d_in[7];
    const float* w_qd   = (const float*)d_in[8];
    const float* rms_w  = (const float*)d_in[9];
    const float* w_qu   = (const float*)d_in[10];
    const float* w_kvu  = (const float*)d_in[11];
    const float* w_out  = (const float*)d_in[12];
    float* out = (float*)d_out;

    float *p_qd, *p_q, *p_kv;
    cudaGetSymbolAddress((void**)&p_qd, g_qd);
    cudaGetSymbolAddress((void**)&p_q,  g_q);
    cudaGetSymbolAddress((void**)&p_kv, g_kv);

    __half *qc, *kc, *kt, *pp, *S16, *xf, *qnf, *Of, *o2f;
    __half *wqdf, *wquf, *wkvdf, *woutf;
    cudaGetSymbolAddress((void**)&qc, g_qc);
    cudaGetSymbolAddress((void**)&kc, g_kc);
    cudaGetSymbolAddress((void**)&kt, g_kt);
    cudaGetSymbolAddress((void**)&pp, g_p);
    cudaGetSymbolAddress((void**)&S16, g_S16);
    cudaGetSymbolAddress((void**)&xf, g_xf);
    cudaGetSymbolAddress((void**)&qnf, g_qnf);
    cudaGetSymbolAddress((void**)&Of, g_Of);
    cudaGetSymbolAddress((void**)&o2f, g_o2f);
    cudaGetSymbolAddress((void**)&wqdf, g_wqdf);
    cudaGetSymbolAddress((void**)&wquf, g_wquf);
    cudaGetSymbolAddress((void**)&wkvdf, g_wkvdf);
    cudaGetSymbolAddress((void**)&woutf, g_woutf);

    static cudaStream_t s_kv = nullptr;
    static cudaEvent_t ev_fork = nullptr, ev_join = nullptr;
    if (!s_kv) {
        cudaStreamCreateWithFlags(&s_kv, cudaStreamNonBlocking);
        cudaEventCreateWithFlags(&ev_fork, cudaEventDisableTiming);
        cudaEventCreateWithFlags(&ev_join, cudaEventDisableTiming);
        cudaFuncSetAttribute(gemm_f16_sk, cudaFuncAttributeMaxDynamicSharedMemorySize, 3 * OF_STAGE);
        cudaFuncSetAttribute(qabs_f16, cudaFuncAttributeMaxDynamicSharedMemorySize, 2 * OF_STAGE);
        cudaFuncSetAttribute(oup_f16, cudaFuncAttributeMaxDynamicSharedMemorySize, 3 * OF_STAGE);
        cudaFuncSetAttribute(scores_f16, cudaFuncAttributeMaxDynamicSharedMemorySize, 3 * SF_STAGE);
        cudaFuncSetAttribute(ogemm_f16, cudaFuncAttributeMaxDynamicSharedMemorySize, 3 * OF_STAGE);
    }

    // ---- root: memsets + conversions ----
    cudaMemsetAsync(p_qd, 0, (size_t)MBL * QR * 4);
    cudaMemsetAsync(p_q, 0, (size_t)MBL * NH * QKD * 4);
    cudaMemsetAsync(p_kv, 0, (size_t)MBL * CATD * 4);
    cudaMemsetAsync(out, 0, (size_t)MBL * DIM * 4);
    conv_all<<<C4_WKVU / 256, 256>>>((const float4*)x, (const float4*)w_qd, (const float4*)w_qu,
                                     (const float4*)w_kvd, (const float4*)w_out, (const float4*)w_kvu);
    build_wnrt<<<dim3(KVR / 32, DNR / 32, NH), dim3(32, 8)>>>(w_kvu);

    // ---- fork: kv-path on s_kv, q-path on default ----
    cudaEventRecord(ev_fork, 0);
    cudaStreamWaitEvent(s_kv, ev_fork, 0);

    // kv path (fp16 kvd -> merged builder with fused rope)
    gemm_f16_sk<<<dim3(KVD_PAD / 128, MBL / 128, 8), 256, 3 * OF_STAGE, s_kv>>>(
        xf, wkvdf, p_kv, CATD, DIM, DIM / 8, CATD);
    build_kv2<<<dim3(MAXT / 32, 18, BATCH), dim3(32, 8), 0, s_kv>>>(kvc, krc, fc, fs);
    cudaEventRecord(ev_join, s_kv);

    // q path
    gemm_f16_sk<<<dim3(QR / 128, MBL / 128, 8), 256, 3 * OF_STAGE>>>(
        xf, wqdf, p_qd, QR, DIM, DIM / 8, QR);
    rms_kernel<<<MBL, 256>>>(rms_w);
    gemm_f16_sk<<<dim3(NH * QKD / 128, MBL / 128, 4), 256, 3 * OF_STAGE>>>(
        qnf, wquf, p_q, NH * QKD, QR, QR / 4, NH * QKD);
    conv_q<<<(CQ_N1 + CQ_N2 + 255) / 256, 256>>>(fc, fs);
    qabs_f16<<<dim3(KVR / 128, MBL / 128, NH), 256, 2 * OF_STAGE>>>();

    // ---- join q/kv ----
    cudaStreamWaitEvent(0, ev_join, 0);

    // ---- attention ----
    scores_f16<<<dim3(MAXT / 256, ROWSPB / 128, BATCH), 256, 3 * SF_STAGE>>>(
        qc, (size_t)ROWSPB * CATD, kc, (size_t)MAXT * CATD,
        S16, MAXT, (size_t)ROWSPB * MAXT, CATD, mask, SCALE_F);
    softmax_split<<<BATCH * ROWSPB, 256>>>();
    ogemm_f16<<<dim3(KVR / 128, ROWSPB / 128, BATCH), 256, 3 * OF_STAGE>>>(
        pp, (size_t)ROWSPB * MAXT, kt, (size_t)KVR * MAXT,
        Of, KVR, (size_t)ROWSPB * KVR, MAXT);

    // ---- output path ----
    oup_f16<<<dim3(1, MBL / 128, NH), 256, 3 * OF_STAGE>>>();
    gemm_f16_sk<<<dim3(DIM / 128, MBL / 128, 8), 256, 3 * OF_STAGE>>>(
        o2f, woutf, out, DIM, NH * DV, NH * DV / 8, DIM);
}

// round 14
// speedup vs baseline: 1.8868x; 1.0169x over previous
#include <cuda_runtime.h>
#include <cuda_fp16.h>
#include <math.h>
#include <stdint.h>

// ---------------- problem constants -----------------------------------------
#define BATCH   8
#define SEQ_L   32
#define DIM     2048
#define KVR     512
#define QR      768
#define NH      16
#define DNR     128
#define DR      64
#define DV      128
#define MAXT    4096
#define START_P 4064
#define QKD     192
#define CATD    576
#define MBL     256
#define ROWSPB  512
#define SCALE_F 0.07216878364870323f
#define KVD_PAD 640

// ---------------- fp32 scratch ----------------------------------------------
__device__ __align__(16) float g_qd  [MBL * QR];
__device__ __align__(16) float g_q   [MBL * NH * QKD];
__device__ __align__(16) float g_kv  [MBL * CATD];
// ---------------- fp16 operands ----------------------------------------------
__device__ __align__(16) __half g_S16[(size_t)BATCH * ROWSPB * MAXT];
__device__ __align__(16) __half g_qc [BATCH * ROWSPB * CATD];
__device__ __align__(16) __half g_kc [(size_t)BATCH * MAXT * CATD];
__device__ __align__(16) __half g_kt [(size_t)BATCH * KVR * MAXT];
__device__ __align__(16) __half g_p  [(size_t)BATCH * ROWSPB * MAXT];
__device__ __align__(16) __half g_Of [BATCH * ROWSPB * KVR];
__device__ __align__(16) __half g_o2f[MBL * NH * DV];
__device__ __align__(16) __half g_xf [MBL * DIM];
__device__ __align__(16) __half g_qnf[MBL * QR];
__device__ __align__(16) __half g_qf [MBL * NH * QKD];
__device__ __align__(16) __half g_wqdf [QR * DIM];
__device__ __align__(16) __half g_wquf [NH * QKD * QR];
__device__ __align__(16) __half g_wkvdf[KVD_PAD * DIM];
__device__ __align__(16) __half g_woutf[DIM * NH * DV];
__device__ __align__(16) __half g_wvf  [NH * 256 * KVR];
__device__ __align__(16) __half g_wnrtf[NH * KVR * DNR];

// ================= helpers ===================================================
__device__ __forceinline__ uint32_t smem_u32(const void* p) {
    uint32_t a;
    asm("{ .reg .u64 t; cvta.to.shared.u64 t, %1; cvt.u32.u64 %0, t; }" : "=r"(a) : "l"(p));
    return a;
}
__device__ __forceinline__ uint32_t sw128(uint32_t o) { return o ^ ((o >> 3) & 0x70); }
__device__ __forceinline__ void cpa16(uint32_t saddr, const void* g) {
    asm volatile("cp.async.cg.shared.global [%0], [%1], 16;" :: "r"(saddr), "l"(g));
}
__device__ __forceinline__ void cpa_commit() { asm volatile("cp.async.commit_group;" ::: "memory"); }
__device__ __forceinline__ void cpa_wait2()  { asm volatile("cp.async.wait_group 2;" ::: "memory"); }
__device__ __forceinline__ void cpa_wait1()  { asm volatile("cp.async.wait_group 1;" ::: "memory"); }
__device__ __forceinline__ void cpa_wait0()  { asm volatile("cp.async.wait_group 0;" ::: "memory"); }
__device__ __forceinline__ void ldm_x4(uint32_t* r, uint32_t addr) {
    asm volatile("ldmatrix.sync.aligned.m8n8.x4.shared.b16 {%0,%1,%2,%3}, [%4];"
                 : "=r"(r[0]), "=r"(r[1]), "=r"(r[2]), "=r"(r[3]) : "r"(addr));
}
__device__ __forceinline__ void mma_f16(float* c, const uint32_t* a, const uint32_t* b) {
    asm volatile("mma.sync.aligned.m16n8k16.row.col.f32.f16.f16.f32 "
                 "{%0,%1,%2,%3}, {%4,%5,%6,%7}, {%8,%9}, {%0,%1,%2,%3};"
                 : "+f"(c[0]), "+f"(c[1]), "+f"(c[2]), "+f"(c[3])
                 : "r"(a[0]), "r"(a[1]), "r"(a[2]), "r"(a[3]), "r"(b[0]), "r"(b[1]));
}
__device__ __forceinline__ void half4_write(float4 v, __half* dst, size_t i4) {
    __half2 a = __floats2half2_rn(v.x, v.y);
    __half2 b = __floats2half2_rn(v.z, v.w);
    *(uint2*)&dst[i4 * 4] = make_uint2(*(uint32_t*)&a, *(uint32_t*)&b);
}
__device__ __forceinline__ uint2 f4_to_h4(float4 v) {
    __half2 a = __floats2half2_rn(v.x, v.y);
    __half2 b = __floats2half2_rn(v.z, v.w);
    return make_uint2(*(uint32_t*)&a, *(uint32_t*)&b);
}

#define OF_STAGE 32768   // fp16 128x128: A 16KB @0, B 16KB @16384
#define SF_STAGE 49152   // fp16 128x256: A 16KB @0, B 32KB @16384

// ======== fp16 128x128 single-term mainloop (one row / thread loader) ========
#define F16_PREFETCH(STAGE, CH)                                                      \
    {                                                                                \
        const uint32_t sb = smem32 + (uint32_t)(STAGE) * OF_STAGE;                   \
        _Pragma("unroll") for (int i = 0; i < 8; i++)                                \
            cpa16(sb + soff[i], src + (CH) * 64 + i * 8);                            \
        cpa_commit();                                                                \
    }

#define F16_MAINLOOP(NCH)                                                            \
    {                                                                                \
        const int pre = ((NCH) < 2) ? (NCH) : 2;                                     \
        for (int s = 0; s < pre; s++) F16_PREFETCH(s, s)                             \
    }                                                                                \
    for (int c = 0; c < (NCH); c++) {                                                \
        if (c + 2 < (NCH)) {                                                         \
            F16_PREFETCH((c + 2) % 3, c + 2)                                         \
            cpa_wait2();                                                             \
        } else if (c + 1 < (NCH)) {                                                  \
            cpa_wait1();                                                             \
        } else {                                                                     \
            cpa_wait0();                                                             \
        }                                                                            \
        __syncthreads();                                                             \
        const uint32_t st = smem32 + (uint32_t)(c % 3) * OF_STAGE;                   \
        const uint32_t A32 = st, B32 = st + 16384;                                   \
        _Pragma("unroll") for (int ks = 0; ks < 4; ks++) {                           \
            const uint32_t kofs = ks * 32u + qsel * 16u;                             \
            uint32_t a[4][4];                                                        \
            _Pragma("unroll") for (int mf = 0; mf < 4; mf++) {                       \
                int row = wm + mf * 16 + qrow;                                       \
                ldm_x4(a[mf], A32 + sw128((uint32_t)row * 128u + kofs));             \
            }                                                                        \
            uint32_t b[4][2];                                                        \
            _Pragma("unroll") for (int nh = 0; nh < 2; nh++) {                       \
                int row = wn + nh * 16 + qrow;                                       \
                uint32_t t[4];                                                       \
                ldm_x4(t, B32 + sw128((uint32_t)row * 128u + kofs));                 \
                b[nh * 2 + 0][0] = t[0]; b[nh * 2 + 0][1] = t[2];                    \
                b[nh * 2 + 1][0] = t[1]; b[nh * 2 + 1][1] = t[3];                    \
            }                                                                        \
            _Pragma("unroll") for (int mf = 0; mf < 4; mf++)                         \
                _Pragma("unroll") for (int nf = 0; nf < 4; nf++)                     \
                    mma_f16(acc[mf][nf], a[mf], b[nf]);                              \
        }                                                                            \
        __syncthreads();                                                             \
    }

#define F16_DECL                                                                     \
    const int tid = threadIdx.x;                                                     \
    const int warp = tid >> 5, lane = tid & 31;                                      \
    const int wm = (warp >> 2) * 64, wn = (warp & 3) * 32;                           \
    const uint32_t smem32 = smem_u32(smem);                                          \
    const int qrow = lane & 15, qsel = lane >> 4;                                    \
    const bool isB = tid >= 128;                                                     \
    const int lrow = tid & 127;                                                      \
    uint32_t soff[8];                                                                \
    _Pragma("unroll") for (int i = 0; i < 8; i++)                                    \
        soff[i] = (isB ? 16384u : 0u) + sw128((uint32_t)lrow * 128u + i * 16u);      \
    float acc[4][4][4];                                                              \
    _Pragma("unroll") for (int i = 0; i < 4; i++)                                    \
        _Pragma("unroll") for (int j = 0; j < 4; j++)                                \
            _Pragma("unroll") for (int r = 0; r < 4; r++) acc[i][j][r] = 0.f;

// ====== fp16 split-K GEMM (qd, kvd, qu, out-proj): fp32 atomicAdd ============
__global__ void __launch_bounds__(256)
gemm_f16_sk(const __half* __restrict__ A, const __half* __restrict__ B,
            float* __restrict__ C, int ldc, int K, int kpart, int N)
{
    extern __shared__ char smem[];
    const int m0 = blockIdx.y * 128, n0 = blockIdx.x * 128;
    const int kb = blockIdx.z * kpart;
    F16_DECL
    const __half* src = isB ? (B + (size_t)(n0 + lrow) * K + kb)
                            : (A + (size_t)(m0 + lrow) * K + kb);
    const int nch = kpart >> 6;
    F16_MAINLOOP(nch)
    const int r0 = lane >> 2, c0 = (lane & 3) * 2;
#pragma unroll
    for (int mf = 0; mf < 4; mf++) {
        const int mA = m0 + wm + mf * 16 + r0;
#pragma unroll
        for (int nf = 0; nf < 4; nf++) {
            const int n = n0 + wn + nf * 8 + c0;
            if (n < N) {
                atomicAdd(&C[(size_t)mA * ldc + n],           acc[mf][nf][0]);
                atomicAdd(&C[(size_t)mA * ldc + n + 1],       acc[mf][nf][1]);
                atomicAdd(&C[(size_t)(mA + 8) * ldc + n],     acc[mf][nf][2]);
                atomicAdd(&C[(size_t)(mA + 8) * ldc + n + 1], acc[mf][nf][3]);
            }
        }
    }
}

// ====== qabs fp16: per-head q_nrope @ w_nr^T -> fp16 qcat ====================
__global__ void __launch_bounds__(256)
qabs_f16()
{
    extern __shared__ char smem[];
    const int h = blockIdx.z;
    const int m0 = blockIdx.y * 128, n0 = blockIdx.x * 128;
    F16_DECL
    const __half* src = isB ? (g_wnrtf + (size_t)h * KVR * DNR + (size_t)(n0 + lrow) * DNR)
                            : (g_qf + (size_t)(m0 + lrow) * (NH * QKD) + h * QKD);
    F16_MAINLOOP(2)
    const int r0 = lane >> 2, c0 = (lane & 3) * 2;
#pragma unroll
    for (int mf = 0; mf < 4; mf++) {
        const int mA = m0 + wm + mf * 16 + r0;
        const int rowA = ((mA >> 5) * ROWSPB) + (mA & 31) * NH + h;
        const int rowB = (((mA + 8) >> 5) * ROWSPB) + ((mA + 8) & 31) * NH + h;
#pragma unroll
        for (int nf = 0; nf < 4; nf++) {
            const int n = n0 + wn + nf * 8 + c0;
            *(__half2*)&g_qc[(size_t)rowA * CATD + n] = __floats2half2_rn(acc[mf][nf][0], acc[mf][nf][1]);
            *(__half2*)&g_qc[(size_t)rowB * CATD + n] = __floats2half2_rn(acc[mf][nf][2], acc[mf][nf][3]);
        }
    }
}

// ====== ogemm fp16: O = P*KV^T -> fp16 O =====================================
__global__ void __launch_bounds__(256)
ogemm_f16(const __half* __restrict__ P, size_t sPz,
          const __half* __restrict__ Kt, size_t sKz,
          __half* __restrict__ C, int ldc, size_t sCz, int K)
{
    extern __shared__ char smem[];
    const int z = blockIdx.z;
    const int m0 = blockIdx.y * 128, n0 = blockIdx.x * 128;
    P += (size_t)z * sPz;  Kt += (size_t)z * sKz;  C += (size_t)z * sCz;
    F16_DECL
    const __half* src = isB ? (Kt + (size_t)(n0 + lrow) * K)
                            : (P + (size_t)(m0 + lrow) * K);
    const int nch = K >> 6;
    F16_MAINLOOP(nch)
    const int r0 = lane >> 2, c0 = (lane & 3) * 2;
#pragma unroll
    for (int mf = 0; mf < 4; mf++) {
        const int mA = m0 + wm + mf * 16 + r0;
#pragma unroll
        for (int nf = 0; nf < 4; nf++) {
            const int n = n0 + wn + nf * 8 + c0;
            *(__half2*)&C[(size_t)mA * ldc + n]       = __floats2half2_rn(acc[mf][nf][0], acc[mf][nf][1]);
            *(__half2*)&C[(size_t)(mA + 8) * ldc + n] = __floats2half2_rn(acc[mf][nf][2], acc[mf][nf][3]);
        }
    }
}

// ====== oup fp16: per-head O @ w_v^T -> fp16 o2 ==============================
__global__ void __launch_bounds__(256)
oup_f16()
{
    extern __shared__ char smem[];
    const int h = blockIdx.z;
    const int m0 = blockIdx.y * 128, n0 = 0;
    F16_DECL
    const int mrow = m0 + lrow;
    const int arow = (mrow >> 5) * ROWSPB + (mrow & 31) * NH + h;
    const __half* src = isB ? (g_wvf + (size_t)(h * 256 + DNR + n0 + lrow) * KVR)
                            : (g_Of + (size_t)arow * KVR);
    F16_MAINLOOP(8)
    const int r0 = lane >> 2, c0 = (lane & 3) * 2;
#pragma unroll
    for (int mf = 0; mf < 4; mf++) {
        const int mA = m0 + wm + mf * 16 + r0;
#pragma unroll
        for (int nf = 0; nf < 4; nf++) {
            const int n = n0 + wn + nf * 8 + c0;
            const size_t i0 = (size_t)mA * (NH * DV) + h * DV + n;
            const size_t i1 = (size_t)(mA + 8) * (NH * DV) + h * DV + n;
            *(__half2*)&g_o2f[i0] = __floats2half2_rn(acc[mf][nf][0], acc[mf][nf][1]);
            *(__half2*)&g_o2f[i1] = __floats2half2_rn(acc[mf][nf][2], acc[mf][nf][3]);
        }
    }
}

// ====== fp16 scores 128x256 tile, 3-stage pipeline, fp16 S output ============
__global__ void __launch_bounds__(256)
scores_f16(const __half* __restrict__ Q, size_t sQz,
           const __half* __restrict__ Kc, size_t sKz,
           __half* __restrict__ C, int ldc, size_t sCz,
           int K, const float* __restrict__ mask, float scale)
{
    extern __shared__ char smem[];
    const int z = blockIdx.z;
    const int m0 = blockIdx.y * 128, n0 = blockIdx.x * 256;
    Q += (size_t)z * sQz;  Kc += (size_t)z * sKz;  C += (size_t)z * sCz;

    const int tid = threadIdx.x;
    const int warp = tid >> 5, lane = tid & 31;
    const int wm = (warp >> 2) * 64, wn = (warp & 3) * 64;
    const uint32_t smem32 = smem_u32(smem);
    const int qrow = lane & 15, qsel = lane >> 4;

    const __half* gsrc[3];
    uint32_t swb[3];
#pragma unroll
    for (int j = 0; j < 3; j++) {
        const int h = tid + j * 256;
        const int half = h & 1;
        int r;
        uint32_t tbase;
        const __half* base;
        if (h < 256) { r = h >> 1; tbase = 0u; base = Q + (size_t)(m0 + r) * K; }
        else { r = (h - 256) >> 1; tbase = 16384u; base = Kc + (size_t)(n0 + r) * K; }
        swb[j] = tbase + sw128((uint32_t)r * 128u + half * 64u);
        gsrc[j] = base + half * 32;
    }

    float acc[4][8][4];
#pragma unroll
    for (int i = 0; i < 4; i++)
#pragma unroll
        for (int j = 0; j < 8; j++)
#pragma unroll
            for (int r = 0; r < 4; r++) acc[i][j][r] = 0.f;

    const int nch = K >> 6;
#define SC_PREFETCH(STAGE, CH)                                                       \
    {                                                                                \
        const uint32_t sb = smem32 + (uint32_t)(STAGE) * SF_STAGE;                   \
        _Pragma("unroll") for (int j = 0; j < 3; j++)                                \
            _Pragma("unroll") for (int i = 0; i < 4; i++)                            \
                cpa16(sb + (swb[j] ^ (i * 16u)), gsrc[j] + (CH) * 64 + i * 8);       \
        cpa_commit();                                                                \
    }
    {
        const int pre = (nch < 2) ? nch : 2;
        for (int s = 0; s < pre; s++) SC_PREFETCH(s, s)
    }
    for (int c = 0; c < nch; c++) {
        if (c + 2 < nch) {
            SC_PREFETCH((c + 2) % 3, c + 2)
            cpa_wait2();
        } else if (c + 1 < nch) {
            cpa_wait1();
        } else {
            cpa_wait0();
        }
        __syncthreads();

        const uint32_t st = smem32 + (uint32_t)(c % 3) * SF_STAGE;
        const uint32_t A32 = st, B32 = st + 16384;
#pragma unroll
        for (int ks = 0; ks < 4; ks++) {
            const uint32_t kofs = ks * 32u + qsel * 16u;
            uint32_t a[4][4];
#pragma unroll
            for (int mf = 0; mf < 4; mf++) {
                int row = wm + mf * 16 + qrow;
                ldm_x4(a[mf], A32 + sw128((uint32_t)row * 128u + kofs));
            }
            uint32_t b[8][2];
#pragma unroll
            for (int nh = 0; nh < 4; nh++) {
                int row = wn + nh * 16 + qrow;
                uint32_t t[4];
                ldm_x4(t, B32 + sw128((uint32_t)row * 128u + kofs));
                b[nh * 2 + 0][0] = t[0]; b[nh * 2 + 0][1] = t[2];
                b[nh * 2 + 1][0] = t[1]; b[nh * 2 + 1][1] = t[3];
            }
#pragma unroll
            for (int mf = 0; mf < 4; mf++)
#pragma unroll
                for (int nf = 0; nf < 8; nf++)
                    mma_f16(acc[mf][nf], a[mf], b[nf]);
        }
        __syncthreads();
    }

    const int r0 = lane >> 2, c0 = (lane & 3) * 2;
#pragma unroll
    for (int mf = 0; mf < 4; mf++) {
        const int mA = m0 + wm + mf * 16 + r0;
        const float* mrow = mask + (size_t)(mA >> 4) * MAXT;
#pragma unroll
        for (int nf = 0; nf < 8; nf++) {
            const int n = n0 + wn + nf * 8 + c0;
            float v0 = acc[mf][nf][0] * scale + mrow[n];
            float v1 = acc[mf][nf][1] * scale + mrow[n + 1];
            float v2 = acc[mf][nf][2] * scale + mrow[n];
            float v3 = acc[mf][nf][3] * scale + mrow[n + 1];
            *(__half2*)&C[(size_t)mA * ldc + n]       = __floats2half2_rn(v0, v1);
            *(__half2*)&C[(size_t)(mA + 8) * ldc + n] = __floats2half2_rn(v2, v3);
        }
    }
}

// ================= merged weight/x conversion (all fp16) =====================
#define C4_X    131072
#define C4_QD   (C4_X + 393216)
#define C4_QU   (C4_QD + 589824)
#define C4_KVD  (C4_QU + 327680)
#define C4_OUT  (C4_KVD + 1048576)
#define C4_WKVU (C4_OUT + 524288)
#define KVD_SRC4 294912
__global__ void conv_all(const float4* __restrict__ x, const float4* __restrict__ wqd,
                         const float4* __restrict__ wqu, const float4* __restrict__ wkvd,
                         const float4* __restrict__ wout, const float4* __restrict__ wkvu) {
    const int i = blockIdx.x * 256 + threadIdx.x;
    if (i < C4_X) {
        half4_write(x[i], g_xf, i);
    } else if (i < C4_QD) {
        const int j = i - C4_X;
        half4_write(wqd[j], g_wqdf, j);
    } else if (i < C4_QU) {
        const int j = i - C4_QD;
        half4_write(wqu[j], g_wquf, j);
    } else if (i < C4_KVD) {
        const int j = i - C4_QU;
        float4 v = (j < KVD_SRC4) ? wkvd[j] : make_float4(0.f, 0.f, 0.f, 0.f);
        half4_write(v, g_wkvdf, j);
    } else if (i < C4_OUT) {
        const int j = i - C4_KVD;
        half4_write(wout[j], g_woutf, j);
    } else if (i < C4_WKVU) {
        const int j = i - C4_OUT;
        half4_write(wkvu[j], g_wvf, j);
    }
}

// transpose nr part of w_kvu -> fp16
__global__ void build_wnrt(const float* __restrict__ wkvu) {
    __shared__ float tile[32][33];
    const int h = blockIdx.z;
    const int n0 = blockIdx.x * 32, d0 = blockIdx.y * 32;
    const int tx = threadIdx.x, ty = threadIdx.y;
#pragma unroll
    for (int i = 0; i < 4; i++) {
        const int d = d0 + ty + i * 8;
        tile[ty + i * 8][tx] = wkvu[(size_t)(h * 256 + d) * KVR + n0 + tx];
    }
    __syncthreads();
#pragma unroll
    for (int i = 0; i < 4; i++) {
        const int n = n0 + ty + i * 8;
        const float v = tile[tx][ty + i * 8];
        g_wnrtf[(size_t)h * KVR * DNR + (size_t)n * DNR + d0 + tx] = __float2half_rn(v);
    }
}

// ====== merged kv builder (VECTORIZED): kc + kt + fused rope =================
// y<16: 32t x 32n tile. 256 threads, each handles one float4.
//   load:  thread (r = tid>>3, q = tid&7) reads float4 at [t0+r, n0+q*4]
//          -> writes uint2 to kc, stores 4 floats to tile[r][q*4..+3]
//   store: thread (n = tid>>3, q = tid&7) reads tile[q*4..+3][n] (pad-33, conflict-free)
//          -> writes uint2 to kt at [n0+n, t0+q*4]
// y==16: rope / krc columns (64), scalar (small fraction).
__global__ void build_kv2(const float* __restrict__ kvc, const float* __restrict__ krc,
                          const float* __restrict__ fc, const float* __restrict__ fs) {
    __shared__ float tile[32][33];
    const int b = blockIdx.z;
    const int t0 = blockIdx.x * 32;
    const int y = blockIdx.y;
    const int tid = threadIdx.x;            // 256 threads (flat)
    if (y < 16) {
        const int n0 = y * 32;
        const int r = tid >> 3, q = tid & 7;
        const int t = t0 + r;
        float4 v;
        if (t >= START_P)
            v = *(const float4*)&g_kv[(size_t)((b << 5) + (t - START_P)) * CATD + n0 + q * 4];
        else
            v = *(const float4*)&kvc[((size_t)b * MAXT + t) * KVR + n0 + q * 4];
        *(uint2*)&g_kc[((size_t)b * MAXT + t) * CATD + n0 + q * 4] = f4_to_h4(v);
        tile[r][q * 4 + 0] = v.x;
        tile[r][q * 4 + 1] = v.y;
        tile[r][q * 4 + 2] = v.z;
        tile[r][q * 4 + 3] = v.w;
        __syncthreads();
        const int n = tid >> 3, tq = (tid & 7) * 4;
        float4 w = make_float4(tile[tq][n], tile[tq + 1][n], tile[tq + 2][n], tile[tq + 3][n]);
        *(uint2*)&g_kt[((size_t)(b * KVR + n0 + n)) * MAXT + t0 + tq] = f4_to_h4(w);
    } else {
        // rope / krc columns c in [KVR, KVR+64): 32t x 64c, 256 threads -> 8 elems/thread
        const int r = tid >> 3, cq = (tid & 7) * 8;   // 8 cols per thread
        const int t = t0 + r;
#pragma unroll
        for (int e = 0; e < 8; e += 2) {
            const int c = KVR + cq + e;
            float v0, v1;
            if (t >= START_P) {
                const int l = t - START_P;
                const int j = (c - KVR) >> 1;
                const size_t base = (size_t)((b << 5) + l) * CATD + KVR + 2 * j;
                const float xr = g_kv[base], xi = g_kv[base + 1];
                const float cth = fc[l * 32 + j], sth = fs[l * 32 + j];
                v0 = xr * cth - xi * sth;
                v1 = xr * sth + xi * cth;
            } else {
                const float2 kk = *(const float2*)&krc[((size_t)b * MAXT + t) * DR + (c - KVR)];
                v0 = kk.x; v1 = kk.y;
            }
            *(__half2*)&g_kc[((size_t)b * MAXT + t) * CATD + c] = __floats2half2_rn(v0, v1);
        }
    }
}

// ================= RMSNorm -> fp16 ===========================================
__global__ void rms_kernel(const float* __restrict__ w) {
    const int row = blockIdx.x;
    const float* xr = g_qd + row * QR;
    __shared__ float red[256];
    const int tid = threadIdx.x;
    float v[3], s = 0.f;
#pragma unroll
    for (int i = 0; i < 3; i++) { v[i] = xr[tid + i * 256]; s += v[i] * v[i]; }
    red[tid] = s; __syncthreads();
    for (int o = 128; o > 0; o >>= 1) {
        if (tid < o) red[tid] += red[tid + o];
        __syncthreads();
    }
    const float r = rsqrtf(red[0] / (float)QR + 1.1920929e-07f);
    __syncthreads();
#pragma unroll
    for (int i = 0; i < 3; i++) {
        const float y = v[i] * r * w[tid + i * 256];
        g_qnf[(size_t)row * QR + tid + i * 256] = __float2half_rn(y);
    }
}

// ====== fused q conversion + rope-q ==========================================
#define CQ_N1 (MBL * NH * QKD / 4)
#define CQ_N2 (BATCH * SEQ_L * NH * 32)
__global__ void conv_q(const float* __restrict__ fc, const float* __restrict__ fs) {
    const int idx = blockIdx.x * 256 + threadIdx.x;
    if (idx < CQ_N1) {
        half4_write(((const float4*)g_q)[idx], g_qf, idx);
    } else if (idx < CQ_N1 + CQ_N2) {
        const int k = idx - CQ_N1;
        const int j = k & 31, h = (k >> 5) & 15, l = (k >> 9) & 31, b = k >> 14;
        const size_t si = (size_t)(b * SEQ_L + l) * (NH * QKD) + h * QKD + DNR + 2 * j;
        const float xr = g_q[si], xi = g_q[si + 1];
        const float c = fc[l * 32 + j], s = fs[l * 32 + j];
        const size_t o = (size_t)(b * ROWSPB + l * NH + h) * CATD + KVR + 2 * j;
        *(__half2*)&g_qc[o] = __floats2half2_rn(xr * c - xi * s, xr * s + xi * c);
    }
}

// ================= softmax (fp16 in) -> fp16 P ===============================
__global__ void softmax_split() {
    const int row = blockIdx.x;
    const __half* srow = g_S16 + (size_t)row * MAXT;
    __shared__ float red[256];
    const int tid = threadIdx.x;
    float4 v[4];
    float mx = -INFINITY;
#pragma unroll
    for (int g = 0; g < 4; g++) {
        uint2 r = *(const uint2*)&srow[tid * 4 + g * 1024];
        float2 fa = __half22float2(*(__half2*)&r.x);
        float2 fb = __half22float2(*(__half2*)&r.y);
        v[g] = make_float4(fa.x, fa.y, fb.x, fb.y);
        mx = fmaxf(mx, fmaxf(fmaxf(v[g].x, v[g].y), fmaxf(v[g].z, v[g].w)));
    }
    red[tid] = mx; __syncthreads();
    for (int o = 128; o > 0; o >>= 1) {
        if (tid < o) red[tid] = fmaxf(red[tid], red[tid + o]);
        __syncthreads();
    }
    mx = red[0]; __syncthreads();
    float sum = 0.f;
#pragma unroll
    for (int g = 0; g < 4; g++) {
        v[g].x = __expf(v[g].x - mx); v[g].y = __expf(v[g].y - mx);
        v[g].z = __expf(v[g].z - mx); v[g].w = __expf(v[g].w - mx);
        sum += v[g].x + v[g].y + v[g].z + v[g].w;
    }
    red[tid] = sum; __syncthreads();
    for (int o = 128; o > 0; o >>= 1) {
        if (tid < o) red[tid] += red[tid + o];
        __syncthreads();
    }
    const float inv = 1.f / red[0];
#pragma unroll
    for (int g = 0; g < 4; g++) {
        float4 p = make_float4(v[g].x * inv, v[g].y * inv, v[g].z * inv, v[g].w * inv);
        half4_write(p, g_p, ((size_t)row * MAXT + tid * 4 + g * 1024) >> 2);
    }
}

// ============================== launcher =====================================
extern "C" void kernel_launch(void* const* d_in, const int* in_sizes, int n_in,
                              void* d_out, int out_size) {
    const float* x      = (const float*)d_in[0];
    const float* fc     = (const float*)d_in[2];
    const float* fs     = (const float*)d_in[3];
    const float* mask   = (const float*)d_in[4];
    const float* kvc    = (const float*)d_in[5];
    const float* krc    = (const float*)d_in[6];
    const float* w_kvd  = (const float*)d_in[7];
    const float* w_qd   = (const float*)d_in[8];
    const float* rms_w  = (const float*)d_in[9];
    const float* w_qu   = (const float*)d_in[10];
    const float* w_kvu  = (const float*)d_in[11];
    const float* w_out  = (const float*)d_in[12];
    float* out = (float*)d_out;

    float *p_qd, *p_q, *p_kv;
    cudaGetSymbolAddress((void**)&p_qd, g_qd);
    cudaGetSymbolAddress((void**)&p_q,  g_q);
    cudaGetSymbolAddress((void**)&p_kv, g_kv);

    __half *qc, *kc, *kt, *pp, *S16, *xf, *qnf, *Of, *o2f;
    __half *wqdf, *wquf, *wkvdf, *woutf;
    cudaGetSymbolAddress((void**)&qc, g_qc);
    cudaGetSymbolAddress((void**)&kc, g_kc);
    cudaGetSymbolAddress((void**)&kt, g_kt);
    cudaGetSymbolAddress((void**)&pp, g_p);
    cudaGetSymbolAddress((void**)&S16, g_S16);
    cudaGetSymbolAddress((void**)&xf, g_xf);
    cudaGetSymbolAddress((void**)&qnf, g_qnf);
    cudaGetSymbolAddress((void**)&Of, g_Of);
    cudaGetSymbolAddress((void**)&o2f, g_o2f);
    cudaGetSymbolAddress((void**)&wqdf, g_wqdf);
    cudaGetSymbolAddress((void**)&wquf, g_wquf);
    cudaGetSymbolAddress((void**)&wkvdf, g_wkvdf);
    cudaGetSymbolAddress((void**)&woutf, g_woutf);

    static cudaStream_t s_kv = nullptr;
    static cudaEvent_t ev_fork = nullptr, ev_join = nullptr;
    if (!s_kv) {
        cudaStreamCreateWithFlags(&s_kv, cudaStreamNonBlocking);
        cudaEventCreateWithFlags(&ev_fork, cudaEventDisableTiming);
        cudaEventCreateWithFlags(&ev_join, cudaEventDisableTiming);
        cudaFuncSetAttribute(gemm_f16_sk, cudaFuncAttributeMaxDynamicSharedMemorySize, 3 * OF_STAGE);
        cudaFuncSetAttribute(qabs_f16, cudaFuncAttributeMaxDynamicSharedMemorySize, 2 * OF_STAGE);
        cudaFuncSetAttribute(oup_f16, cudaFuncAttributeMaxDynamicSharedMemorySize, 3 * OF_STAGE);
        cudaFuncSetAttribute(scores_f16, cudaFuncAttributeMaxDynamicSharedMemorySize, 3 * SF_STAGE);
        cudaFuncSetAttribute(ogemm_f16, cudaFuncAttributeMaxDynamicSharedMemorySize, 3 * OF_STAGE);
    }

    // ---- root: memsets + conversions ----
    cudaMemsetAsync(p_qd, 0, (size_t)MBL * QR * 4);
    cudaMemsetAsync(p_q, 0, (size_t)MBL * NH * QKD * 4);
    cudaMemsetAsync(p_kv, 0, (size_t)MBL * CATD * 4);
    cudaMemsetAsync(out, 0, (size_t)MBL * DIM * 4);
    conv_all<<<C4_WKVU / 256, 256>>>((const float4*)x, (const float4*)w_qd, (const float4*)w_qu,
                                     (const float4*)w_kvd, (const float4*)w_out, (const float4*)w_kvu);
    build_wnrt<<<dim3(KVR / 32, DNR / 32, NH), dim3(32, 8)>>>(w_kvu);

    // ---- fork: kv-path on s_kv, q-path on default ----
    cudaEventRecord(ev_fork, 0);
    cudaStreamWaitEvent(s_kv, ev_fork, 0);

    // kv path
    gemm_f16_sk<<<dim3(KVD_PAD / 128, MBL / 128, 8), 256, 3 * OF_STAGE, s_kv>>>(
        xf, wkvdf, p_kv, CATD, DIM, DIM / 8, CATD);
    build_kv2<<<dim3(MAXT / 32, 17, BATCH), 256, 0, s_kv>>>(kvc, krc, fc, fs);
    cudaEventRecord(ev_join, s_kv);

    // q path
    gemm_f16_sk<<<dim3(QR / 128, MBL / 128, 8), 256, 3 * OF_STAGE>>>(
        xf, wqdf, p_qd, QR, DIM, DIM / 8, QR);
    rms_kernel<<<MBL, 256>>>(rms_w);
    gemm_f16_sk<<<dim3(NH * QKD / 128, MBL / 128, 4), 256, 3 * OF_STAGE>>>(
        qnf, wquf, p_q, NH * QKD, QR, QR / 4, NH * QKD);
    conv_q<<<(CQ_N1 + CQ_N2 + 255) / 256, 256>>>(fc, fs);
    qabs_f16<<<dim3(KVR / 128, MBL / 128, NH), 256, 2 * OF_STAGE>>>();

    // ---- join q/kv ----
    cudaStreamWaitEvent(0, ev_join, 0);

    // ---- attention ----
    scores_f16<<<dim3(MAXT / 256, ROWSPB / 128, BATCH), 256, 3 * SF_STAGE>>>(
        qc, (size_t)ROWSPB * CATD, kc, (size_t)MAXT * CATD,
        S16, MAXT, (size_t)ROWSPB * MAXT, CATD, mask, SCALE_F);
    softmax_split<<<BATCH * ROWSPB, 256>>>();
    ogemm_f16<<<dim3(KVR / 128, ROWSPB / 128, BATCH), 256, 3 * OF_STAGE>>>(
        pp, (size_t)ROWSPB * MAXT, kt, (size_t)KVR * MAXT,
        Of, KVR, (size_t)ROWSPB * KVR, MAXT);

    // ---- output path ----
    oup_f16<<<dim3(1, MBL / 128, NH), 256, 3 * OF_STAGE>>>();
    gemm_f16_sk<<<dim3(DIM / 128, MBL / 128, 8), 256, 3 * OF_STAGE>>>(
        o2f, woutf, out, DIM, NH * DV, NH * DV / 8, DIM);
}

// round 17
// speedup vs baseline: 1.9106x; 1.0126x over previous
#include <cuda_runtime.h>
#include <cuda_fp16.h>
#include <math.h>
#include <stdint.h>

// ---------------- problem constants -----------------------------------------
#define BATCH   8
#define SEQ_L   32
#define DIM     2048
#define KVR     512
#define QR      768
#define NH      16
#define DNR     128
#define DR      64
#define DV      128
#define MAXT    4096
#define START_P 4064
#define QKD     192
#define CATD    576
#define MBL     256
#define ROWSPB  512
#define SCALE_F 0.07216878364870323f
#define KVD_PAD 640
#define DPAD    1408          // QR + KVD_PAD (combined down-proj width)

// ---------------- fp32 scratch ----------------------------------------------
__device__ __align__(16) float g_qkv [MBL * DPAD];   // [q | kv] combined
__device__ __align__(16) float g_q   [MBL * NH * QKD];
// ---------------- fp16 operands ----------------------------------------------
__device__ __align__(16) __half g_S16[(size_t)BATCH * ROWSPB * MAXT];
__device__ __align__(16) __half g_qc [BATCH * ROWSPB * CATD];
__device__ __align__(16) __half g_kc [(size_t)BATCH * MAXT * CATD];
__device__ __align__(16) __half g_kt [(size_t)BATCH * KVR * MAXT];
__device__ __align__(16) __half g_p  [(size_t)BATCH * ROWSPB * MAXT];
__device__ __align__(16) __half g_Of [BATCH * ROWSPB * KVR];
__device__ __align__(16) __half g_o2f[MBL * NH * DV];
__device__ __align__(16) __half g_xf [MBL * DIM];
__device__ __align__(16) __half g_qnf[MBL * QR];
__device__ __align__(16) __half g_qf [MBL * NH * QKD];
__device__ __align__(16) __half g_wdf  [DPAD * DIM];      // [w_qd rows | w_kvd rows]
__device__ __align__(16) __half g_wquf [NH * QKD * QR];
__device__ __align__(16) __half g_woutf[DIM * NH * DV];
__device__ __align__(16) __half g_wvf  [NH * 256 * KVR];
__device__ __align__(16) __half g_wnrtf[NH * KVR * DNR];

// ================= helpers ===================================================
__device__ __forceinline__ uint32_t smem_u32(const void* p) {
    uint32_t a;
    asm("{ .reg .u64 t; cvta.to.shared.u64 t, %1; cvt.u32.u64 %0, t; }" : "=r"(a) : "l"(p));
    return a;
}
__device__ __forceinline__ uint32_t sw128(uint32_t o) { return o ^ ((o >> 3) & 0x70); }
__device__ __forceinline__ void cpa16(uint32_t saddr, const void* g) {
    asm volatile("cp.async.cg.shared.global [%0], [%1], 16;" :: "r"(saddr), "l"(g));
}
__device__ __forceinline__ void cpa_commit() { asm volatile("cp.async.commit_group;" ::: "memory"); }
__device__ __forceinline__ void cpa_wait2()  { asm volatile("cp.async.wait_group 2;" ::: "memory"); }
__device__ __forceinline__ void cpa_wait1()  { asm volatile("cp.async.wait_group 1;" ::: "memory"); }
__device__ __forceinline__ void cpa_wait0()  { asm volatile("cp.async.wait_group 0;" ::: "memory"); }
__device__ __forceinline__ void ldm_x4(uint32_t* r, uint32_t addr) {
    asm volatile("ldmatrix.sync.aligned.m8n8.x4.shared.b16 {%0,%1,%2,%3}, [%4];"
                 : "=r"(r[0]), "=r"(r[1]), "=r"(r[2]), "=r"(r[3]) : "r"(addr));
}
__device__ __forceinline__ void mma_f16(float* c, const uint32_t* a, const uint32_t* b) {
    asm volatile("mma.sync.aligned.m16n8k16.row.col.f32.f16.f16.f32 "
                 "{%0,%1,%2,%3}, {%4,%5,%6,%7}, {%8,%9}, {%0,%1,%2,%3};"
                 : "+f"(c[0]), "+f"(c[1]), "+f"(c[2]), "+f"(c[3])
                 : "r"(a[0]), "r"(a[1]), "r"(a[2]), "r"(a[3]), "r"(b[0]), "r"(b[1]));
}
__device__ __forceinline__ void half4_write(float4 v, __half* dst, size_t i4) {
    __half2 a = __floats2half2_rn(v.x, v.y);
    __half2 b = __floats2half2_rn(v.z, v.w);
    *(uint2*)&dst[i4 * 4] = make_uint2(*(uint32_t*)&a, *(uint32_t*)&b);
}
__device__ __forceinline__ uint2 f4_to_h4(float4 v) {
    __half2 a = __floats2half2_rn(v.x, v.y);
    __half2 b = __floats2half2_rn(v.z, v.w);
    return make_uint2(*(uint32_t*)&a, *(uint32_t*)&b);
}

#define OF_STAGE 32768   // fp16 128x128: A 16KB @0, B 16KB @16384
#define SF_STAGE 49152   // fp16 128x256: A 16KB @0, B 32KB @16384

// ======== fp16 128x128 single-term mainloop (one row / thread loader) ========
#define F16_PREFETCH(STAGE, CH)                                                      \
    {                                                                                \
        const uint32_t sb = smem32 + (uint32_t)(STAGE) * OF_STAGE;                   \
        _Pragma("unroll") for (int i = 0; i < 8; i++)                                \
            cpa16(sb + soff[i], src + (CH) * 64 + i * 8);                            \
        cpa_commit();                                                                \
    }

#define F16_MAINLOOP(NCH)                                                            \
    {                                                                                \
        const int pre = ((NCH) < 2) ? (NCH) : 2;                                     \
        for (int s = 0; s < pre; s++) F16_PREFETCH(s, s)                             \
    }                                                                                \
    for (int c = 0; c < (NCH); c++) {                                                \
        if (c + 2 < (NCH)) {                                                         \
            F16_PREFETCH((c + 2) % 3, c + 2)                                         \
            cpa_wait2();                                                             \
        } else if (c + 1 < (NCH)) {                                                  \
            cpa_wait1();                                                             \
        } else {                                                                     \
            cpa_wait0();                                                             \
        }                                                                            \
        __syncthreads();                                                             \
        const uint32_t st = smem32 + (uint32_t)(c % 3) * OF_STAGE;                   \
        const uint32_t A32 = st, B32 = st + 16384;                                   \
        _Pragma("unroll") for (int ks = 0; ks < 4; ks++) {                           \
            const uint32_t kofs = ks * 32u + qsel * 16u;                             \
            uint32_t a[4][4];                                                        \
            _Pragma("unroll") for (int mf = 0; mf < 4; mf++) {                       \
                int row = wm + mf * 16 + qrow;                                       \
                ldm_x4(a[mf], A32 + sw128((uint32_t)row * 128u + kofs));             \
            }                                                                        \
            uint32_t b[4][2];                                                        \
            _Pragma("unroll") for (int nh = 0; nh < 2; nh++) {                       \
                int row = wn + nh * 16 + qrow;                                       \
                uint32_t t[4];                                                       \
                ldm_x4(t, B32 + sw128((uint32_t)row * 128u + kofs));                 \
                b[nh * 2 + 0][0] = t[0]; b[nh * 2 + 0][1] = t[2];                    \
                b[nh * 2 + 1][0] = t[1]; b[nh * 2 + 1][1] = t[3];                    \
            }                                                                        \
            _Pragma("unroll") for (int mf = 0; mf < 4; mf++)                         \
                _Pragma("unroll") for (int nf = 0; nf < 4; nf++)                     \
                    mma_f16(acc[mf][nf], a[mf], b[nf]);                              \
        }                                                                            \
        __syncthreads();                                                             \
    }

#define F16_DECL                                                                     \
    const int tid = threadIdx.x;                                                     \
    const int warp = tid >> 5, lane = tid & 31;                                      \
    const int wm = (warp >> 2) * 64, wn = (warp & 3) * 32;                           \
    const uint32_t smem32 = smem_u32(smem);                                          \
    const int qrow = lane & 15, qsel = lane >> 4;                                    \
    const bool isB = tid >= 128;                                                     \
    const int lrow = tid & 127;                                                      \
    uint32_t soff[8];                                                                \
    _Pragma("unroll") for (int i = 0; i < 8; i++)                                    \
        soff[i] = (isB ? 16384u : 0u) + sw128((uint32_t)lrow * 128u + i * 16u);      \
    float acc[4][4][4];                                                              \
    _Pragma("unroll") for (int i = 0; i < 4; i++)                                    \
        _Pragma("unroll") for (int j = 0; j < 4; j++)                                \
            _Pragma("unroll") for (int r = 0; r < 4; r++) acc[i][j][r] = 0.f;

// ====== fp16 split-K GEMM (down-proj, qu, out-proj): fp32 atomicAdd ==========
__global__ void __launch_bounds__(256)
gemm_f16_sk(const __half* __restrict__ A, const __half* __restrict__ B,
            float* __restrict__ C, int ldc, int K, int kpart, int N)
{
    extern __shared__ char smem[];
    const int m0 = blockIdx.y * 128, n0 = blockIdx.x * 128;
    const int kb = blockIdx.z * kpart;
    F16_DECL
    const __half* src = isB ? (B + (size_t)(n0 + lrow) * K + kb)
                            : (A + (size_t)(m0 + lrow) * K + kb);
    const int nch = kpart >> 6;
    F16_MAINLOOP(nch)
    const int r0 = lane >> 2, c0 = (lane & 3) * 2;
#pragma unroll
    for (int mf = 0; mf < 4; mf++) {
        const int mA = m0 + wm + mf * 16 + r0;
#pragma unroll
        for (int nf = 0; nf < 4; nf++) {
            const int n = n0 + wn + nf * 8 + c0;
            if (n < N) {
                atomicAdd(&C[(size_t)mA * ldc + n],           acc[mf][nf][0]);
                atomicAdd(&C[(size_t)mA * ldc + n + 1],       acc[mf][nf][1]);
                atomicAdd(&C[(size_t)(mA + 8) * ldc + n],     acc[mf][nf][2]);
                atomicAdd(&C[(size_t)(mA + 8) * ldc + n + 1], acc[mf][nf][3]);
            }
        }
    }
}

// ====== qabs fp16: per-head q_nrope @ w_nr^T -> fp16 qcat ====================
__global__ void __launch_bounds__(256)
qabs_f16()
{
    extern __shared__ char smem[];
    const int h = blockIdx.z;
    const int m0 = blockIdx.y * 128, n0 = blockIdx.x * 128;
    F16_DECL
    const __half* src = isB ? (g_wnrtf + (size_t)h * KVR * DNR + (size_t)(n0 + lrow) * DNR)
                            : (g_qf + (size_t)(m0 + lrow) * (NH * QKD) + h * QKD);
    F16_MAINLOOP(2)
    const int r0 = lane >> 2, c0 = (lane & 3) * 2;
#pragma unroll
    for (int mf = 0; mf < 4; mf++) {
        const int mA = m0 + wm + mf * 16 + r0;
        const int rowA = ((mA >> 5) * ROWSPB) + (mA & 31) * NH + h;
        const int rowB = (((mA + 8) >> 5) * ROWSPB) + ((mA + 8) & 31) * NH + h;
#pragma unroll
        for (int nf = 0; nf < 4; nf++) {
            const int n = n0 + wn + nf * 8 + c0;
            *(__half2*)&g_qc[(size_t)rowA * CATD + n] = __floats2half2_rn(acc[mf][nf][0], acc[mf][nf][1]);
            *(__half2*)&g_qc[(size_t)rowB * CATD + n] = __floats2half2_rn(acc[mf][nf][2], acc[mf][nf][3]);
        }
    }
}

// ====== ogemm fp16: O = P*KV^T -> fp16 O =====================================
__global__ void __launch_bounds__(256)
ogemm_f16(const __half* __restrict__ P, size_t sPz,
          const __half* __restrict__ Kt, size_t sKz,
          __half* __restrict__ C, int ldc, size_t sCz, int K)
{
    extern __shared__ char smem[];
    const int z = blockIdx.z;
    const int m0 = blockIdx.y * 128, n0 = blockIdx.x * 128;
    P += (size_t)z * sPz;  Kt += (size_t)z * sKz;  C += (size_t)z * sCz;
    F16_DECL
    const __half* src = isB ? (Kt + (size_t)(n0 + lrow) * K)
                            : (P + (size_t)(m0 + lrow) * K);
    const int nch = K >> 6;
    F16_MAINLOOP(nch)
    const int r0 = lane >> 2, c0 = (lane & 3) * 2;
#pragma unroll
    for (int mf = 0; mf < 4; mf++) {
        const int mA = m0 + wm + mf * 16 + r0;
#pragma unroll
        for (int nf = 0; nf < 4; nf++) {
            const int n = n0 + wn + nf * 8 + c0;
            *(__half2*)&C[(size_t)mA * ldc + n]       = __floats2half2_rn(acc[mf][nf][0], acc[mf][nf][1]);
            *(__half2*)&C[(size_t)(mA + 8) * ldc + n] = __floats2half2_rn(acc[mf][nf][2], acc[mf][nf][3]);
        }
    }
}

// ====== oup fp16 (2-way split-K): per-head O @ w_v^T -> half2 atomics ========
__global__ void __launch_bounds__(256)
oup_f16()
{
    extern __shared__ char smem[];
    const int h = blockIdx.z;
    const int m0 = blockIdx.y * 128, n0 = 0;
    const int kb = blockIdx.x * 256;        // 2-way split over KVR
    F16_DECL
    const int mrow = m0 + lrow;
    const int arow = (mrow >> 5) * ROWSPB + (mrow & 31) * NH + h;
    const __half* src = isB ? (g_wvf + (size_t)(h * 256 + DNR + n0 + lrow) * KVR + kb)
                            : (g_Of + (size_t)arow * KVR + kb);
    F16_MAINLOOP(4)
    const int r0 = lane >> 2, c0 = (lane & 3) * 2;
#pragma unroll
    for (int mf = 0; mf < 4; mf++) {
        const int mA = m0 + wm + mf * 16 + r0;
#pragma unroll
        for (int nf = 0; nf < 4; nf++) {
            const int n = n0 + wn + nf * 8 + c0;
            const size_t i0 = (size_t)mA * (NH * DV) + h * DV + n;
            const size_t i1 = (size_t)(mA + 8) * (NH * DV) + h * DV + n;
            atomicAdd((__half2*)&g_o2f[i0], __floats2half2_rn(acc[mf][nf][0], acc[mf][nf][1]));
            atomicAdd((__half2*)&g_o2f[i1], __floats2half2_rn(acc[mf][nf][2], acc[mf][nf][3]));
        }
    }
}

// ====== fp16 scores 128x256 tile, 3-stage pipeline, fp16 S output ============
__global__ void __launch_bounds__(256)
scores_f16(const __half* __restrict__ Q, size_t sQz,
           const __half* __restrict__ Kc, size_t sKz,
           __half* __restrict__ C, int ldc, size_t sCz,
           int K, const float* __restrict__ mask, float scale)
{
    extern __shared__ char smem[];
    const int z = blockIdx.z;
    const int m0 = blockIdx.y * 128, n0 = blockIdx.x * 256;
    Q += (size_t)z * sQz;  Kc += (size_t)z * sKz;  C += (size_t)z * sCz;

    const int tid = threadIdx.x;
    const int warp = tid >> 5, lane = tid & 31;
    const int wm = (warp >> 2) * 64, wn = (warp & 3) * 64;
    const uint32_t smem32 = smem_u32(smem);
    const int qrow = lane & 15, qsel = lane >> 4;

    const __half* gsrc[3];
    uint32_t swb[3];
#pragma unroll
    for (int j = 0; j < 3; j++) {
        const int h = tid + j * 256;
        const int half = h & 1;
        int r;
        uint32_t tbase;
        const __half* base;
        if (h < 256) { r = h >> 1; tbase = 0u; base = Q + (size_t)(m0 + r) * K; }
        else { r = (h - 256) >> 1; tbase = 16384u; base = Kc + (size_t)(n0 + r) * K; }
        swb[j] = tbase + sw128((uint32_t)r * 128u + half * 64u);
        gsrc[j] = base + half * 32;
    }

    float acc[4][8][4];
#pragma unroll
    for (int i = 0; i < 4; i++)
#pragma unroll
        for (int j = 0; j < 8; j++)
#pragma unroll
            for (int r = 0; r < 4; r++) acc[i][j][r] = 0.f;

    const int nch = K >> 6;
#define SC_PREFETCH(STAGE, CH)                                                       \
    {                                                                                \
        const uint32_t sb = smem32 + (uint32_t)(STAGE) * SF_STAGE;                   \
        _Pragma("unroll") for (int j = 0; j < 3; j++)                                \
            _Pragma("unroll") for (int i = 0; i < 4; i++)                            \
                cpa16(sb + (swb[j] ^ (i * 16u)), gsrc[j] + (CH) * 64 + i * 8);       \
        cpa_commit();                                                                \
    }
    {
        const int pre = (nch < 2) ? nch : 2;
        for (int s = 0; s < pre; s++) SC_PREFETCH(s, s)
    }
    for (int c = 0; c < nch; c++) {
        if (c + 2 < nch) {
            SC_PREFETCH((c + 2) % 3, c + 2)
            cpa_wait2();
        } else if (c + 1 < nch) {
            cpa_wait1();
        } else {
            cpa_wait0();
        }
        __syncthreads();

        const uint32_t st = smem32 + (uint32_t)(c % 3) * SF_STAGE;
        const uint32_t A32 = st, B32 = st + 16384;
#pragma unroll
        for (int ks = 0; ks < 4; ks++) {
            const uint32_t kofs = ks * 32u + qsel * 16u;
            uint32_t a[4][4];
#pragma unroll
            for (int mf = 0; mf < 4; mf++) {
                int row = wm + mf * 16 + qrow;
                ldm_x4(a[mf], A32 + sw128((uint32_t)row * 128u + kofs));
            }
            uint32_t b[8][2];
#pragma unroll
            for (int nh = 0; nh < 4; nh++) {
                int row = wn + nh * 16 + qrow;
                uint32_t t[4];
                ldm_x4(t, B32 + sw128((uint32_t)row * 128u + kofs));
                b[nh * 2 + 0][0] = t[0]; b[nh * 2 + 0][1] = t[2];
                b[nh * 2 + 1][0] = t[1]; b[nh * 2 + 1][1] = t[3];
            }
#pragma unroll
            for (int mf = 0; mf < 4; mf++)
#pragma unroll
                for (int nf = 0; nf < 8; nf++)
                    mma_f16(acc[mf][nf], a[mf], b[nf]);
        }
        __syncthreads();
    }

    const int r0 = lane >> 2, c0 = (lane & 3) * 2;
#pragma unroll
    for (int mf = 0; mf < 4; mf++) {
        const int mA = m0 + wm + mf * 16 + r0;
        const float* mrow = mask + (size_t)(mA >> 4) * MAXT;
#pragma unroll
        for (int nf = 0; nf < 8; nf++) {
            const int n = n0 + wn + nf * 8 + c0;
            float v0 = acc[mf][nf][0] * scale + mrow[n];
            float v1 = acc[mf][nf][1] * scale + mrow[n + 1];
            float v2 = acc[mf][nf][2] * scale + mrow[n];
            float v3 = acc[mf][nf][3] * scale + mrow[n + 1];
            *(__half2*)&C[(size_t)mA * ldc + n]       = __floats2half2_rn(v0, v1);
            *(__half2*)&C[(size_t)(mA + 8) * ldc + n] = __floats2half2_rn(v2, v3);
        }
    }
}

// ============ merged weight/x conversion (CORRECT segment table) =============
// quads: x 131072 | wqd 393216 | wqu 589824 | wkvd(pad) 327680 | wout 1048576 | wkvu 524288
#define C4_X     131072
#define C4_WQD   (C4_X + 393216)      // 524288
#define C4_QU    (C4_WQD + 589824)    // 1114112
#define C4_WKVD  (C4_QU + 327680)     // 1441792
#define C4_OUT   (C4_WKVD + 1048576)  // 2490368
#define C4_WKVU  (C4_OUT + 524288)    // 3014656
#define KVD_SRC4 294912
#define WDF_KV_OFF 393216   // quad offset of kvd rows inside g_wdf
__global__ void conv_all(const float4* __restrict__ x, const float4* __restrict__ wqd,
                         const float4* __restrict__ wqu, const float4* __restrict__ wkvd,
                         const float4* __restrict__ wout, const float4* __restrict__ wkvu) {
    const int i = blockIdx.x * 256 + threadIdx.x;
    if (i < C4_X) {
        half4_write(x[i], g_xf, i);
    } else if (i < C4_WQD) {
        const int j = i - C4_X;
        half4_write(wqd[j], g_wdf, j);
    } else if (i < C4_QU) {
        const int j = i - C4_WQD;
        half4_write(wqu[j], g_wquf, j);
    } else if (i < C4_WKVD) {
        const int j = i - C4_QU;
        float4 v = (j < KVD_SRC4) ? wkvd[j] : make_float4(0.f, 0.f, 0.f, 0.f);
        half4_write(v, g_wdf, WDF_KV_OFF + j);
    } else if (i < C4_OUT) {
        const int j = i - C4_WKVD;
        half4_write(wout[j], g_woutf, j);
    } else if (i < C4_WKVU) {
        const int j = i - C4_OUT;
        half4_write(wkvu[j], g_wvf, j);
    }
}

// transpose nr part of w_kvu -> fp16
__global__ void build_wnrt(const float* __restrict__ wkvu) {
    __shared__ float tile[32][33];
    const int h = blockIdx.z;
    const int n0 = blockIdx.x * 32, d0 = blockIdx.y * 32;
    const int tx = threadIdx.x, ty = threadIdx.y;
#pragma unroll
    for (int i = 0; i < 4; i++) {
        const int d = d0 + ty + i * 8;
        tile[ty + i * 8][tx] = wkvu[(size_t)(h * 256 + d) * KVR + n0 + tx];
    }
    __syncthreads();
#pragma unroll
    for (int i = 0; i < 4; i++) {
        const int n = n0 + ty + i * 8;
        const float v = tile[tx][ty + i * 8];
        g_wnrtf[(size_t)h * KVR * DNR + (size_t)n * DNR + d0 + tx] = __float2half_rn(v);
    }
}

// ====== merged kv builder (vectorized): kc + kt + fused rope =================
__global__ void build_kv2(const float* __restrict__ kvc, const float* __restrict__ krc,
                          const float* __restrict__ fc, const float* __restrict__ fs) {
    __shared__ float tile[32][33];
    const int b = blockIdx.z;
    const int t0 = blockIdx.x * 32;
    const int y = blockIdx.y;
    const int tid = threadIdx.x;
    if (y < 16) {
        const int n0 = y * 32;
        const int r = tid >> 3, q = tid & 7;
        const int t = t0 + r;
        float4 v;
        if (t >= START_P)
            v = *(const float4*)&g_qkv[(size_t)((b << 5) + (t - START_P)) * DPAD + QR + n0 + q * 4];
        else
            v = *(const float4*)&kvc[((size_t)b * MAXT + t) * KVR + n0 + q * 4];
        *(uint2*)&g_kc[((size_t)b * MAXT + t) * CATD + n0 + q * 4] = f4_to_h4(v);
        tile[r][q * 4 + 0] = v.x;
        tile[r][q * 4 + 1] = v.y;
        tile[r][q * 4 + 2] = v.z;
        tile[r][q * 4 + 3] = v.w;
        __syncthreads();
        const int n = tid >> 3, tq = (tid & 7) * 4;
        float4 w = make_float4(tile[tq][n], tile[tq + 1][n], tile[tq + 2][n], tile[tq + 3][n]);
        *(uint2*)&g_kt[((size_t)(b * KVR + n0 + n)) * MAXT + t0 + tq] = f4_to_h4(w);
    } else {
        const int r = tid >> 3, cq = (tid & 7) * 8;
        const int t = t0 + r;
#pragma unroll
        for (int e = 0; e < 8; e += 2) {
            const int c = KVR + cq + e;
            float v0, v1;
            if (t >= START_P) {
                const int l = t - START_P;
                const int j = (c - KVR) >> 1;
                const size_t base = (size_t)((b << 5) + l) * DPAD + QR + KVR + 2 * j;
                const float xr = g_qkv[base], xi = g_qkv[base + 1];
                const float cth = fc[l * 32 + j], sth = fs[l * 32 + j];
                v0 = xr * cth - xi * sth;
                v1 = xr * sth + xi * cth;
            } else {
                const float2 kk = *(const float2*)&krc[((size_t)b * MAXT + t) * DR + (c - KVR)];
                v0 = kk.x; v1 = kk.y;
            }
            *(__half2*)&g_kc[((size_t)b * MAXT + t) * CATD + c] = __floats2half2_rn(v0, v1);
        }
    }
}

// ================= RMSNorm (reads combined qkv) -> fp16 ======================
__global__ void rms_kernel(const float* __restrict__ w) {
    const int row = blockIdx.x;
    const float* xr = g_qkv + (size_t)row * DPAD;
    __shared__ float red[256];
    const int tid = threadIdx.x;
    float v[3], s = 0.f;
#pragma unroll
    for (int i = 0; i < 3; i++) { v[i] = xr[tid + i * 256]; s += v[i] * v[i]; }
    red[tid] = s; __syncthreads();
    for (int o = 128; o > 0; o >>= 1) {
        if (tid < o) red[tid] += red[tid + o];
        __syncthreads();
    }
    const float r = rsqrtf(red[0] / (float)QR + 1.1920929e-07f);
    __syncthreads();
#pragma unroll
    for (int i = 0; i < 3; i++) {
        const float y = v[i] * r * w[tid + i * 256];
        g_qnf[(size_t)row * QR + tid + i * 256] = __float2half_rn(y);
    }
}

// ====== fused q conversion + rope-q ==========================================
#define CQ_N1 (MBL * NH * QKD / 4)
#define CQ_N2 (BATCH * SEQ_L * NH * 32)
__global__ void conv_q(const float* __restrict__ fc, const float* __restrict__ fs) {
    const int idx = blockIdx.x * 256 + threadIdx.x;
    if (idx < CQ_N1) {
        half4_write(((const float4*)g_q)[idx], g_qf, idx);
    } else if (idx < CQ_N1 + CQ_N2) {
        const int k = idx - CQ_N1;
        const int j = k & 31, h = (k >> 5) & 15, l = (k >> 9) & 31, b = k >> 14;
        const size_t si = (size_t)(b * SEQ_L + l) * (NH * QKD) + h * QKD + DNR + 2 * j;
        const float xr = g_q[si], xi = g_q[si + 1];
        const float c = fc[l * 32 + j], s = fs[l * 32 + j];
        const size_t o = (size_t)(b * ROWSPB + l * NH + h) * CATD + KVR + 2 * j;
        *(__half2*)&g_qc[o] = __floats2half2_rn(xr * c - xi * s, xr * s + xi * c);
    }
}

// ================= softmax (fp16 in) -> fp16 P ===============================
__global__ void softmax_split() {
    const int row = blockIdx.x;
    const __half* srow = g_S16 + (size_t)row * MAXT;
    __shared__ float red[256];
    const int tid = threadIdx.x;
    float4 v[4];
    float mx = -INFINITY;
#pragma unroll
    for (int g = 0; g < 4; g++) {
        uint2 r = *(const uint2*)&srow[tid * 4 + g * 1024];
        float2 fa = __half22float2(*(__half2*)&r.x);
        float2 fb = __half22float2(*(__half2*)&r.y);
        v[g] = make_float4(fa.x, fa.y, fb.x, fb.y);
        mx = fmaxf(mx, fmaxf(fmaxf(v[g].x, v[g].y), fmaxf(v[g].z, v[g].w)));
    }
    red[tid] = mx; __syncthreads();
    for (int o = 128; o > 0; o >>= 1) {
        if (tid < o) red[tid] = fmaxf(red[tid], red[tid + o]);
        __syncthreads();
    }
    mx = red[0]; __syncthreads();
    float sum = 0.f;
#pragma unroll
    for (int g = 0; g < 4; g++) {
        v[g].x = __expf(v[g].x - mx); v[g].y = __expf(v[g].y - mx);
        v[g].z = __expf(v[g].z - mx); v[g].w = __expf(v[g].w - mx);
        sum += v[g].x + v[g].y + v[g].z + v[g].w;
    }
    red[tid] = sum; __syncthreads();
    for (int o = 128; o > 0; o >>= 1) {
        if (tid < o) red[tid] += red[tid + o];
        __syncthreads();
    }
    const float inv = 1.f / red[0];
#pragma unroll
    for (int g = 0; g < 4; g++) {
        float4 p = make_float4(v[g].x * inv, v[g].y * inv, v[g].z * inv, v[g].w * inv);
        half4_write(p, g_p, ((size_t)row * MAXT + tid * 4 + g * 1024) >> 2);
    }
}

// ============================== launcher =====================================
extern "C" void kernel_launch(void* const* d_in, const int* in_sizes, int n_in,
                              void* d_out, int out_size) {
    const float* x      = (const float*)d_in[0];
    const float* fc     = (const float*)d_in[2];
    const float* fs     = (const float*)d_in[3];
    const float* mask   = (const float*)d_in[4];
    const float* kvc    = (const float*)d_in[5];
    const float* krc    = (const float*)d_in[6];
    const float* w_kvd  = (const float*)d_in[7];
    const float* w_qd   = (const float*)d_in[8];
    const float* rms_w  = (const float*)d_in[9];
    const float* w_qu   = (const float*)d_in[10];
    const float* w_kvu  = (const float*)d_in[11];
    const float* w_out  = (const float*)d_in[12];
    float* out = (float*)d_out;

    float *p_qkv, *p_q;
    cudaGetSymbolAddress((void**)&p_qkv, g_qkv);
    cudaGetSymbolAddress((void**)&p_q,  g_q);

    __half *qc, *kc, *kt, *pp, *S16, *xf, *qnf, *Of, *o2f;
    __half *wdf, *wquf, *woutf;
    cudaGetSymbolAddress((void**)&qc, g_qc);
    cudaGetSymbolAddress((void**)&kc, g_kc);
    cudaGetSymbolAddress((void**)&kt, g_kt);
    cudaGetSymbolAddress((void**)&pp, g_p);
    cudaGetSymbolAddress((void**)&S16, g_S16);
    cudaGetSymbolAddress((void**)&xf, g_xf);
    cudaGetSymbolAddress((void**)&qnf, g_qnf);
    cudaGetSymbolAddress((void**)&Of, g_Of);
    cudaGetSymbolAddress((void**)&o2f, g_o2f);
    cudaGetSymbolAddress((void**)&wdf, g_wdf);
    cudaGetSymbolAddress((void**)&wquf, g_wquf);
    cudaGetSymbolAddress((void**)&woutf, g_woutf);

    static cudaStream_t s_kv = nullptr;
    static cudaEvent_t ev_fork = nullptr, ev_dp = nullptr, ev_join = nullptr, ev_wnrt = nullptr;
    if (!s_kv) {
        cudaStreamCreateWithFlags(&s_kv, cudaStreamNonBlocking);
        cudaEventCreateWithFlags(&ev_fork, cudaEventDisableTiming);
        cudaEventCreateWithFlags(&ev_dp, cudaEventDisableTiming);
        cudaEventCreateWithFlags(&ev_join, cudaEventDisableTiming);
        cudaEventCreateWithFlags(&ev_wnrt, cudaEventDisableTiming);
        cudaFuncSetAttribute(gemm_f16_sk, cudaFuncAttributeMaxDynamicSharedMemorySize, 3 * OF_STAGE);
        cudaFuncSetAttribute(qabs_f16, cudaFuncAttributeMaxDynamicSharedMemorySize, 2 * OF_STAGE);
        cudaFuncSetAttribute(oup_f16, cudaFuncAttributeMaxDynamicSharedMemorySize, 3 * OF_STAGE);
        cudaFuncSetAttribute(scores_f16, cudaFuncAttributeMaxDynamicSharedMemorySize, 3 * SF_STAGE);
        cudaFuncSetAttribute(ogemm_f16, cudaFuncAttributeMaxDynamicSharedMemorySize, 3 * OF_STAGE);
    }

    // ---- root: memsets on default stream, then legal fork ----
    cudaMemsetAsync(p_qkv, 0, (size_t)MBL * DPAD * 4);
    cudaMemsetAsync(p_q, 0, (size_t)MBL * NH * QKD * 4);
    cudaMemsetAsync(o2f, 0, (size_t)MBL * NH * DV * 2);
    cudaMemsetAsync(out, 0, (size_t)MBL * DIM * 4);
    cudaEventRecord(ev_fork, 0);
    cudaStreamWaitEvent(s_kv, ev_fork, 0);

    // side stream: wnrt (reads raw input only) overlaps conv_all + down-proj
    build_wnrt<<<dim3(KVR / 32, DNR / 32, NH), dim3(32, 8), 0, s_kv>>>(w_kvu);
    cudaEventRecord(ev_wnrt, s_kv);

    // default: conversions + combined down-projection (176 CTAs)
    conv_all<<<C4_WKVU / 256, 256>>>((const float4*)x, (const float4*)w_qd, (const float4*)w_qu,
                                     (const float4*)w_kvd, (const float4*)w_out, (const float4*)w_kvu);
    gemm_f16_sk<<<dim3(DPAD / 128, MBL / 128, 8), 256, 3 * OF_STAGE>>>(
        xf, wdf, p_qkv, DPAD, DIM, DIM / 8, DPAD);
    cudaEventRecord(ev_dp, 0);

    // kv path on s_kv (after down-proj)
    cudaStreamWaitEvent(s_kv, ev_dp, 0);
    build_kv2<<<dim3(MAXT / 32, 17, BATCH), 256, 0, s_kv>>>(kvc, krc, fc, fs);
    cudaEventRecord(ev_join, s_kv);

    // q path (default)
    rms_kernel<<<MBL, 256>>>(rms_w);
    gemm_f16_sk<<<dim3(NH * QKD / 128, MBL / 128, 4), 256, 3 * OF_STAGE>>>(
        qnf, wquf, p_q, NH * QKD, QR, QR / 4, NH * QKD);
    conv_q<<<(CQ_N1 + CQ_N2 + 255) / 256, 256>>>(fc, fs);
    cudaStreamWaitEvent(0, ev_wnrt, 0);
    qabs_f16<<<dim3(KVR / 128, MBL / 128, NH), 256, 2 * OF_STAGE>>>();

    // ---- join q/kv ----
    cudaStreamWaitEvent(0, ev_join, 0);

    // ---- attention ----
    scores_f16<<<dim3(MAXT / 256, ROWSPB / 128, BATCH), 256, 3 * SF_STAGE>>>(
        qc, (size_t)ROWSPB * CATD, kc, (size_t)MAXT * CATD,
        S16, MAXT, (size_t)ROWSPB * MAXT, CATD, mask, SCALE_F);
    softmax_split<<<BATCH * ROWSPB, 256>>>();
    ogemm_f16<<<dim3(KVR / 128, ROWSPB / 128, BATCH), 256, 3 * OF_STAGE>>>(
        pp, (size_t)ROWSPB * MAXT, kt, (size_t)KVR * MAXT,
        Of, KVR, (size_t)ROWSPB * KVR, MAXT);

    // ---- output path ----
    oup_f16<<<dim3(2, MBL / 128, NH), 256, 3 * OF_STAGE>>>();
    gemm_f16_sk<<<dim3(DIM / 128, MBL / 128, 8), 256, 3 * OF_STAGE>>>(
        o2f, woutf, out, DIM, NH * DV, NH * DV / 8, DIM);
}